// round 1
// baseline (speedup 1.0000x reference)
#include <cuda_runtime.h>
#include <cstddef>

#define EMBED    256
#define HEADS    8
#define LEVELS   4
#define POINTS   4
#define HEAD_DIM 32

// ---------------------------------------------------------------------------
// Scratch (static __device__ globals; runtime allocation is forbidden)
// ---------------------------------------------------------------------------
__device__ float g_vproj[4 * 13312 * EMBED];   // projected value  [bs*Lv, 256]
__device__ float g_off  [3600 * EMBED];        // sampling offsets [bs*Lq, 256]
__device__ float g_logit[3600 * 128];          // attn logits      [bs*Lq, 128]
__device__ float g_samp [3600 * EMBED];        // sampled output   [bs*Lq, 256]

// ---------------------------------------------------------------------------
// C[M,N] = A[M,K] * B[N,K]^T + bias[N]      (row-major A, row-major B)
// 64x64 tile, BK=32, 256 threads, 4x4 per-thread microtile, float4 smem reads
// ---------------------------------------------------------------------------
__global__ __launch_bounds__(256)
void gemm_nt_bias(const float* __restrict__ A, const float* __restrict__ B,
                  const float* __restrict__ bias, float* __restrict__ C,
                  int M, int N, int K)
{
    __shared__ float As[32][68];   // [k][m], pad 4 keeps float4 alignment
    __shared__ float Bs[32][68];   // [k][n]

    const int tid = threadIdx.x;
    const int tx  = tid & 15;          // column group
    const int ty  = tid >> 4;          // row group
    const int m0  = blockIdx.y * 64;
    const int n0  = blockIdx.x * 64;

    float acc[4][4] = {};

    for (int k0 = 0; k0 < K; k0 += 32) {
        // Load 64x32 A and B tiles (512 float4s each, 2 per thread), transposed
        #pragma unroll
        for (int i = 0; i < 2; i++) {
            int idx = tid + i * 256;           // 0..511
            int r   = idx >> 3;                // row in tile 0..63
            int c4  = idx & 7;                 // float4 column 0..7
            int m   = m0 + r;
            float4 av = (m < M) ? *(const float4*)&A[(size_t)m * K + k0 + c4 * 4]
                                : make_float4(0.f, 0.f, 0.f, 0.f);
            As[c4 * 4 + 0][r] = av.x;
            As[c4 * 4 + 1][r] = av.y;
            As[c4 * 4 + 2][r] = av.z;
            As[c4 * 4 + 3][r] = av.w;
            int n   = n0 + r;
            float4 bv = (n < N) ? *(const float4*)&B[(size_t)n * K + k0 + c4 * 4]
                                : make_float4(0.f, 0.f, 0.f, 0.f);
            Bs[c4 * 4 + 0][r] = bv.x;
            Bs[c4 * 4 + 1][r] = bv.y;
            Bs[c4 * 4 + 2][r] = bv.z;
            Bs[c4 * 4 + 3][r] = bv.w;
        }
        __syncthreads();

        #pragma unroll
        for (int kk = 0; kk < 32; kk++) {
            float4 a = *(const float4*)&As[kk][ty * 4];
            float4 b = *(const float4*)&Bs[kk][tx * 4];
            acc[0][0] += a.x * b.x; acc[0][1] += a.x * b.y;
            acc[0][2] += a.x * b.z; acc[0][3] += a.x * b.w;
            acc[1][0] += a.y * b.x; acc[1][1] += a.y * b.y;
            acc[1][2] += a.y * b.z; acc[1][3] += a.y * b.w;
            acc[2][0] += a.z * b.x; acc[2][1] += a.z * b.y;
            acc[2][2] += a.z * b.z; acc[2][3] += a.z * b.w;
            acc[3][0] += a.w * b.x; acc[3][1] += a.w * b.y;
            acc[3][2] += a.w * b.z; acc[3][3] += a.w * b.w;
        }
        __syncthreads();
    }

    #pragma unroll
    for (int i = 0; i < 4; i++) {
        int m = m0 + ty * 4 + i;
        if (m >= M) continue;
        #pragma unroll
        for (int j = 0; j < 4; j++) {
            int n = n0 + tx * 4 + j;
            if (n < N) C[(size_t)m * N + n] = acc[i][j] + bias[n];
        }
    }
}

// ---------------------------------------------------------------------------
// Deformable sampling: one block per (b, q); 256 threads = (head h, dim d)
// Computes softmax(attn logits) over 16 (L*P) per head, then bilinear-gathers
// 4 corners x 16 points from the projected value and accumulates.
// ---------------------------------------------------------------------------
__global__ __launch_bounds__(256)
void msda_sample(const float* __restrict__ vproj,
                 const float* __restrict__ refp,     // [bs, Lq, 4, 2]
                 const float* __restrict__ off,      // [bs*Lq, 256]
                 const float* __restrict__ logits,   // [bs*Lq, 128]
                 const int*   __restrict__ shapes,   // [4, 2]  (H, W)
                 const int*   __restrict__ lstart,   // [4]
                 float*       __restrict__ samp,     // [bs*Lq, 256]
                 int Lq, int Lv)
{
    const int bq  = blockIdx.x;          // b*Lq + q
    const int b   = bq / Lq;
    const int tid = threadIdx.x;
    const int h   = tid >> 5;            // head
    const int d   = tid & 31;            // dim within head

    __shared__ float s_log[HEADS * LEVELS * POINTS];  // 128
    __shared__ float s_off[EMBED];                    // 256
    __shared__ float s_ref[LEVELS * 2];
    __shared__ int   s_shape[LEVELS * 2];
    __shared__ int   s_start[LEVELS];

    if (tid < 128) s_log[tid] = logits[(size_t)bq * 128 + tid];
    s_off[tid] = off[(size_t)bq * EMBED + tid];
    if (tid < LEVELS * 2) {
        s_ref[tid]   = refp[(size_t)bq * (LEVELS * 2) + tid];
        s_shape[tid] = shapes[tid];
    }
    if (tid < LEVELS) s_start[tid] = lstart[tid];
    __syncthreads();

    // softmax over 16 logits for this head (redundant per thread; trivial cost)
    float w[LEVELS * POINTS];
    float mx = -1e30f;
    #pragma unroll
    for (int i = 0; i < 16; i++) { w[i] = s_log[h * 16 + i]; mx = fmaxf(mx, w[i]); }
    float sum = 0.f;
    #pragma unroll
    for (int i = 0; i < 16; i++) { w[i] = __expf(w[i] - mx); sum += w[i]; }
    const float inv = 1.f / sum;

    const float* vb = vproj + (size_t)b * Lv * EMBED + h * HEAD_DIM + d;

    float acc = 0.f;
    #pragma unroll
    for (int l = 0; l < LEVELS; l++) {
        const int   Hh = s_shape[l * 2 + 0];
        const int   Ww = s_shape[l * 2 + 1];
        const float Hf = (float)Hh;
        const float Wf = (float)Ww;
        const int   st = s_start[l];
        const float rx = s_ref[l * 2 + 0];
        const float ry = s_ref[l * 2 + 1];
        #pragma unroll
        for (int p = 0; p < POINTS; p++) {
            const int oi = ((h * LEVELS + l) * POINTS + p) * 2;
            // loc = ref + off / (W, H);  pixel = loc * size - 0.5
            const float x = (rx + s_off[oi + 0] / Wf) * Wf - 0.5f;
            const float y = (ry + s_off[oi + 1] / Hf) * Hf - 0.5f;
            const float x0f = floorf(x), y0f = floorf(y);
            const float lx = x - x0f,  ly = y - y0f;
            const int   x0 = (int)x0f, y0 = (int)y0f;
            const float aw = w[l * POINTS + p] * inv;

            const float cw0 = (1.f - lx) * (1.f - ly);
            const float cw1 = lx * (1.f - ly);
            const float cw2 = (1.f - lx) * ly;
            const float cw3 = lx * ly;

            const bool vx0 = (x0 >= 0) & (x0 < Ww);
            const bool vx1 = (x0 + 1 >= 0) & (x0 + 1 < Ww);
            const bool vy0 = (y0 >= 0) & (y0 < Hh);
            const bool vy1 = (y0 + 1 >= 0) & (y0 + 1 < Hh);

            if (vy0) {
                const int rowb = st + y0 * Ww;
                if (vx0) acc += aw * cw0 * vb[(size_t)(rowb + x0)     * EMBED];
                if (vx1) acc += aw * cw1 * vb[(size_t)(rowb + x0 + 1) * EMBED];
            }
            if (vy1) {
                const int rowb = st + (y0 + 1) * Ww;
                if (vx0) acc += aw * cw2 * vb[(size_t)(rowb + x0)     * EMBED];
                if (vx1) acc += aw * cw3 * vb[(size_t)(rowb + x0 + 1) * EMBED];
            }
        }
    }
    samp[(size_t)bq * EMBED + tid] = acc;
}

// ---------------------------------------------------------------------------
// kernel_launch
// ---------------------------------------------------------------------------
extern "C" void kernel_launch(void* const* d_in, const int* in_sizes, int n_in,
                              void* d_out, int out_size)
{
    const float* query   = (const float*)d_in[0];
    const float* refp    = (const float*)d_in[1];
    const float* value   = (const float*)d_in[2];
    const int*   shapes  = (const int*)  d_in[3];
    const int*   lstart  = (const int*)  d_in[4];
    const float* w_value = (const float*)d_in[5];
    const float* b_value = (const float*)d_in[6];
    const float* w_off   = (const float*)d_in[7];
    const float* b_off   = (const float*)d_in[8];
    const float* w_attn  = (const float*)d_in[9];
    const float* b_attn  = (const float*)d_in[10];
    const float* w_out   = (const float*)d_in[11];
    const float* b_out   = (const float*)d_in[12];

    const int Mv = in_sizes[2] / EMBED;   // bs * Lv = 53176
    const int Mq = in_sizes[0] / EMBED;   // bs * Lq = 3600
    const int bs = 4;
    const int Lv = Mv / bs;
    const int Lq = Mq / bs;

    float *vproj, *offb, *logitb, *sampb;
    cudaGetSymbolAddress((void**)&vproj,  g_vproj);
    cudaGetSymbolAddress((void**)&offb,   g_off);
    cudaGetSymbolAddress((void**)&logitb, g_logit);
    cudaGetSymbolAddress((void**)&sampb,  g_samp);

    // 1) value projection: [Mv,256] @ w_value^T + b_value
    gemm_nt_bias<<<dim3(EMBED / 64, (Mv + 63) / 64), 256>>>(
        value, w_value, b_value, vproj, Mv, EMBED, EMBED);

    // 2) sampling offsets: [Mq,256] @ w_off^T + b_off
    gemm_nt_bias<<<dim3(EMBED / 64, (Mq + 63) / 64), 256>>>(
        query, w_off, b_off, offb, Mq, EMBED, EMBED);

    // 3) attention logits: [Mq,128] @ w_attn^T + b_attn
    gemm_nt_bias<<<dim3(128 / 64, (Mq + 63) / 64), 256>>>(
        query, w_attn, b_attn, logitb, Mq, 128, EMBED);

    // 4) softmax + bilinear deformable sampling
    msda_sample<<<Mq, 256>>>(vproj, refp, offb, logitb, shapes, lstart,
                             sampb, Lq, Lv);

    // 5) output projection: [Mq,256] @ w_out^T + b_out -> d_out
    gemm_nt_bias<<<dim3(EMBED / 64, (Mq + 63) / 64), 256>>>(
        sampb, w_out, b_out, (float*)d_out, Mq, EMBED, EMBED);
}

// round 2
// speedup vs baseline: 1.2150x; 1.2150x over previous
#include <cuda_runtime.h>
#include <cstddef>

#define EMBED    256
#define HEADS    8
#define LEVELS   4
#define POINTS   4
#define HEAD_DIM 32

// ---------------------------------------------------------------------------
// Scratch (static __device__ globals; runtime allocation is forbidden)
// ---------------------------------------------------------------------------
__device__ float g_vproj[4 * 13312 * EMBED];   // projected value  [bs*Lv, 256]
__device__ float g_off  [3600 * EMBED];        // sampling offsets [bs*Lq, 256]
__device__ float g_logit[3600 * 128];          // attn logits      [bs*Lq, 128]
__device__ float g_samp [3600 * EMBED];        // sampled output   [bs*Lq, 256]

// ---------------------------------------------------------------------------
// Small-GEMM kernel (64x64 tile, 4x4 microtile) — used for the M=3600 GEMMs
// C[M,N] = A[M,K] * B[N,K]^T + bias[N]
// ---------------------------------------------------------------------------
__global__ __launch_bounds__(256)
void gemm_nt_bias(const float* __restrict__ A, const float* __restrict__ B,
                  const float* __restrict__ bias, float* __restrict__ C,
                  int M, int N, int K)
{
    __shared__ float As[32][68];
    __shared__ float Bs[32][68];

    const int tid = threadIdx.x;
    const int tx  = tid & 15;
    const int ty  = tid >> 4;
    const int m0  = blockIdx.y * 64;
    const int n0  = blockIdx.x * 64;

    float acc[4][4] = {};

    for (int k0 = 0; k0 < K; k0 += 32) {
        #pragma unroll
        for (int i = 0; i < 2; i++) {
            int idx = tid + i * 256;
            int r   = idx >> 3;
            int c4  = idx & 7;
            int m   = m0 + r;
            float4 av = (m < M) ? *(const float4*)&A[(size_t)m * K + k0 + c4 * 4]
                                : make_float4(0.f, 0.f, 0.f, 0.f);
            As[c4 * 4 + 0][r] = av.x;
            As[c4 * 4 + 1][r] = av.y;
            As[c4 * 4 + 2][r] = av.z;
            As[c4 * 4 + 3][r] = av.w;
            int n   = n0 + r;
            float4 bv = (n < N) ? *(const float4*)&B[(size_t)n * K + k0 + c4 * 4]
                                : make_float4(0.f, 0.f, 0.f, 0.f);
            Bs[c4 * 4 + 0][r] = bv.x;
            Bs[c4 * 4 + 1][r] = bv.y;
            Bs[c4 * 4 + 2][r] = bv.z;
            Bs[c4 * 4 + 3][r] = bv.w;
        }
        __syncthreads();

        #pragma unroll
        for (int kk = 0; kk < 32; kk++) {
            float4 a = *(const float4*)&As[kk][ty * 4];
            float4 b = *(const float4*)&Bs[kk][tx * 4];
            acc[0][0] += a.x * b.x; acc[0][1] += a.x * b.y;
            acc[0][2] += a.x * b.z; acc[0][3] += a.x * b.w;
            acc[1][0] += a.y * b.x; acc[1][1] += a.y * b.y;
            acc[1][2] += a.y * b.z; acc[1][3] += a.y * b.w;
            acc[2][0] += a.z * b.x; acc[2][1] += a.z * b.y;
            acc[2][2] += a.z * b.z; acc[2][3] += a.z * b.w;
            acc[3][0] += a.w * b.x; acc[3][1] += a.w * b.y;
            acc[3][2] += a.w * b.z; acc[3][3] += a.w * b.w;
        }
        __syncthreads();
    }

    #pragma unroll
    for (int i = 0; i < 4; i++) {
        int m = m0 + ty * 4 + i;
        if (m >= M) continue;
        #pragma unroll
        for (int j = 0; j < 4; j++) {
            int n = n0 + tx * 4 + j;
            if (n < N) C[(size_t)m * N + n] = acc[i][j] + bias[n];
        }
    }
}

// ---------------------------------------------------------------------------
// Big-GEMM kernel: 128x128 tile, BK=16, 256 threads, 8x8 microtile,
// gmem->register prefetch of the next K-slab. Used for the value projection.
// C[M,N] = A[M,K] * B[N,K]^T + bias[N]
// ---------------------------------------------------------------------------
__global__ __launch_bounds__(256, 2)
void gemm128_nt_bias(const float* __restrict__ A, const float* __restrict__ B,
                     const float* __restrict__ bias, float* __restrict__ C,
                     int M, int N, int K)
{
    __shared__ float As[16][132];   // [k][m], pad keeps banks spread
    __shared__ float Bs[16][132];   // [k][n]

    const int tid = threadIdx.x;
    const int tx  = tid & 15;          // 0..15 (n groups)
    const int ty  = tid >> 4;          // 0..15 (m groups)
    const int m0  = blockIdx.y * 128;
    const int n0  = blockIdx.x * 128;

    // Loader mapping: 512 float4 per matrix per slab; 2 per thread.
    // idx = tid + 256*i -> row = idx>>2 (0..127), c4 = idx&3 (float4 within 16 k)
    const int lrow0 = tid >> 2;
    const int lc4   = tid & 3;

    float4 pa[2], pb[2];

    // ---- load slab 0 into registers, then smem ----
    #pragma unroll
    for (int i = 0; i < 2; i++) {
        int r = lrow0 + i * 64;
        int m = m0 + r;
        pa[i] = (m < M) ? *(const float4*)&A[(size_t)m * K + lc4 * 4]
                        : make_float4(0.f, 0.f, 0.f, 0.f);
        int n = n0 + r;
        pb[i] = (n < N) ? *(const float4*)&B[(size_t)n * K + lc4 * 4]
                        : make_float4(0.f, 0.f, 0.f, 0.f);
    }

    float acc[8][8] = {};

    for (int k0 = 0; k0 < K; k0 += 16) {
        // store prefetched slab to smem (transposed)
        #pragma unroll
        for (int i = 0; i < 2; i++) {
            int r = lrow0 + i * 64;
            As[lc4 * 4 + 0][r] = pa[i].x;
            As[lc4 * 4 + 1][r] = pa[i].y;
            As[lc4 * 4 + 2][r] = pa[i].z;
            As[lc4 * 4 + 3][r] = pa[i].w;
            Bs[lc4 * 4 + 0][r] = pb[i].x;
            Bs[lc4 * 4 + 1][r] = pb[i].y;
            Bs[lc4 * 4 + 2][r] = pb[i].z;
            Bs[lc4 * 4 + 3][r] = pb[i].w;
        }
        __syncthreads();

        // prefetch next slab into registers while computing this one
        if (k0 + 16 < K) {
            #pragma unroll
            for (int i = 0; i < 2; i++) {
                int r = lrow0 + i * 64;
                int m = m0 + r;
                pa[i] = (m < M) ? *(const float4*)&A[(size_t)m * K + k0 + 16 + lc4 * 4]
                                : make_float4(0.f, 0.f, 0.f, 0.f);
                int n = n0 + r;
                pb[i] = (n < N) ? *(const float4*)&B[(size_t)n * K + k0 + 16 + lc4 * 4]
                                : make_float4(0.f, 0.f, 0.f, 0.f);
            }
        }

        #pragma unroll
        for (int kk = 0; kk < 16; kk++) {
            float4 a0 = *(const float4*)&As[kk][ty * 4];
            float4 a1 = *(const float4*)&As[kk][64 + ty * 4];
            float4 b0 = *(const float4*)&Bs[kk][tx * 4];
            float4 b1 = *(const float4*)&Bs[kk][64 + tx * 4];
            float av[8] = {a0.x, a0.y, a0.z, a0.w, a1.x, a1.y, a1.z, a1.w};
            float bv[8] = {b0.x, b0.y, b0.z, b0.w, b1.x, b1.y, b1.z, b1.w};
            #pragma unroll
            for (int i = 0; i < 8; i++)
                #pragma unroll
                for (int j = 0; j < 8; j++)
                    acc[i][j] += av[i] * bv[j];
        }
        __syncthreads();
    }

    // epilogue: float4 stores, bias added
    #pragma unroll
    for (int i = 0; i < 8; i++) {
        int m = m0 + (i < 4 ? ty * 4 + i : 64 + ty * 4 + (i - 4));
        if (m >= M) continue;
        #pragma unroll
        for (int jh = 0; jh < 2; jh++) {
            int n = n0 + (jh == 0 ? tx * 4 : 64 + tx * 4);
            if (n + 3 < N) {
                float4 o;
                o.x = acc[i][jh * 4 + 0] + bias[n + 0];
                o.y = acc[i][jh * 4 + 1] + bias[n + 1];
                o.z = acc[i][jh * 4 + 2] + bias[n + 2];
                o.w = acc[i][jh * 4 + 3] + bias[n + 3];
                *(float4*)&C[(size_t)m * N + n] = o;
            }
        }
    }
}

// ---------------------------------------------------------------------------
// Deformable sampling: one block per (b, q); 256 threads = (head h, dim d)
// ---------------------------------------------------------------------------
__global__ __launch_bounds__(256)
void msda_sample(const float* __restrict__ vproj,
                 const float* __restrict__ refp,     // [bs, Lq, 4, 2]
                 const float* __restrict__ off,      // [bs*Lq, 256]
                 const float* __restrict__ logits,   // [bs*Lq, 128]
                 const int*   __restrict__ shapes,   // [4, 2]  (H, W)
                 const int*   __restrict__ lstart,   // [4]
                 float*       __restrict__ samp,     // [bs*Lq, 256]
                 int Lq, int Lv)
{
    const int bq  = blockIdx.x;
    const int b   = bq / Lq;
    const int tid = threadIdx.x;
    const int h   = tid >> 5;
    const int d   = tid & 31;

    __shared__ float s_log[HEADS * LEVELS * POINTS];
    __shared__ float s_off[EMBED];
    __shared__ float s_ref[LEVELS * 2];
    __shared__ int   s_shape[LEVELS * 2];
    __shared__ int   s_start[LEVELS];

    if (tid < 128) s_log[tid] = logits[(size_t)bq * 128 + tid];
    s_off[tid] = off[(size_t)bq * EMBED + tid];
    if (tid < LEVELS * 2) {
        s_ref[tid]   = refp[(size_t)bq * (LEVELS * 2) + tid];
        s_shape[tid] = shapes[tid];
    }
    if (tid < LEVELS) s_start[tid] = lstart[tid];
    __syncthreads();

    float w[LEVELS * POINTS];
    float mx = -1e30f;
    #pragma unroll
    for (int i = 0; i < 16; i++) { w[i] = s_log[h * 16 + i]; mx = fmaxf(mx, w[i]); }
    float sum = 0.f;
    #pragma unroll
    for (int i = 0; i < 16; i++) { w[i] = __expf(w[i] - mx); sum += w[i]; }
    const float inv = 1.f / sum;

    const float* vb = vproj + (size_t)b * Lv * EMBED + h * HEAD_DIM + d;

    float acc = 0.f;
    #pragma unroll
    for (int l = 0; l < LEVELS; l++) {
        const int   Hh = s_shape[l * 2 + 0];
        const int   Ww = s_shape[l * 2 + 1];
        const float Hf = (float)Hh;
        const float Wf = (float)Ww;
        const int   st = s_start[l];
        const float rx = s_ref[l * 2 + 0];
        const float ry = s_ref[l * 2 + 1];
        #pragma unroll
        for (int p = 0; p < POINTS; p++) {
            const int oi = ((h * LEVELS + l) * POINTS + p) * 2;
            const float x = (rx + s_off[oi + 0] / Wf) * Wf - 0.5f;
            const float y = (ry + s_off[oi + 1] / Hf) * Hf - 0.5f;
            const float x0f = floorf(x), y0f = floorf(y);
            const float lx = x - x0f,  ly = y - y0f;
            const int   x0 = (int)x0f, y0 = (int)y0f;
            const float aw = w[l * POINTS + p] * inv;

            const float cw0 = (1.f - lx) * (1.f - ly);
            const float cw1 = lx * (1.f - ly);
            const float cw2 = (1.f - lx) * ly;
            const float cw3 = lx * ly;

            const bool vx0 = (x0 >= 0) & (x0 < Ww);
            const bool vx1 = (x0 + 1 >= 0) & (x0 + 1 < Ww);
            const bool vy0 = (y0 >= 0) & (y0 < Hh);
            const bool vy1 = (y0 + 1 >= 0) & (y0 + 1 < Hh);

            if (vy0) {
                const int rowb = st + y0 * Ww;
                if (vx0) acc += aw * cw0 * vb[(size_t)(rowb + x0)     * EMBED];
                if (vx1) acc += aw * cw1 * vb[(size_t)(rowb + x0 + 1) * EMBED];
            }
            if (vy1) {
                const int rowb = st + (y0 + 1) * Ww;
                if (vx0) acc += aw * cw2 * vb[(size_t)(rowb + x0)     * EMBED];
                if (vx1) acc += aw * cw3 * vb[(size_t)(rowb + x0 + 1) * EMBED];
            }
        }
    }
    samp[(size_t)bq * EMBED + tid] = acc;
}

// ---------------------------------------------------------------------------
// kernel_launch
// ---------------------------------------------------------------------------
extern "C" void kernel_launch(void* const* d_in, const int* in_sizes, int n_in,
                              void* d_out, int out_size)
{
    const float* query   = (const float*)d_in[0];
    const float* refp    = (const float*)d_in[1];
    const float* value   = (const float*)d_in[2];
    const int*   shapes  = (const int*)  d_in[3];
    const int*   lstart  = (const int*)  d_in[4];
    const float* w_value = (const float*)d_in[5];
    const float* b_value = (const float*)d_in[6];
    const float* w_off   = (const float*)d_in[7];
    const float* b_off   = (const float*)d_in[8];
    const float* w_attn  = (const float*)d_in[9];
    const float* b_attn  = (const float*)d_in[10];
    const float* w_out   = (const float*)d_in[11];
    const float* b_out   = (const float*)d_in[12];

    const int Mv = in_sizes[2] / EMBED;   // bs * Lv = 53176
    const int Mq = in_sizes[0] / EMBED;   // bs * Lq = 3600
    const int bs = 4;
    const int Lv = Mv / bs;
    const int Lq = Mq / bs;

    float *vproj, *offb, *logitb, *sampb;
    cudaGetSymbolAddress((void**)&vproj,  g_vproj);
    cudaGetSymbolAddress((void**)&offb,   g_off);
    cudaGetSymbolAddress((void**)&logitb, g_logit);
    cudaGetSymbolAddress((void**)&sampb,  g_samp);

    // 1) value projection (big): [Mv,256] @ w_value^T + b_value
    gemm128_nt_bias<<<dim3(EMBED / 128, (Mv + 127) / 128), 256>>>(
        value, w_value, b_value, vproj, Mv, EMBED, EMBED);

    // 2) sampling offsets: [Mq,256] @ w_off^T + b_off
    gemm_nt_bias<<<dim3(EMBED / 64, (Mq + 63) / 64), 256>>>(
        query, w_off, b_off, offb, Mq, EMBED, EMBED);

    // 3) attention logits: [Mq,128] @ w_attn^T + b_attn
    gemm_nt_bias<<<dim3(128 / 64, (Mq + 63) / 64), 256>>>(
        query, w_attn, b_attn, logitb, Mq, 128, EMBED);

    // 4) softmax + bilinear deformable sampling
    msda_sample<<<Mq, 256>>>(vproj, refp, offb, logitb, shapes, lstart,
                             sampb, Lq, Lv);

    // 5) output projection: [Mq,256] @ w_out^T + b_out -> d_out
    gemm_nt_bias<<<dim3(EMBED / 64, (Mq + 63) / 64), 256>>>(
        sampb, w_out, b_out, (float*)d_out, Mq, EMBED, EMBED);
}

// round 4
// speedup vs baseline: 1.4249x; 1.1727x over previous
#include <cuda_runtime.h>
#include <cuda_bf16.h>
#include <cstdint>
#include <cstddef>

#define EMBED    256
#define HEADS    8
#define LEVELS   4
#define POINTS   4
#define HEAD_DIM 32

// ---------------------------------------------------------------------------
// Scratch (static __device__ globals; runtime allocation is forbidden)
// ---------------------------------------------------------------------------
__device__ float g_vproj[4 * 13312 * EMBED];   // projected value  [bs*Lv, 256]
__device__ float g_off  [3600 * EMBED];        // sampling offsets [bs*Lq, 256]
__device__ float g_logit[3600 * 128];          // attn logits      [bs*Lq, 128]
__device__ float g_samp [3600 * EMBED];        // sampled output   [bs*Lq, 256]

// ---------------------------------------------------------------------------
// helpers
// ---------------------------------------------------------------------------
__device__ __forceinline__ uint32_t smem_u32(const void* p) {
    uint32_t a;
    asm("{ .reg .u64 t; cvta.to.shared.u64 t, %1; cvt.u32.u64 %0, t; }"
        : "=r"(a) : "l"(p));
    return a;
}

__device__ __forceinline__ void ldsm4(uint32_t* r, uint32_t addr) {
    asm volatile("ldmatrix.sync.aligned.m8n8.x4.shared.b16 {%0,%1,%2,%3}, [%4];"
                 : "=r"(r[0]), "=r"(r[1]), "=r"(r[2]), "=r"(r[3]) : "r"(addr));
}

__device__ __forceinline__ void mma_bf16(float* c, const uint32_t* a,
                                         uint32_t b0, uint32_t b1) {
    asm volatile(
        "mma.sync.aligned.m16n8k16.row.col.f32.bf16.bf16.f32 "
        "{%0,%1,%2,%3}, {%4,%5,%6,%7}, {%8,%9}, {%0,%1,%2,%3};"
        : "+f"(c[0]), "+f"(c[1]), "+f"(c[2]), "+f"(c[3])
        : "r"(a[0]), "r"(a[1]), "r"(a[2]), "r"(a[3]), "r"(b0), "r"(b1));
}

// convert 8 fp32 -> 8 bf16 hi + 8 bf16 lo (2-term split)
union Pack8 { uint4 u; __nv_bfloat16 b[8]; };
__device__ __forceinline__ void cvt8(const float4& v0, const float4& v1,
                                     uint4& hi, uint4& lo) {
    float f[8] = {v0.x, v0.y, v0.z, v0.w, v1.x, v1.y, v1.z, v1.w};
    Pack8 H, L;
    #pragma unroll
    for (int j = 0; j < 8; j++) {
        __nv_bfloat16 h = __float2bfloat16_rn(f[j]);
        H.b[j] = h;
        L.b[j] = __float2bfloat16_rn(f[j] - __bfloat162float(h));
    }
    hi = H.u; lo = L.u;
}

#define SWZ(o) ((o) ^ (((o) >> 3) & 0x70))

// ---------------------------------------------------------------------------
// Value projection: C[M,256] = A[M,256] @ B[256,256]^T + bias, bf16x3 mma.sync
// Tile 128x128, BK=32 fp32 (hi/lo bf16 stored side by side: 64 bf16 = 128B rows)
// 8 warps, warp tile 64x32, double-buffered smem.
// smem per buffer: A 16KB + B 16KB; total 64KB dynamic.
// ---------------------------------------------------------------------------
__global__ __launch_bounds__(256)
void vproj_bf16x3(const float* __restrict__ A, const float* __restrict__ B,
                  const float* __restrict__ bias, float* __restrict__ C, int M)
{
    extern __shared__ char sm[];
    const int tid  = threadIdx.x;
    const int lane = tid & 31;
    const int w    = tid >> 5;
    const int wm   = (w & 1) * 64;       // warp m offset in tile
    const int wn   = (w >> 1) * 32;      // warp n offset in tile
    const int m0   = blockIdx.y * 128;
    const int n0   = blockIdx.x * 128;
    const uint32_t sb = smem_u32(sm);

    float acc[4][4][4] = {};             // [mt][n8tile][4]

    auto load_chunk = [&](int kc, int buf) {
        char* ap = sm + buf * 32768;
        char* bp = ap + 16384;
        const int kb = kc * 32;
        #pragma unroll
        for (int i = 0; i < 2; i++) {
            int idx = tid + i * 256;       // 0..511
            int row = idx >> 2;            // 0..127
            int seg = idx & 3;             // 8-float segment
            // ---- A ----
            int m = m0 + row;
            float4 v0, v1;
            if (m < M) {
                v0 = *(const float4*)&A[(size_t)m * 256 + kb + seg * 8];
                v1 = *(const float4*)&A[(size_t)m * 256 + kb + seg * 8 + 4];
            } else {
                v0 = make_float4(0.f, 0.f, 0.f, 0.f); v1 = v0;
            }
            uint4 hi, lo;
            cvt8(v0, v1, hi, lo);
            uint32_t ohi = SWZ((uint32_t)(row * 128 + seg * 16));
            uint32_t olo = SWZ((uint32_t)(row * 128 + 64 + seg * 16));
            *(uint4*)(ap + ohi) = hi;
            *(uint4*)(ap + olo) = lo;
            // ---- B ----
            int n = n0 + row;
            v0 = *(const float4*)&B[(size_t)n * 256 + kb + seg * 8];
            v1 = *(const float4*)&B[(size_t)n * 256 + kb + seg * 8 + 4];
            cvt8(v0, v1, hi, lo);
            *(uint4*)(bp + ohi) = hi;
            *(uint4*)(bp + olo) = lo;
        }
    };

    auto compute = [&](int buf) {
        const uint32_t abase = sb + buf * 32768;
        const uint32_t bbase = abase + 16384;
        // (A bf16 col base, B bf16 col base) for the 3 split terms x 2 k16
        const int KP[6][2] = {{0,0},{16,16},{0,32},{16,48},{32,0},{48,16}};
        const int j = lane >> 3, r = lane & 7;
        #pragma unroll
        for (int s = 0; s < 6; s++) {
            const int ka = KP[s][0], kb2 = KP[s][1];
            uint32_t af[4][4], bfr[2][4];
            #pragma unroll
            for (int mt = 0; mt < 4; mt++) {
                uint32_t row  = wm + mt * 16 + (j & 1) * 8 + r;
                uint32_t colb = (ka + (j >> 1) * 8) * 2;
                uint32_t off  = SWZ(row * 128 + colb);
                ldsm4(af[mt], abase + off);
            }
            #pragma unroll
            for (int nt = 0; nt < 2; nt++) {
                uint32_t row  = wn + nt * 16 + (j >> 1) * 8 + r;
                uint32_t colb = (kb2 + (j & 1) * 8) * 2;
                uint32_t off  = SWZ(row * 128 + colb);
                ldsm4(bfr[nt], bbase + off);
            }
            #pragma unroll
            for (int mt = 0; mt < 4; mt++)
                #pragma unroll
                for (int ns = 0; ns < 4; ns++)
                    mma_bf16(acc[mt][ns], af[mt],
                             bfr[ns >> 1][(ns & 1) * 2],
                             bfr[ns >> 1][(ns & 1) * 2 + 1]);
        }
    };

    load_chunk(0, 0);
    __syncthreads();
    #pragma unroll 1
    for (int kc = 0; kc < 8; kc++) {
        int buf = kc & 1;
        if (kc + 1 < 8) load_chunk(kc + 1, buf ^ 1);
        compute(buf);
        __syncthreads();
    }

    // epilogue
    const int g = lane >> 2, tig = lane & 3;
    #pragma unroll
    for (int mt = 0; mt < 4; mt++) {
        int mr = m0 + wm + mt * 16 + g;
        #pragma unroll
        for (int ns = 0; ns < 4; ns++) {
            int col = n0 + wn + ns * 8 + tig * 2;
            float bx = bias[col], by = bias[col + 1];
            if (mr < M) {
                float2 o = {acc[mt][ns][0] + bx, acc[mt][ns][1] + by};
                *(float2*)&C[(size_t)mr * 256 + col] = o;
            }
            if (mr + 8 < M) {
                float2 o = {acc[mt][ns][2] + bx, acc[mt][ns][3] + by};
                *(float2*)&C[(size_t)(mr + 8) * 256 + col] = o;
            }
        }
    }
}

// ---------------------------------------------------------------------------
// Small-GEMM kernel (64x64 tile, 4x4 microtile) — used for the M=3600 GEMMs
// ---------------------------------------------------------------------------
__global__ __launch_bounds__(256)
void gemm_nt_bias(const float* __restrict__ A, const float* __restrict__ B,
                  const float* __restrict__ bias, float* __restrict__ C,
                  int M, int N, int K)
{
    __shared__ float As[32][68];
    __shared__ float Bs[32][68];

    const int tid = threadIdx.x;
    const int tx  = tid & 15;
    const int ty  = tid >> 4;
    const int m0  = blockIdx.y * 64;
    const int n0  = blockIdx.x * 64;

    float acc[4][4] = {};

    for (int k0 = 0; k0 < K; k0 += 32) {
        #pragma unroll
        for (int i = 0; i < 2; i++) {
            int idx = tid + i * 256;
            int r   = idx >> 3;
            int c4  = idx & 7;
            int m   = m0 + r;
            float4 av = (m < M) ? *(const float4*)&A[(size_t)m * K + k0 + c4 * 4]
                                : make_float4(0.f, 0.f, 0.f, 0.f);
            As[c4 * 4 + 0][r] = av.x;
            As[c4 * 4 + 1][r] = av.y;
            As[c4 * 4 + 2][r] = av.z;
            As[c4 * 4 + 3][r] = av.w;
            int n   = n0 + r;
            float4 bv = (n < N) ? *(const float4*)&B[(size_t)n * K + k0 + c4 * 4]
                                : make_float4(0.f, 0.f, 0.f, 0.f);
            Bs[c4 * 4 + 0][r] = bv.x;
            Bs[c4 * 4 + 1][r] = bv.y;
            Bs[c4 * 4 + 2][r] = bv.z;
            Bs[c4 * 4 + 3][r] = bv.w;
        }
        __syncthreads();

        #pragma unroll
        for (int kk = 0; kk < 32; kk++) {
            float4 a = *(const float4*)&As[kk][ty * 4];
            float4 b = *(const float4*)&Bs[kk][tx * 4];
            acc[0][0] += a.x * b.x; acc[0][1] += a.x * b.y;
            acc[0][2] += a.x * b.z; acc[0][3] += a.x * b.w;
            acc[1][0] += a.y * b.x; acc[1][1] += a.y * b.y;
            acc[1][2] += a.y * b.z; acc[1][3] += a.y * b.w;
            acc[2][0] += a.z * b.x; acc[2][1] += a.z * b.y;
            acc[2][2] += a.z * b.z; acc[2][3] += a.z * b.w;
            acc[3][0] += a.w * b.x; acc[3][1] += a.w * b.y;
            acc[3][2] += a.w * b.z; acc[3][3] += a.w * b.w;
        }
        __syncthreads();
    }

    #pragma unroll
    for (int i = 0; i < 4; i++) {
        int m = m0 + ty * 4 + i;
        if (m >= M) continue;
        #pragma unroll
        for (int j = 0; j < 4; j++) {
            int n = n0 + tx * 4 + j;
            if (n < N) C[(size_t)m * N + n] = acc[i][j] + bias[n];
        }
    }
}

// ---------------------------------------------------------------------------
// Deformable sampling: one block per (b, q); 256 threads = (head h, dim d)
// ---------------------------------------------------------------------------
__global__ __launch_bounds__(256)
void msda_sample(const float* __restrict__ vproj,
                 const float* __restrict__ refp,
                 const float* __restrict__ off,
                 const float* __restrict__ logits,
                 const int*   __restrict__ shapes,
                 const int*   __restrict__ lstart,
                 float*       __restrict__ samp,
                 int Lq, int Lv)
{
    const int bq  = blockIdx.x;
    const int b   = bq / Lq;
    const int tid = threadIdx.x;
    const int h   = tid >> 5;
    const int d   = tid & 31;

    __shared__ float s_log[HEADS * LEVELS * POINTS];
    __shared__ float s_off[EMBED];
    __shared__ float s_ref[LEVELS * 2];
    __shared__ int   s_shape[LEVELS * 2];
    __shared__ int   s_start[LEVELS];

    if (tid < 128) s_log[tid] = logits[(size_t)bq * 128 + tid];
    s_off[tid] = off[(size_t)bq * EMBED + tid];
    if (tid < LEVELS * 2) {
        s_ref[tid]   = refp[(size_t)bq * (LEVELS * 2) + tid];
        s_shape[tid] = shapes[tid];
    }
    if (tid < LEVELS) s_start[tid] = lstart[tid];
    __syncthreads();

    float w[LEVELS * POINTS];
    float mx = -1e30f;
    #pragma unroll
    for (int i = 0; i < 16; i++) { w[i] = s_log[h * 16 + i]; mx = fmaxf(mx, w[i]); }
    float sum = 0.f;
    #pragma unroll
    for (int i = 0; i < 16; i++) { w[i] = __expf(w[i] - mx); sum += w[i]; }
    const float inv = 1.f / sum;

    const float* vb = vproj + (size_t)b * Lv * EMBED + h * HEAD_DIM + d;

    float acc = 0.f;
    #pragma unroll
    for (int l = 0; l < LEVELS; l++) {
        const int   Hh = s_shape[l * 2 + 0];
        const int   Ww = s_shape[l * 2 + 1];
        const float Hf = (float)Hh;
        const float Wf = (float)Ww;
        const int   st = s_start[l];
        const float rx = s_ref[l * 2 + 0];
        const float ry = s_ref[l * 2 + 1];
        #pragma unroll
        for (int p = 0; p < POINTS; p++) {
            const int oi = ((h * LEVELS + l) * POINTS + p) * 2;
            const float x = (rx + s_off[oi + 0] / Wf) * Wf - 0.5f;
            const float y = (ry + s_off[oi + 1] / Hf) * Hf - 0.5f;
            const float x0f = floorf(x), y0f = floorf(y);
            const float lx = x - x0f,  ly = y - y0f;
            const int   x0 = (int)x0f, y0 = (int)y0f;
            const float aw = w[l * POINTS + p] * inv;

            const float cw0 = (1.f - lx) * (1.f - ly);
            const float cw1 = lx * (1.f - ly);
            const float cw2 = (1.f - lx) * ly;
            const float cw3 = lx * ly;

            const bool vx0 = (x0 >= 0) & (x0 < Ww);
            const bool vx1 = (x0 + 1 >= 0) & (x0 + 1 < Ww);
            const bool vy0 = (y0 >= 0) & (y0 < Hh);
            const bool vy1 = (y0 + 1 >= 0) & (y0 + 1 < Hh);

            if (vy0) {
                const int rowb = st + y0 * Ww;
                if (vx0) acc += aw * cw0 * vb[(size_t)(rowb + x0)     * EMBED];
                if (vx1) acc += aw * cw1 * vb[(size_t)(rowb + x0 + 1) * EMBED];
            }
            if (vy1) {
                const int rowb = st + (y0 + 1) * Ww;
                if (vx0) acc += aw * cw2 * vb[(size_t)(rowb + x0)     * EMBED];
                if (vx1) acc += aw * cw3 * vb[(size_t)(rowb + x0 + 1) * EMBED];
            }
        }
    }
    samp[(size_t)bq * EMBED + tid] = acc;
}

// ---------------------------------------------------------------------------
// kernel_launch
// ---------------------------------------------------------------------------
extern "C" void kernel_launch(void* const* d_in, const int* in_sizes, int n_in,
                              void* d_out, int out_size)
{
    const float* query   = (const float*)d_in[0];
    const float* refp    = (const float*)d_in[1];
    const float* value   = (const float*)d_in[2];
    const int*   shapes  = (const int*)  d_in[3];
    const int*   lstart  = (const int*)  d_in[4];
    const float* w_value = (const float*)d_in[5];
    const float* b_value = (const float*)d_in[6];
    const float* w_off   = (const float*)d_in[7];
    const float* b_off   = (const float*)d_in[8];
    const float* w_attn  = (const float*)d_in[9];
    const float* b_attn  = (const float*)d_in[10];
    const float* w_out   = (const float*)d_in[11];
    const float* b_out   = (const float*)d_in[12];

    const int Mv = in_sizes[2] / EMBED;   // bs * Lv = 53176
    const int Mq = in_sizes[0] / EMBED;   // bs * Lq = 3600
    const int bs = 4;
    const int Lv = Mv / bs;
    const int Lq = Mq / bs;

    float *vproj, *offb, *logitb, *sampb;
    cudaGetSymbolAddress((void**)&vproj,  g_vproj);
    cudaGetSymbolAddress((void**)&offb,   g_off);
    cudaGetSymbolAddress((void**)&logitb, g_logit);
    cudaGetSymbolAddress((void**)&sampb,  g_samp);

    // 1) value projection via bf16x3 mma.sync
    static bool cfg = false;
    if (!cfg) {
        cudaFuncSetAttribute(vproj_bf16x3,
                             cudaFuncAttributeMaxDynamicSharedMemorySize, 65536);
        cfg = true;
    }
    vproj_bf16x3<<<dim3(2, (Mv + 127) / 128), 256, 65536>>>(
        value, w_value, b_value, vproj, Mv);

    // 2) sampling offsets: [Mq,256] @ w_off^T + b_off
    gemm_nt_bias<<<dim3(EMBED / 64, (Mq + 63) / 64), 256>>>(
        query, w_off, b_off, offb, Mq, EMBED, EMBED);

    // 3) attention logits: [Mq,128] @ w_attn^T + b_attn
    gemm_nt_bias<<<dim3(128 / 64, (Mq + 63) / 64), 256>>>(
        query, w_attn, b_attn, logitb, Mq, 128, EMBED);

    // 4) softmax + bilinear deformable sampling
    msda_sample<<<Mq, 256>>>(vproj, refp, offb, logitb, shapes, lstart,
                             sampb, Lq, Lv);

    // 5) output projection: [Mq,256] @ w_out^T + b_out -> d_out
    gemm_nt_bias<<<dim3(EMBED / 64, (Mq + 63) / 64), 256>>>(
        sampb, w_out, b_out, (float*)d_out, Mq, EMBED, EMBED);
}

// round 5
// speedup vs baseline: 1.8720x; 1.3138x over previous
#include <cuda_runtime.h>
#include <cuda_bf16.h>
#include <cstdint>
#include <cstddef>

#define EMBED    256
#define HEADS    8
#define LEVELS   4
#define POINTS   4
#define HEAD_DIM 32

// ---------------------------------------------------------------------------
// Scratch (static __device__ globals; runtime allocation is forbidden)
// ---------------------------------------------------------------------------
__device__ float g_vproj[4 * 13312 * EMBED];   // projected value  [bs*Lv, 256]
__device__ float g_off  [3600 * EMBED];        // sampling offsets [bs*Lq, 256]
__device__ float g_logit[3600 * 128];          // attn logits      [bs*Lq, 128]
__device__ float g_samp [3600 * EMBED];        // sampled output   [bs*Lq, 256]

// ---------------------------------------------------------------------------
// helpers
// ---------------------------------------------------------------------------
__device__ __forceinline__ uint32_t smem_u32(const void* p) {
    uint32_t a;
    asm("{ .reg .u64 t; cvta.to.shared.u64 t, %1; cvt.u32.u64 %0, t; }"
        : "=r"(a) : "l"(p));
    return a;
}

__device__ __forceinline__ void ldsm4(uint32_t* r, uint32_t addr) {
    asm volatile("ldmatrix.sync.aligned.m8n8.x4.shared.b16 {%0,%1,%2,%3}, [%4];"
                 : "=r"(r[0]), "=r"(r[1]), "=r"(r[2]), "=r"(r[3]) : "r"(addr));
}

__device__ __forceinline__ void mma_bf16(float* c, const uint32_t* a,
                                         uint32_t b0, uint32_t b1) {
    asm volatile(
        "mma.sync.aligned.m16n8k16.row.col.f32.bf16.bf16.f32 "
        "{%0,%1,%2,%3}, {%4,%5,%6,%7}, {%8,%9}, {%0,%1,%2,%3};"
        : "+f"(c[0]), "+f"(c[1]), "+f"(c[2]), "+f"(c[3])
        : "r"(a[0]), "r"(a[1]), "r"(a[2]), "r"(a[3]), "r"(b0), "r"(b1));
}

// convert 8 fp32 -> 8 bf16 hi + 8 bf16 lo (2-term split)
union Pack8 { uint4 u; __nv_bfloat16 b[8]; };
__device__ __forceinline__ void cvt8(const float4& v0, const float4& v1,
                                     uint4& hi, uint4& lo) {
    float f[8] = {v0.x, v0.y, v0.z, v0.w, v1.x, v1.y, v1.z, v1.w};
    Pack8 H, L;
    #pragma unroll
    for (int j = 0; j < 8; j++) {
        __nv_bfloat16 h = __float2bfloat16_rn(f[j]);
        H.b[j] = h;
        L.b[j] = __float2bfloat16_rn(f[j] - __bfloat162float(h));
    }
    hi = H.u; lo = L.u;
}

#define SWZ(o) ((o) ^ (((o) >> 3) & 0x70))

// ---------------------------------------------------------------------------
// Value projection: C[M,256] = A[M,256] @ B[256,256]^T + bias, bf16x3 mma.sync
// Tile 128x128, BK=32 fp32. Pipeline: fetch(kc+1) -> compute(buf) -> cvt+store.
// ---------------------------------------------------------------------------
__global__ __launch_bounds__(256)
void vproj_bf16x3(const float* __restrict__ A, const float* __restrict__ B,
                  const float* __restrict__ bias, float* __restrict__ C, int M)
{
    extern __shared__ char sm[];
    const int tid  = threadIdx.x;
    const int lane = tid & 31;
    const int w    = tid >> 5;
    const int wm   = (w & 1) * 64;       // warp m offset in tile
    const int wn   = (w >> 1) * 32;      // warp n offset in tile
    const int m0   = blockIdx.y * 128;
    const int n0   = blockIdx.x * 128;
    const uint32_t sb = smem_u32(sm);

    float acc[4][4][4] = {};             // [mt][n8tile][4]

    float4 ra[2][2], rb[2][2];           // raw fetched A/B (next chunk)

    auto fetch = [&](int kc) {
        const int kb = kc * 32;
        #pragma unroll
        for (int i = 0; i < 2; i++) {
            int idx = tid + i * 256;       // 0..511
            int row = idx >> 2;            // 0..127
            int seg = idx & 3;             // 8-float segment
            int m = m0 + row;
            if (m < M) {
                ra[i][0] = *(const float4*)&A[(size_t)m * 256 + kb + seg * 8];
                ra[i][1] = *(const float4*)&A[(size_t)m * 256 + kb + seg * 8 + 4];
            } else {
                ra[i][0] = make_float4(0.f, 0.f, 0.f, 0.f);
                ra[i][1] = ra[i][0];
            }
            int n = n0 + row;
            rb[i][0] = *(const float4*)&B[(size_t)n * 256 + kb + seg * 8];
            rb[i][1] = *(const float4*)&B[(size_t)n * 256 + kb + seg * 8 + 4];
        }
    };

    auto store_cvt = [&](int buf) {
        char* ap = sm + buf * 32768;
        char* bp = ap + 16384;
        #pragma unroll
        for (int i = 0; i < 2; i++) {
            int idx = tid + i * 256;
            int row = idx >> 2;
            int seg = idx & 3;
            uint32_t ohi = SWZ((uint32_t)(row * 128 + seg * 16));
            uint32_t olo = SWZ((uint32_t)(row * 128 + 64 + seg * 16));
            uint4 hi, lo;
            cvt8(ra[i][0], ra[i][1], hi, lo);
            *(uint4*)(ap + ohi) = hi;
            *(uint4*)(ap + olo) = lo;
            cvt8(rb[i][0], rb[i][1], hi, lo);
            *(uint4*)(bp + ohi) = hi;
            *(uint4*)(bp + olo) = lo;
        }
    };

    auto compute = [&](int buf) {
        const uint32_t abase = sb + buf * 32768;
        const uint32_t bbase = abase + 16384;
        const int KP[6][2] = {{0,0},{16,16},{0,32},{16,48},{32,0},{48,16}};
        const int j = lane >> 3, r = lane & 7;
        #pragma unroll
        for (int s = 0; s < 6; s++) {
            const int ka = KP[s][0], kb2 = KP[s][1];
            uint32_t af[4][4], bfr[2][4];
            #pragma unroll
            for (int mt = 0; mt < 4; mt++) {
                uint32_t row  = wm + mt * 16 + (j & 1) * 8 + r;
                uint32_t colb = (ka + (j >> 1) * 8) * 2;
                ldsm4(af[mt], abase + SWZ(row * 128 + colb));
            }
            #pragma unroll
            for (int nt = 0; nt < 2; nt++) {
                uint32_t row  = wn + nt * 16 + (j >> 1) * 8 + r;
                uint32_t colb = (kb2 + (j & 1) * 8) * 2;
                ldsm4(bfr[nt], bbase + SWZ(row * 128 + colb));
            }
            #pragma unroll
            for (int mt = 0; mt < 4; mt++)
                #pragma unroll
                for (int ns = 0; ns < 4; ns++)
                    mma_bf16(acc[mt][ns], af[mt],
                             bfr[ns >> 1][(ns & 1) * 2],
                             bfr[ns >> 1][(ns & 1) * 2 + 1]);
        }
    };

    fetch(0);
    store_cvt(0);
    __syncthreads();
    #pragma unroll 1
    for (int kc = 0; kc < 8; kc++) {
        int buf = kc & 1;
        if (kc + 1 < 8) fetch(kc + 1);          // LDG in flight during MMAs
        compute(buf);
        if (kc + 1 < 8) store_cvt(buf ^ 1);     // convert after compute
        __syncthreads();
    }

    // epilogue
    const int g = lane >> 2, tig = lane & 3;
    #pragma unroll
    for (int mt = 0; mt < 4; mt++) {
        int mr = m0 + wm + mt * 16 + g;
        #pragma unroll
        for (int ns = 0; ns < 4; ns++) {
            int col = n0 + wn + ns * 8 + tig * 2;
            float bx = bias[col], by = bias[col + 1];
            if (mr < M) {
                float2 o = {acc[mt][ns][0] + bx, acc[mt][ns][1] + by};
                *(float2*)&C[(size_t)mr * 256 + col] = o;
            }
            if (mr + 8 < M) {
                float2 o = {acc[mt][ns][2] + bx, acc[mt][ns][3] + by};
                *(float2*)&C[(size_t)(mr + 8) * 256 + col] = o;
            }
        }
    }
}

// ---------------------------------------------------------------------------
// Small-GEMM kernel (64x64 tile, 4x4 microtile) — used for the M=3600 GEMMs
// ---------------------------------------------------------------------------
__global__ __launch_bounds__(256)
void gemm_nt_bias(const float* __restrict__ A, const float* __restrict__ B,
                  const float* __restrict__ bias, float* __restrict__ C,
                  int M, int N, int K)
{
    __shared__ float As[32][68];
    __shared__ float Bs[32][68];

    const int tid = threadIdx.x;
    const int tx  = tid & 15;
    const int ty  = tid >> 4;
    const int m0  = blockIdx.y * 64;
    const int n0  = blockIdx.x * 64;

    float acc[4][4] = {};

    for (int k0 = 0; k0 < K; k0 += 32) {
        #pragma unroll
        for (int i = 0; i < 2; i++) {
            int idx = tid + i * 256;
            int r   = idx >> 3;
            int c4  = idx & 7;
            int m   = m0 + r;
            float4 av = (m < M) ? *(const float4*)&A[(size_t)m * K + k0 + c4 * 4]
                                : make_float4(0.f, 0.f, 0.f, 0.f);
            As[c4 * 4 + 0][r] = av.x;
            As[c4 * 4 + 1][r] = av.y;
            As[c4 * 4 + 2][r] = av.z;
            As[c4 * 4 + 3][r] = av.w;
            int n   = n0 + r;
            float4 bv = (n < N) ? *(const float4*)&B[(size_t)n * K + k0 + c4 * 4]
                                : make_float4(0.f, 0.f, 0.f, 0.f);
            Bs[c4 * 4 + 0][r] = bv.x;
            Bs[c4 * 4 + 1][r] = bv.y;
            Bs[c4 * 4 + 2][r] = bv.z;
            Bs[c4 * 4 + 3][r] = bv.w;
        }
        __syncthreads();

        #pragma unroll
        for (int kk = 0; kk < 32; kk++) {
            float4 a = *(const float4*)&As[kk][ty * 4];
            float4 b = *(const float4*)&Bs[kk][tx * 4];
            acc[0][0] += a.x * b.x; acc[0][1] += a.x * b.y;
            acc[0][2] += a.x * b.z; acc[0][3] += a.x * b.w;
            acc[1][0] += a.y * b.x; acc[1][1] += a.y * b.y;
            acc[1][2] += a.y * b.z; acc[1][3] += a.y * b.w;
            acc[2][0] += a.z * b.x; acc[2][1] += a.z * b.y;
            acc[2][2] += a.z * b.z; acc[2][3] += a.z * b.w;
            acc[3][0] += a.w * b.x; acc[3][1] += a.w * b.y;
            acc[3][2] += a.w * b.z; acc[3][3] += a.w * b.w;
        }
        __syncthreads();
    }

    #pragma unroll
    for (int i = 0; i < 4; i++) {
        int m = m0 + ty * 4 + i;
        if (m >= M) continue;
        #pragma unroll
        for (int j = 0; j < 4; j++) {
            int n = n0 + tx * 4 + j;
            if (n < N) C[(size_t)m * N + n] = acc[i][j] + bias[n];
        }
    }
}

// ---------------------------------------------------------------------------
// Deformable sampling v2: one block per (b, q).
// Phase 1: 128 threads (one per (h,l,p)) compute softmax weight + bilinear
//          indices/weights once -> smem.
// Phase 2: 256 threads (h,d) do pure gather + FMA with 4 accumulators.
// ---------------------------------------------------------------------------
__global__ __launch_bounds__(256)
void msda_sample(const float* __restrict__ vproj,
                 const float* __restrict__ refp,     // [bs,Lq,4,2]
                 const float* __restrict__ off,      // [bs*Lq,256]
                 const float* __restrict__ logits,   // [bs*Lq,128]
                 const int*   __restrict__ shapes,   // [4,2] (H,W)
                 const int*   __restrict__ lstart,   // [4]
                 float*       __restrict__ samp,     // [bs*Lq,256]
                 int Lq, int Lv)
{
    const int bq  = blockIdx.x;
    const int b   = bq / Lq;
    const int tid = threadIdx.x;

    __shared__ float s_log[128];
    __shared__ float s_off[EMBED];
    __shared__ float s_ref[LEVELS * 2];
    __shared__ int   s_shape[LEVELS * 2];
    __shared__ int   s_start[LEVELS];
    __shared__ int4   s_idx4[128];   // per (h,l,p): 4 corner flat rows (-1 invalid)
    __shared__ float4 s_w4[128];     // per (h,l,p): 4 corner weights (incl. attn)

    if (tid < 128) s_log[tid] = logits[(size_t)bq * 128 + tid];
    s_off[tid] = off[(size_t)bq * EMBED + tid];
    if (tid < LEVELS * 2) {
        s_ref[tid]   = refp[(size_t)bq * (LEVELS * 2) + tid];
        s_shape[tid] = shapes[tid];
    }
    if (tid < LEVELS) s_start[tid] = lstart[tid];
    __syncthreads();

    if (tid < 128) {
        const int h = tid >> 4;
        const int i = tid & 15;          // l*4+p
        const int l = i >> 2;

        // softmax weight for this combo (16-wide redundant scan per thread)
        float mx = -1e30f;
        #pragma unroll
        for (int j = 0; j < 16; j++) mx = fmaxf(mx, s_log[h * 16 + j]);
        float sum = 0.f;
        #pragma unroll
        for (int j = 0; j < 16; j++) sum += __expf(s_log[h * 16 + j] - mx);
        const float aw = __expf(s_log[tid] - mx) / sum;

        const int   Hh = s_shape[l * 2 + 0];
        const int   Ww = s_shape[l * 2 + 1];
        const float Wf = (float)Ww, Hf = (float)Hh;
        const int   st = s_start[l];
        const float rx = s_ref[l * 2 + 0];
        const float ry = s_ref[l * 2 + 1];

        const float x = (rx + s_off[tid * 2 + 0] / Wf) * Wf - 0.5f;
        const float y = (ry + s_off[tid * 2 + 1] / Hf) * Hf - 0.5f;
        const float x0f = floorf(x), y0f = floorf(y);
        const float lx = x - x0f, ly = y - y0f;
        const int   x0 = (int)x0f, y0 = (int)y0f;

        const bool vx0 = (x0 >= 0) & (x0 < Ww);
        const bool vx1 = (x0 + 1 >= 0) & (x0 + 1 < Ww);
        const bool vy0 = (y0 >= 0) & (y0 < Hh);
        const bool vy1 = (y0 + 1 >= 0) & (y0 + 1 < Hh);

        int4 id;
        id.x = (vy0 && vx0) ? st + y0 * Ww + x0           : -1;
        id.y = (vy0 && vx1) ? st + y0 * Ww + x0 + 1       : -1;
        id.z = (vy1 && vx0) ? st + (y0 + 1) * Ww + x0     : -1;
        id.w = (vy1 && vx1) ? st + (y0 + 1) * Ww + x0 + 1 : -1;

        float4 ww;
        ww.x = aw * (1.f - lx) * (1.f - ly);
        ww.y = aw * lx * (1.f - ly);
        ww.z = aw * (1.f - lx) * ly;
        ww.w = aw * lx * ly;

        s_idx4[tid] = id;
        s_w4[tid]   = ww;
    }
    __syncthreads();

    // Phase 2: gather + FMA
    const int h = tid >> 5;
    const int d = tid & 31;
    const float* vb = vproj + (size_t)b * Lv * EMBED + h * HEAD_DIM + d;

    float a0 = 0.f, a1 = 0.f, a2 = 0.f, a3 = 0.f;
    #pragma unroll 4
    for (int i = 0; i < 16; i++) {
        const int t = h * 16 + i;
        const int4   id = s_idx4[t];
        const float4 ww = s_w4[t];
        if (id.x >= 0) a0 += ww.x * __ldg(vb + (size_t)id.x * EMBED);
        if (id.y >= 0) a1 += ww.y * __ldg(vb + (size_t)id.y * EMBED);
        if (id.z >= 0) a2 += ww.z * __ldg(vb + (size_t)id.z * EMBED);
        if (id.w >= 0) a3 += ww.w * __ldg(vb + (size_t)id.w * EMBED);
    }
    samp[(size_t)bq * EMBED + tid] = (a0 + a1) + (a2 + a3);
}

// ---------------------------------------------------------------------------
// kernel_launch
// ---------------------------------------------------------------------------
extern "C" void kernel_launch(void* const* d_in, const int* in_sizes, int n_in,
                              void* d_out, int out_size)
{
    const float* query   = (const float*)d_in[0];
    const float* refp    = (const float*)d_in[1];
    const float* value   = (const float*)d_in[2];
    const int*   shapes  = (const int*)  d_in[3];
    const int*   lstart  = (const int*)  d_in[4];
    const float* w_value = (const float*)d_in[5];
    const float* b_value = (const float*)d_in[6];
    const float* w_off   = (const float*)d_in[7];
    const float* b_off   = (const float*)d_in[8];
    const float* w_attn  = (const float*)d_in[9];
    const float* b_attn  = (const float*)d_in[10];
    const float* w_out   = (const float*)d_in[11];
    const float* b_out   = (const float*)d_in[12];

    const int Mv = in_sizes[2] / EMBED;   // bs * Lv = 53176
    const int Mq = in_sizes[0] / EMBED;   // bs * Lq = 3600
    const int bs = 4;
    const int Lv = Mv / bs;
    const int Lq = Mq / bs;

    float *vproj, *offb, *logitb, *sampb;
    cudaGetSymbolAddress((void**)&vproj,  g_vproj);
    cudaGetSymbolAddress((void**)&offb,   g_off);
    cudaGetSymbolAddress((void**)&logitb, g_logit);
    cudaGetSymbolAddress((void**)&sampb,  g_samp);

    // 1) value projection via bf16x3 mma.sync (pipelined)
    static bool cfg = false;
    if (!cfg) {
        cudaFuncSetAttribute(vproj_bf16x3,
                             cudaFuncAttributeMaxDynamicSharedMemorySize, 65536);
        cfg = true;
    }
    vproj_bf16x3<<<dim3(2, (Mv + 127) / 128), 256, 65536>>>(
        value, w_value, b_value, vproj, Mv);

    // 2) sampling offsets: [Mq,256] @ w_off^T + b_off
    gemm_nt_bias<<<dim3(EMBED / 64, (Mq + 63) / 64), 256>>>(
        query, w_off, b_off, offb, Mq, EMBED, EMBED);

    // 3) attention logits: [Mq,128] @ w_attn^T + b_attn
    gemm_nt_bias<<<dim3(128 / 64, (Mq + 63) / 64), 256>>>(
        query, w_attn, b_attn, logitb, Mq, 128, EMBED);

    // 4) softmax + bilinear deformable sampling
    msda_sample<<<Mq, 256>>>(vproj, refp, offb, logitb, shapes, lstart,
                             sampb, Lq, Lv);

    // 5) output projection: [Mq,256] @ w_out^T + b_out -> d_out
    gemm_nt_bias<<<dim3(EMBED / 64, (Mq + 63) / 64), 256>>>(
        sampb, w_out, b_out, (float*)d_out, Mq, EMBED, EMBED);
}

// round 6
// speedup vs baseline: 2.0100x; 1.0737x over previous
#include <cuda_runtime.h>
#include <cuda_bf16.h>
#include <cstdint>
#include <cstddef>

#define EMBED    256
#define HEADS    8
#define LEVELS   4
#define POINTS   4
#define HEAD_DIM 32

// ---------------------------------------------------------------------------
// Scratch (static __device__ globals; runtime allocation is forbidden)
// ---------------------------------------------------------------------------
__device__ float g_vproj[4 * 13312 * EMBED];            // projected value
__device__ __nv_bfloat16 g_abf16[53248 * 512];          // value split hi|lo
__device__ __nv_bfloat16 g_bbf16[256 * 512];            // w_value split hi|lo
__device__ float g_off  [3600 * EMBED];                 // sampling offsets
__device__ float g_logit[3600 * 128];                   // attn logits
__device__ float g_samp [3600 * EMBED];                 // sampled output

// ---------------------------------------------------------------------------
// helpers
// ---------------------------------------------------------------------------
__device__ __forceinline__ uint32_t smem_u32(const void* p) {
    uint32_t a;
    asm("{ .reg .u64 t; cvta.to.shared.u64 t, %1; cvt.u32.u64 %0, t; }"
        : "=r"(a) : "l"(p));
    return a;
}

__device__ __forceinline__ void ldsm4(uint32_t* r, uint32_t addr) {
    asm volatile("ldmatrix.sync.aligned.m8n8.x4.shared.b16 {%0,%1,%2,%3}, [%4];"
                 : "=r"(r[0]), "=r"(r[1]), "=r"(r[2]), "=r"(r[3]) : "r"(addr));
}

__device__ __forceinline__ void mma_bf16(float* c, const uint32_t* a,
                                         uint32_t b0, uint32_t b1) {
    asm volatile(
        "mma.sync.aligned.m16n8k16.row.col.f32.bf16.bf16.f32 "
        "{%0,%1,%2,%3}, {%4,%5,%6,%7}, {%8,%9}, {%0,%1,%2,%3};"
        : "+f"(c[0]), "+f"(c[1]), "+f"(c[2]), "+f"(c[3])
        : "r"(a[0]), "r"(a[1]), "r"(a[2]), "r"(a[3]), "r"(b0), "r"(b1));
}

__device__ __forceinline__ void cp_async16(uint32_t saddr, const void* gaddr) {
    asm volatile("cp.async.cg.shared.global [%0], [%1], 16;"
                 :: "r"(saddr), "l"(gaddr) : "memory");
}
#define CP_ASYNC_COMMIT() asm volatile("cp.async.commit_group;" ::: "memory")
#define CP_ASYNC_WAIT(N)  asm volatile("cp.async.wait_group %0;" :: "n"(N) : "memory")

union Pack8 { uint4 u; __nv_bfloat16 b[8]; };
__device__ __forceinline__ void cvt8(const float4& v0, const float4& v1,
                                     uint4& hi, uint4& lo) {
    float f[8] = {v0.x, v0.y, v0.z, v0.w, v1.x, v1.y, v1.z, v1.w};
    Pack8 H, L;
    #pragma unroll
    for (int j = 0; j < 8; j++) {
        __nv_bfloat16 h = __float2bfloat16_rn(f[j]);
        H.b[j] = h;
        L.b[j] = __float2bfloat16_rn(f[j] - __bfloat162float(h));
    }
    hi = H.u; lo = L.u;
}

#define SWZ(o) ((o) ^ (((o) >> 3) & 0x70))

// ---------------------------------------------------------------------------
// Split-convert A (value) and B (w_value) fp32 -> bf16 hi|lo, chunked layout:
// row stride 512 bf16; chunk c (k=32c..32c+31): [c*64 .. c*64+32) hi, +32 lo
// ---------------------------------------------------------------------------
__global__ __launch_bounds__(256)
void cvt_split(const float* __restrict__ A, const float* __restrict__ B,
               __nv_bfloat16* __restrict__ Ab, __nv_bfloat16* __restrict__ Bb,
               int Mv)
{
    int t = blockIdx.x * 256 + threadIdx.x;      // one thread per 8 floats
    int total = (Mv + 256) * 32;
    if (t >= total) return;
    int row = t >> 5;
    int s8  = t & 31;
    int kc  = s8 >> 2;
    int seg = s8 & 3;
    const float* src;
    __nv_bfloat16* dst;
    if (row < Mv) { src = A + (size_t)row * 256; dst = Ab + (size_t)row * 512; }
    else { src = B + (size_t)(row - Mv) * 256; dst = Bb + (size_t)(row - Mv) * 512; }
    float4 v0 = *(const float4*)(src + kc * 32 + seg * 8);
    float4 v1 = *(const float4*)(src + kc * 32 + seg * 8 + 4);
    uint4 hi, lo;
    cvt8(v0, v1, hi, lo);
    *(uint4*)(dst + kc * 64 + seg * 8)      = hi;
    *(uint4*)(dst + kc * 64 + 32 + seg * 8) = lo;
}

// ---------------------------------------------------------------------------
// SIMT small-GEMM body (64x64 tile, 4x4 microtile), device function on
// caller-provided dynamic smem.  C[M,N] = A[M,K=256] * B[N,K]^T + bias.
// ---------------------------------------------------------------------------
__device__ void gemm_small_body(const float* __restrict__ A,
                                const float* __restrict__ B,
                                const float* __restrict__ bias,
                                float* __restrict__ C,
                                int M, int N, int m0, int n0, char* smraw)
{
    float (*As)[68] = (float (*)[68])smraw;
    float (*Bs)[68] = (float (*)[68])(smraw + 32 * 68 * 4);

    const int tid = threadIdx.x;
    const int tx  = tid & 15;
    const int ty  = tid >> 4;

    float acc[4][4] = {};

    for (int k0 = 0; k0 < 256; k0 += 32) {
        #pragma unroll
        for (int i = 0; i < 2; i++) {
            int idx = tid + i * 256;
            int r   = idx >> 3;
            int c4  = idx & 7;
            int m   = m0 + r;
            float4 av = (m < M) ? *(const float4*)&A[(size_t)m * 256 + k0 + c4 * 4]
                                : make_float4(0.f, 0.f, 0.f, 0.f);
            As[c4 * 4 + 0][r] = av.x;
            As[c4 * 4 + 1][r] = av.y;
            As[c4 * 4 + 2][r] = av.z;
            As[c4 * 4 + 3][r] = av.w;
            int n   = n0 + r;
            float4 bv = (n < N) ? *(const float4*)&B[(size_t)n * 256 + k0 + c4 * 4]
                                : make_float4(0.f, 0.f, 0.f, 0.f);
            Bs[c4 * 4 + 0][r] = bv.x;
            Bs[c4 * 4 + 1][r] = bv.y;
            Bs[c4 * 4 + 2][r] = bv.z;
            Bs[c4 * 4 + 3][r] = bv.w;
        }
        __syncthreads();

        #pragma unroll
        for (int kk = 0; kk < 32; kk++) {
            float4 a = *(const float4*)&As[kk][ty * 4];
            float4 b = *(const float4*)&Bs[kk][tx * 4];
            acc[0][0] += a.x * b.x; acc[0][1] += a.x * b.y;
            acc[0][2] += a.x * b.z; acc[0][3] += a.x * b.w;
            acc[1][0] += a.y * b.x; acc[1][1] += a.y * b.y;
            acc[1][2] += a.y * b.z; acc[1][3] += a.y * b.w;
            acc[2][0] += a.z * b.x; acc[2][1] += a.z * b.y;
            acc[2][2] += a.z * b.z; acc[2][3] += a.z * b.w;
            acc[3][0] += a.w * b.x; acc[3][1] += a.w * b.y;
            acc[3][2] += a.w * b.z; acc[3][3] += a.w * b.w;
        }
        __syncthreads();
    }

    #pragma unroll
    for (int i = 0; i < 4; i++) {
        int m = m0 + ty * 4 + i;
        if (m >= M) continue;
        #pragma unroll
        for (int j = 0; j < 4; j++) {
            int n = n0 + tx * 4 + j;
            if (n < N) C[(size_t)m * N + n] = acc[i][j] + bias[n];
        }
    }
}

// ---------------------------------------------------------------------------
// Fat kernel:
//   blocks [0, 2*MB)           : vproj bf16x3 mma.sync, cp.async mainloop
//   blocks [2*MB, +228)        : offsets GEMM  [Mq,256]
//   blocks [.., +114)          : logits  GEMM  [Mq,128]
// ---------------------------------------------------------------------------
__global__ __launch_bounds__(256)
void fat_gemms(const __nv_bfloat16* __restrict__ Ab,
               const __nv_bfloat16* __restrict__ Bb,
               const float* __restrict__ b_value,
               float* __restrict__ Cv, int Mv, int MB,
               const float* __restrict__ query,
               const float* __restrict__ w_off, const float* __restrict__ b_off,
               float* __restrict__ offb,
               const float* __restrict__ w_attn, const float* __restrict__ b_attn,
               float* __restrict__ logitb, int Mq)
{
    extern __shared__ char sm[];
    const int bx = blockIdx.x;

    if (bx >= 2 * MB) {
        int ix = bx - 2 * MB;
        if (ix < 228) {            // offsets: 57 m-blocks x 4 n-blocks
            gemm_small_body(query, w_off, b_off, offb, Mq, 256,
                            (ix >> 2) * 64, (ix & 3) * 64, sm);
        } else {                   // logits: 57 m-blocks x 2 n-blocks
            ix -= 228;
            gemm_small_body(query, w_attn, b_attn, logitb, Mq, 128,
                            (ix >> 1) * 64, (ix & 1) * 64, sm);
        }
        return;
    }

    // ---------------- vproj path ----------------
    const int tid  = threadIdx.x;
    const int lane = tid & 31;
    const int w    = tid >> 5;
    const int wm   = (w & 1) * 64;
    const int wn   = (w >> 1) * 32;
    const int m0   = (bx >> 1) * 128;
    const int n0   = (bx & 1) * 128;
    const uint32_t sb = smem_u32(sm);

    float acc[4][4][4] = {};

    // cp.async prefetch of chunk kc into buffer buf
    auto prefetch = [&](int kc, int buf) {
        const uint32_t abase = sb + buf * 32768;
        const uint32_t bbase = abase + 16384;
        #pragma unroll
        for (int i = 0; i < 4; i++) {
            int idx = tid + i * 256;     // 0..1023
            int row = idx >> 3;          // 0..127
            int seg = idx & 7;           // 16B segment in 128B row
            uint32_t so = SWZ((uint32_t)(row * 128 + seg * 16));
            cp_async16(abase + so,
                       Ab + ((size_t)(m0 + row) * 512 + kc * 64 + seg * 8));
            cp_async16(bbase + so,
                       Bb + ((size_t)(n0 + row) * 512 + kc * 64 + seg * 8));
        }
    };

    auto compute = [&](int buf) {
        const uint32_t abase = sb + buf * 32768;
        const uint32_t bbase = abase + 16384;
        const int KP[6][2] = {{0,0},{16,16},{0,32},{16,48},{32,0},{48,16}};
        const int j = lane >> 3, r = lane & 7;
        #pragma unroll
        for (int s = 0; s < 6; s++) {
            const int ka = KP[s][0], kb2 = KP[s][1];
            uint32_t af[4][4], bfr[2][4];
            #pragma unroll
            for (int mt = 0; mt < 4; mt++) {
                uint32_t row  = wm + mt * 16 + (j & 1) * 8 + r;
                uint32_t colb = (ka + (j >> 1) * 8) * 2;
                ldsm4(af[mt], abase + SWZ(row * 128 + colb));
            }
            #pragma unroll
            for (int nt = 0; nt < 2; nt++) {
                uint32_t row  = wn + nt * 16 + (j >> 1) * 8 + r;
                uint32_t colb = (kb2 + (j & 1) * 8) * 2;
                ldsm4(bfr[nt], bbase + SWZ(row * 128 + colb));
            }
            #pragma unroll
            for (int mt = 0; mt < 4; mt++)
                #pragma unroll
                for (int ns = 0; ns < 4; ns++)
                    mma_bf16(acc[mt][ns], af[mt],
                             bfr[ns >> 1][(ns & 1) * 2],
                             bfr[ns >> 1][(ns & 1) * 2 + 1]);
        }
    };

    prefetch(0, 0);
    CP_ASYNC_COMMIT();
    #pragma unroll 1
    for (int kc = 0; kc < 8; kc++) {
        int buf = kc & 1;
        if (kc + 1 < 8) {
            prefetch(kc + 1, buf ^ 1);
            CP_ASYNC_COMMIT();
            CP_ASYNC_WAIT(1);
        } else {
            CP_ASYNC_WAIT(0);
        }
        __syncthreads();
        compute(buf);
        __syncthreads();
    }

    // epilogue
    const int g = lane >> 2, tig = lane & 3;
    #pragma unroll
    for (int mt = 0; mt < 4; mt++) {
        int mr = m0 + wm + mt * 16 + g;
        #pragma unroll
        for (int ns = 0; ns < 4; ns++) {
            int col = n0 + wn + ns * 8 + tig * 2;
            float bxv = b_value[col], byv = b_value[col + 1];
            if (mr < Mv) {
                float2 o = {acc[mt][ns][0] + bxv, acc[mt][ns][1] + byv};
                *(float2*)&Cv[(size_t)mr * 256 + col] = o;
            }
            if (mr + 8 < Mv) {
                float2 o = {acc[mt][ns][2] + bxv, acc[mt][ns][3] + byv};
                *(float2*)&Cv[(size_t)(mr + 8) * 256 + col] = o;
            }
        }
    }
}

// ---------------------------------------------------------------------------
// Standalone small GEMM (used for the final output projection)
// ---------------------------------------------------------------------------
__global__ __launch_bounds__(256)
void gemm_nt_bias(const float* __restrict__ A, const float* __restrict__ B,
                  const float* __restrict__ bias, float* __restrict__ C,
                  int M, int N)
{
    __shared__ char smraw[2 * 32 * 68 * 4];
    gemm_small_body(A, B, bias, C, M, N, blockIdx.y * 64, blockIdx.x * 64, smraw);
}

// ---------------------------------------------------------------------------
// Deformable sampling v2 (unchanged from round 5)
// ---------------------------------------------------------------------------
__global__ __launch_bounds__(256)
void msda_sample(const float* __restrict__ vproj,
                 const float* __restrict__ refp,
                 const float* __restrict__ off,
                 const float* __restrict__ logits,
                 const int*   __restrict__ shapes,
                 const int*   __restrict__ lstart,
                 float*       __restrict__ samp,
                 int Lq, int Lv)
{
    const int bq  = blockIdx.x;
    const int b   = bq / Lq;
    const int tid = threadIdx.x;

    __shared__ float s_log[128];
    __shared__ float s_off[EMBED];
    __shared__ float s_ref[LEVELS * 2];
    __shared__ int   s_shape[LEVELS * 2];
    __shared__ int   s_start[LEVELS];
    __shared__ int4   s_idx4[128];
    __shared__ float4 s_w4[128];

    if (tid < 128) s_log[tid] = logits[(size_t)bq * 128 + tid];
    s_off[tid] = off[(size_t)bq * EMBED + tid];
    if (tid < LEVELS * 2) {
        s_ref[tid]   = refp[(size_t)bq * (LEVELS * 2) + tid];
        s_shape[tid] = shapes[tid];
    }
    if (tid < LEVELS) s_start[tid] = lstart[tid];
    __syncthreads();

    if (tid < 128) {
        const int h = tid >> 4;
        const int i = tid & 15;
        const int l = i >> 2;

        float mx = -1e30f;
        #pragma unroll
        for (int j = 0; j < 16; j++) mx = fmaxf(mx, s_log[h * 16 + j]);
        float sum = 0.f;
        #pragma unroll
        for (int j = 0; j < 16; j++) sum += __expf(s_log[h * 16 + j] - mx);
        const float aw = __expf(s_log[tid] - mx) / sum;

        const int   Hh = s_shape[l * 2 + 0];
        const int   Ww = s_shape[l * 2 + 1];
        const float Wf = (float)Ww, Hf = (float)Hh;
        const int   st = s_start[l];
        const float rx = s_ref[l * 2 + 0];
        const float ry = s_ref[l * 2 + 1];

        const float x = (rx + s_off[tid * 2 + 0] / Wf) * Wf - 0.5f;
        const float y = (ry + s_off[tid * 2 + 1] / Hf) * Hf - 0.5f;
        const float x0f = floorf(x), y0f = floorf(y);
        const float lx = x - x0f, ly = y - y0f;
        const int   x0 = (int)x0f, y0 = (int)y0f;

        const bool vx0 = (x0 >= 0) & (x0 < Ww);
        const bool vx1 = (x0 + 1 >= 0) & (x0 + 1 < Ww);
        const bool vy0 = (y0 >= 0) & (y0 < Hh);
        const bool vy1 = (y0 + 1 >= 0) & (y0 + 1 < Hh);

        int4 id;
        id.x = (vy0 && vx0) ? st + y0 * Ww + x0           : -1;
        id.y = (vy0 && vx1) ? st + y0 * Ww + x0 + 1       : -1;
        id.z = (vy1 && vx0) ? st + (y0 + 1) * Ww + x0     : -1;
        id.w = (vy1 && vx1) ? st + (y0 + 1) * Ww + x0 + 1 : -1;

        float4 ww;
        ww.x = aw * (1.f - lx) * (1.f - ly);
        ww.y = aw * lx * (1.f - ly);
        ww.z = aw * (1.f - lx) * ly;
        ww.w = aw * lx * ly;

        s_idx4[tid] = id;
        s_w4[tid]   = ww;
    }
    __syncthreads();

    const int h = tid >> 5;
    const int d = tid & 31;
    const float* vb = vproj + (size_t)b * Lv * EMBED + h * HEAD_DIM + d;

    float a0 = 0.f, a1 = 0.f, a2 = 0.f, a3 = 0.f;
    #pragma unroll 4
    for (int i = 0; i < 16; i++) {
        const int t = h * 16 + i;
        const int4   id = s_idx4[t];
        const float4 ww = s_w4[t];
        if (id.x >= 0) a0 += ww.x * __ldg(vb + (size_t)id.x * EMBED);
        if (id.y >= 0) a1 += ww.y * __ldg(vb + (size_t)id.y * EMBED);
        if (id.z >= 0) a2 += ww.z * __ldg(vb + (size_t)id.z * EMBED);
        if (id.w >= 0) a3 += ww.w * __ldg(vb + (size_t)id.w * EMBED);
    }
    samp[(size_t)bq * EMBED + tid] = (a0 + a1) + (a2 + a3);
}

// ---------------------------------------------------------------------------
// kernel_launch
// ---------------------------------------------------------------------------
extern "C" void kernel_launch(void* const* d_in, const int* in_sizes, int n_in,
                              void* d_out, int out_size)
{
    const float* query   = (const float*)d_in[0];
    const float* refp    = (const float*)d_in[1];
    const float* value   = (const float*)d_in[2];
    const int*   shapes  = (const int*)  d_in[3];
    const int*   lstart  = (const int*)  d_in[4];
    const float* w_value = (const float*)d_in[5];
    const float* b_value = (const float*)d_in[6];
    const float* w_off   = (const float*)d_in[7];
    const float* b_off   = (const float*)d_in[8];
    const float* w_attn  = (const float*)d_in[9];
    const float* b_attn  = (const float*)d_in[10];
    const float* w_out   = (const float*)d_in[11];
    const float* b_out   = (const float*)d_in[12];

    const int Mv = in_sizes[2] / EMBED;   // bs * Lv = 53176
    const int Mq = in_sizes[0] / EMBED;   // bs * Lq = 3600
    const int bs = 4;
    const int Lv = Mv / bs;
    const int Lq = Mq / bs;

    float *vproj, *offb, *logitb, *sampb;
    __nv_bfloat16 *abf, *bbf;
    cudaGetSymbolAddress((void**)&vproj,  g_vproj);
    cudaGetSymbolAddress((void**)&offb,   g_off);
    cudaGetSymbolAddress((void**)&logitb, g_logit);
    cudaGetSymbolAddress((void**)&sampb,  g_samp);
    cudaGetSymbolAddress((void**)&abf,    g_abf16);
    cudaGetSymbolAddress((void**)&bbf,    g_bbf16);

    // 1) split-convert value + w_value to bf16 hi|lo
    {
        int total = (Mv + 256) * 32;
        cvt_split<<<(total + 255) / 256, 256>>>(value, w_value, abf, bbf, Mv);
    }

    // 2) fat kernel: vproj (tensor) + offsets GEMM + logits GEMM
    const int MB = (Mv + 127) / 128;               // 416
    static bool cfg = false;
    if (!cfg) {
        cudaFuncSetAttribute(fat_gemms,
                             cudaFuncAttributeMaxDynamicSharedMemorySize, 65536);
        cfg = true;
    }
    fat_gemms<<<2 * MB + 228 + 114, 256, 65536>>>(
        abf, bbf, b_value, vproj, Mv, MB,
        query, w_off, b_off, offb, w_attn, b_attn, logitb, Mq);

    // 3) softmax + bilinear deformable sampling
    msda_sample<<<Mq, 256>>>(vproj, refp, offb, logitb, shapes, lstart,
                             sampb, Lq, Lv);

    // 4) output projection -> d_out
    gemm_nt_bias<<<dim3(EMBED / 64, (Mq + 63) / 64), 256>>>(
        sampb, w_out, b_out, (float*)d_out, Mq, EMBED);
}

// round 7
// speedup vs baseline: 2.2389x; 1.1139x over previous
#include <cuda_runtime.h>
#include <cuda_bf16.h>
#include <cstdint>
#include <cstddef>

#define EMBED    256
#define HEADS    8
#define LEVELS   4
#define POINTS   4
#define HEAD_DIM 32

// ---------------------------------------------------------------------------
// Scratch (static __device__ globals; runtime allocation is forbidden)
// ---------------------------------------------------------------------------
__device__ float g_vproj[4 * 13312 * EMBED];            // projected value
__device__ __nv_bfloat16 g_abf16[53248 * 512];          // value split hi|lo
__device__ __nv_bfloat16 g_bbf16[256 * 512];            // w_value split hi|lo
__device__ float g_off  [3600 * EMBED];                 // sampling offsets
__device__ float g_logit[3600 * 128];                   // attn logits
__device__ float g_samp [3600 * EMBED];                 // sampled output

// ---------------------------------------------------------------------------
// helpers
// ---------------------------------------------------------------------------
__device__ __forceinline__ uint32_t smem_u32(const void* p) {
    uint32_t a;
    asm("{ .reg .u64 t; cvta.to.shared.u64 t, %1; cvt.u32.u64 %0, t; }"
        : "=r"(a) : "l"(p));
    return a;
}

__device__ __forceinline__ void ldsm4(uint32_t* r, uint32_t addr) {
    asm volatile("ldmatrix.sync.aligned.m8n8.x4.shared.b16 {%0,%1,%2,%3}, [%4];"
                 : "=r"(r[0]), "=r"(r[1]), "=r"(r[2]), "=r"(r[3]) : "r"(addr));
}

__device__ __forceinline__ void mma_bf16(float* c, const uint32_t* a,
                                         uint32_t b0, uint32_t b1) {
    asm volatile(
        "mma.sync.aligned.m16n8k16.row.col.f32.bf16.bf16.f32 "
        "{%0,%1,%2,%3}, {%4,%5,%6,%7}, {%8,%9}, {%0,%1,%2,%3};"
        : "+f"(c[0]), "+f"(c[1]), "+f"(c[2]), "+f"(c[3])
        : "r"(a[0]), "r"(a[1]), "r"(a[2]), "r"(a[3]), "r"(b0), "r"(b1));
}

__device__ __forceinline__ void cp_async16(uint32_t saddr, const void* gaddr) {
    asm volatile("cp.async.cg.shared.global [%0], [%1], 16;"
                 :: "r"(saddr), "l"(gaddr) : "memory");
}
#define CP_ASYNC_COMMIT() asm volatile("cp.async.commit_group;" ::: "memory")
#define CP_ASYNC_WAIT(N)  asm volatile("cp.async.wait_group %0;" :: "n"(N) : "memory")

union Pack8 { uint4 u; __nv_bfloat16 b[8]; };
__device__ __forceinline__ void cvt8(const float4& v0, const float4& v1,
                                     uint4& hi, uint4& lo) {
    float f[8] = {v0.x, v0.y, v0.z, v0.w, v1.x, v1.y, v1.z, v1.w};
    Pack8 H, L;
    #pragma unroll
    for (int j = 0; j < 8; j++) {
        __nv_bfloat16 h = __float2bfloat16_rn(f[j]);
        H.b[j] = h;
        L.b[j] = __float2bfloat16_rn(f[j] - __bfloat162float(h));
    }
    hi = H.u; lo = L.u;
}

#define SWZ(o) ((o) ^ (((o) >> 3) & 0x70))

// ---------------------------------------------------------------------------
// Split-convert A (value) + B (w_value) fp32 -> bf16 hi|lo, AND initialize
// d_out with the output bias (extra blocks at the tail of the grid).
// ---------------------------------------------------------------------------
__global__ __launch_bounds__(256)
void cvt_split_init(const float* __restrict__ A, const float* __restrict__ B,
                    __nv_bfloat16* __restrict__ Ab, __nv_bfloat16* __restrict__ Bb,
                    int Mv, int cvt_total,
                    float* __restrict__ outp, const float* __restrict__ b_out,
                    int Mq)
{
    int t = blockIdx.x * 256 + threadIdx.x;
    if (t < cvt_total) {
        int row = t >> 5;
        int s8  = t & 31;
        int kc  = s8 >> 2;
        int seg = s8 & 3;
        const float* src;
        __nv_bfloat16* dst;
        if (row < Mv) { src = A + (size_t)row * 256; dst = Ab + (size_t)row * 512; }
        else { src = B + (size_t)(row - Mv) * 256; dst = Bb + (size_t)(row - Mv) * 512; }
        float4 v0 = *(const float4*)(src + kc * 32 + seg * 8);
        float4 v1 = *(const float4*)(src + kc * 32 + seg * 8 + 4);
        uint4 hi, lo;
        cvt8(v0, v1, hi, lo);
        *(uint4*)(dst + kc * 64 + seg * 8)      = hi;
        *(uint4*)(dst + kc * 64 + 32 + seg * 8) = lo;
    } else {
        // bias init of d_out: one float4 per thread
        int t2 = t - cvt_total;
        if (t2 < Mq * 64) {
            int row = t2 >> 6;
            int c4  = t2 & 63;
            float4 bv = *(const float4*)(b_out + c4 * 4);
            *(float4*)(outp + (size_t)row * 256 + c4 * 4) = bv;
        }
    }
}

// ---------------------------------------------------------------------------
// SIMT small-GEMM body (64x64 tile, 4x4 microtile) on caller smem.
// C[M,N] = A[M,K=256] * B[N,K]^T + bias.
// ---------------------------------------------------------------------------
__device__ void gemm_small_body(const float* __restrict__ A,
                                const float* __restrict__ B,
                                const float* __restrict__ bias,
                                float* __restrict__ C,
                                int M, int N, int m0, int n0, char* smraw)
{
    float (*As)[68] = (float (*)[68])smraw;
    float (*Bs)[68] = (float (*)[68])(smraw + 32 * 68 * 4);

    const int tid = threadIdx.x;
    const int tx  = tid & 15;
    const int ty  = tid >> 4;

    float acc[4][4] = {};

    for (int k0 = 0; k0 < 256; k0 += 32) {
        #pragma unroll
        for (int i = 0; i < 2; i++) {
            int idx = tid + i * 256;
            int r   = idx >> 3;
            int c4  = idx & 7;
            int m   = m0 + r;
            float4 av = (m < M) ? *(const float4*)&A[(size_t)m * 256 + k0 + c4 * 4]
                                : make_float4(0.f, 0.f, 0.f, 0.f);
            As[c4 * 4 + 0][r] = av.x;
            As[c4 * 4 + 1][r] = av.y;
            As[c4 * 4 + 2][r] = av.z;
            As[c4 * 4 + 3][r] = av.w;
            int n   = n0 + r;
            float4 bv = (n < N) ? *(const float4*)&B[(size_t)n * 256 + k0 + c4 * 4]
                                : make_float4(0.f, 0.f, 0.f, 0.f);
            Bs[c4 * 4 + 0][r] = bv.x;
            Bs[c4 * 4 + 1][r] = bv.y;
            Bs[c4 * 4 + 2][r] = bv.z;
            Bs[c4 * 4 + 3][r] = bv.w;
        }
        __syncthreads();

        #pragma unroll
        for (int kk = 0; kk < 32; kk++) {
            float4 a = *(const float4*)&As[kk][ty * 4];
            float4 b = *(const float4*)&Bs[kk][tx * 4];
            acc[0][0] += a.x * b.x; acc[0][1] += a.x * b.y;
            acc[0][2] += a.x * b.z; acc[0][3] += a.x * b.w;
            acc[1][0] += a.y * b.x; acc[1][1] += a.y * b.y;
            acc[1][2] += a.y * b.z; acc[1][3] += a.y * b.w;
            acc[2][0] += a.z * b.x; acc[2][1] += a.z * b.y;
            acc[2][2] += a.z * b.z; acc[2][3] += a.z * b.w;
            acc[3][0] += a.w * b.x; acc[3][1] += a.w * b.y;
            acc[3][2] += a.w * b.z; acc[3][3] += a.w * b.w;
        }
        __syncthreads();
    }

    #pragma unroll
    for (int i = 0; i < 4; i++) {
        int m = m0 + ty * 4 + i;
        if (m >= M) continue;
        #pragma unroll
        for (int j = 0; j < 4; j++) {
            int n = n0 + tx * 4 + j;
            if (n < N) C[(size_t)m * N + n] = acc[i][j] + bias[n];
        }
    }
}

// ---------------------------------------------------------------------------
// Fat kernel (forced 2 CTAs/SM):
//   blocks [0, 2*MB)    : vproj bf16x3 mma.sync, cp.async mainloop
//   blocks [2*MB, +228) : offsets GEMM  [Mq,256]
//   blocks [.., +114)   : logits  GEMM  [Mq,128]
// ---------------------------------------------------------------------------
__global__ __launch_bounds__(256, 2)
void fat_gemms(const __nv_bfloat16* __restrict__ Ab,
               const __nv_bfloat16* __restrict__ Bb,
               const float* __restrict__ b_value,
               float* __restrict__ Cv, int Mv, int MB,
               const float* __restrict__ query,
               const float* __restrict__ w_off, const float* __restrict__ b_off,
               float* __restrict__ offb,
               const float* __restrict__ w_attn, const float* __restrict__ b_attn,
               float* __restrict__ logitb, int Mq)
{
    extern __shared__ char sm[];
    const int bx = blockIdx.x;

    if (bx >= 2 * MB) {
        int ix = bx - 2 * MB;
        if (ix < 228) {
            gemm_small_body(query, w_off, b_off, offb, Mq, 256,
                            (ix >> 2) * 64, (ix & 3) * 64, sm);
        } else {
            ix -= 228;
            gemm_small_body(query, w_attn, b_attn, logitb, Mq, 128,
                            (ix >> 1) * 64, (ix & 1) * 64, sm);
        }
        return;
    }

    // ---------------- vproj path ----------------
    const int tid  = threadIdx.x;
    const int lane = tid & 31;
    const int w    = tid >> 5;
    const int wm   = (w & 1) * 64;
    const int wn   = (w >> 1) * 32;
    const int m0   = (bx >> 1) * 128;
    const int n0   = (bx & 1) * 128;
    const uint32_t sb = smem_u32(sm);

    float acc[4][4][4] = {};

    auto prefetch = [&](int kc, int buf) {
        const uint32_t abase = sb + buf * 32768;
        const uint32_t bbase = abase + 16384;
        #pragma unroll
        for (int i = 0; i < 4; i++) {
            int idx = tid + i * 256;
            int row = idx >> 3;
            int seg = idx & 7;
            uint32_t so = SWZ((uint32_t)(row * 128 + seg * 16));
            cp_async16(abase + so,
                       Ab + ((size_t)(m0 + row) * 512 + kc * 64 + seg * 8));
            cp_async16(bbase + so,
                       Bb + ((size_t)(n0 + row) * 512 + kc * 64 + seg * 8));
        }
    };

    auto compute = [&](int buf) {
        const uint32_t abase = sb + buf * 32768;
        const uint32_t bbase = abase + 16384;
        const int KP[6][2] = {{0,0},{16,16},{0,32},{16,48},{32,0},{48,16}};
        const int j = lane >> 3, r = lane & 7;
        #pragma unroll
        for (int s = 0; s < 6; s++) {
            const int ka = KP[s][0], kb2 = KP[s][1];
            uint32_t af[4][4], bfr[2][4];
            #pragma unroll
            for (int mt = 0; mt < 4; mt++) {
                uint32_t row  = wm + mt * 16 + (j & 1) * 8 + r;
                uint32_t colb = (ka + (j >> 1) * 8) * 2;
                ldsm4(af[mt], abase + SWZ(row * 128 + colb));
            }
            #pragma unroll
            for (int nt = 0; nt < 2; nt++) {
                uint32_t row  = wn + nt * 16 + (j >> 1) * 8 + r;
                uint32_t colb = (kb2 + (j & 1) * 8) * 2;
                ldsm4(bfr[nt], bbase + SWZ(row * 128 + colb));
            }
            #pragma unroll
            for (int mt = 0; mt < 4; mt++)
                #pragma unroll
                for (int ns = 0; ns < 4; ns++)
                    mma_bf16(acc[mt][ns], af[mt],
                             bfr[ns >> 1][(ns & 1) * 2],
                             bfr[ns >> 1][(ns & 1) * 2 + 1]);
        }
    };

    prefetch(0, 0);
    CP_ASYNC_COMMIT();
    #pragma unroll 1
    for (int kc = 0; kc < 8; kc++) {
        int buf = kc & 1;
        if (kc + 1 < 8) {
            prefetch(kc + 1, buf ^ 1);
            CP_ASYNC_COMMIT();
            CP_ASYNC_WAIT(1);
        } else {
            CP_ASYNC_WAIT(0);
        }
        __syncthreads();
        compute(buf);
        __syncthreads();
    }

    const int g = lane >> 2, tig = lane & 3;
    #pragma unroll
    for (int mt = 0; mt < 4; mt++) {
        int mr = m0 + wm + mt * 16 + g;
        #pragma unroll
        for (int ns = 0; ns < 4; ns++) {
            int col = n0 + wn + ns * 8 + tig * 2;
            float bxv = b_value[col], byv = b_value[col + 1];
            if (mr < Mv) {
                float2 o = {acc[mt][ns][0] + bxv, acc[mt][ns][1] + byv};
                *(float2*)&Cv[(size_t)mr * 256 + col] = o;
            }
            if (mr + 8 < Mv) {
                float2 o = {acc[mt][ns][2] + bxv, acc[mt][ns][3] + byv};
                *(float2*)&Cv[(size_t)(mr + 8) * 256 + col] = o;
            }
        }
    }
}

// ---------------------------------------------------------------------------
// Output projection, split-K x4 with atomic accumulation.
// grid: (4 n-blocks, ceil(M/64) m-blocks, 4 k-slices). d_out pre-set to bias.
// ---------------------------------------------------------------------------
__global__ __launch_bounds__(256)
void outproj_splitk(const float* __restrict__ A, const float* __restrict__ B,
                    float* __restrict__ C, int M)
{
    __shared__ float As[32][68];
    __shared__ float Bs[32][68];

    const int tid = threadIdx.x;
    const int tx  = tid & 15;
    const int ty  = tid >> 4;
    const int m0  = blockIdx.y * 64;
    const int n0  = blockIdx.x * 64;
    const int k0  = blockIdx.z * 64;

    float acc[4][4] = {};

    #pragma unroll
    for (int kc = 0; kc < 2; kc++) {
        const int kb = k0 + kc * 32;
        #pragma unroll
        for (int i = 0; i < 2; i++) {
            int idx = tid + i * 256;
            int r   = idx >> 3;
            int c4  = idx & 7;
            int m   = m0 + r;
            float4 av = (m < M) ? *(const float4*)&A[(size_t)m * 256 + kb + c4 * 4]
                                : make_float4(0.f, 0.f, 0.f, 0.f);
            As[c4 * 4 + 0][r] = av.x;
            As[c4 * 4 + 1][r] = av.y;
            As[c4 * 4 + 2][r] = av.z;
            As[c4 * 4 + 3][r] = av.w;
            int n = n0 + r;
            float4 bv = *(const float4*)&B[(size_t)n * 256 + kb + c4 * 4];
            Bs[c4 * 4 + 0][r] = bv.x;
            Bs[c4 * 4 + 1][r] = bv.y;
            Bs[c4 * 4 + 2][r] = bv.z;
            Bs[c4 * 4 + 3][r] = bv.w;
        }
        __syncthreads();

        #pragma unroll
        for (int kk = 0; kk < 32; kk++) {
            float4 a = *(const float4*)&As[kk][ty * 4];
            float4 b = *(const float4*)&Bs[kk][tx * 4];
            acc[0][0] += a.x * b.x; acc[0][1] += a.x * b.y;
            acc[0][2] += a.x * b.z; acc[0][3] += a.x * b.w;
            acc[1][0] += a.y * b.x; acc[1][1] += a.y * b.y;
            acc[1][2] += a.y * b.z; acc[1][3] += a.y * b.w;
            acc[2][0] += a.z * b.x; acc[2][1] += a.z * b.y;
            acc[2][2] += a.z * b.z; acc[2][3] += a.z * b.w;
            acc[3][0] += a.w * b.x; acc[3][1] += a.w * b.y;
            acc[3][2] += a.w * b.z; acc[3][3] += a.w * b.w;
        }
        __syncthreads();
    }

    #pragma unroll
    for (int i = 0; i < 4; i++) {
        int m = m0 + ty * 4 + i;
        if (m >= M) continue;
        #pragma unroll
        for (int j = 0; j < 4; j++) {
            int n = n0 + tx * 4 + j;
            atomicAdd(&C[(size_t)m * 256 + n], acc[i][j]);
        }
    }
}

// ---------------------------------------------------------------------------
// Deformable sampling v2 (unchanged)
// ---------------------------------------------------------------------------
__global__ __launch_bounds__(256)
void msda_sample(const float* __restrict__ vproj,
                 const float* __restrict__ refp,
                 const float* __restrict__ off,
                 const float* __restrict__ logits,
                 const int*   __restrict__ shapes,
                 const int*   __restrict__ lstart,
                 float*       __restrict__ samp,
                 int Lq, int Lv)
{
    const int bq  = blockIdx.x;
    const int b   = bq / Lq;
    const int tid = threadIdx.x;

    __shared__ float s_log[128];
    __shared__ float s_off[EMBED];
    __shared__ float s_ref[LEVELS * 2];
    __shared__ int   s_shape[LEVELS * 2];
    __shared__ int   s_start[LEVELS];
    __shared__ int4   s_idx4[128];
    __shared__ float4 s_w4[128];

    if (tid < 128) s_log[tid] = logits[(size_t)bq * 128 + tid];
    s_off[tid] = off[(size_t)bq * EMBED + tid];
    if (tid < LEVELS * 2) {
        s_ref[tid]   = refp[(size_t)bq * (LEVELS * 2) + tid];
        s_shape[tid] = shapes[tid];
    }
    if (tid < LEVELS) s_start[tid] = lstart[tid];
    __syncthreads();

    if (tid < 128) {
        const int h = tid >> 4;
        const int i = tid & 15;
        const int l = i >> 2;

        float mx = -1e30f;
        #pragma unroll
        for (int j = 0; j < 16; j++) mx = fmaxf(mx, s_log[h * 16 + j]);
        float sum = 0.f;
        #pragma unroll
        for (int j = 0; j < 16; j++) sum += __expf(s_log[h * 16 + j] - mx);
        const float aw = __expf(s_log[tid] - mx) / sum;

        const int   Hh = s_shape[l * 2 + 0];
        const int   Ww = s_shape[l * 2 + 1];
        const float Wf = (float)Ww, Hf = (float)Hh;
        const int   st = s_start[l];
        const float rx = s_ref[l * 2 + 0];
        const float ry = s_ref[l * 2 + 1];

        const float x = (rx + s_off[tid * 2 + 0] / Wf) * Wf - 0.5f;
        const float y = (ry + s_off[tid * 2 + 1] / Hf) * Hf - 0.5f;
        const float x0f = floorf(x), y0f = floorf(y);
        const float lx = x - x0f, ly = y - y0f;
        const int   x0 = (int)x0f, y0 = (int)y0f;

        const bool vx0 = (x0 >= 0) & (x0 < Ww);
        const bool vx1 = (x0 + 1 >= 0) & (x0 + 1 < Ww);
        const bool vy0 = (y0 >= 0) & (y0 < Hh);
        const bool vy1 = (y0 + 1 >= 0) & (y0 + 1 < Hh);

        int4 id;
        id.x = (vy0 && vx0) ? st + y0 * Ww + x0           : -1;
        id.y = (vy0 && vx1) ? st + y0 * Ww + x0 + 1       : -1;
        id.z = (vy1 && vx0) ? st + (y0 + 1) * Ww + x0     : -1;
        id.w = (vy1 && vx1) ? st + (y0 + 1) * Ww + x0 + 1 : -1;

        float4 ww;
        ww.x = aw * (1.f - lx) * (1.f - ly);
        ww.y = aw * lx * (1.f - ly);
        ww.z = aw * (1.f - lx) * ly;
        ww.w = aw * lx * ly;

        s_idx4[tid] = id;
        s_w4[tid]   = ww;
    }
    __syncthreads();

    const int h = tid >> 5;
    const int d = tid & 31;
    const float* vb = vproj + (size_t)b * Lv * EMBED + h * HEAD_DIM + d;

    float a0 = 0.f, a1 = 0.f, a2 = 0.f, a3 = 0.f;
    #pragma unroll 4
    for (int i = 0; i < 16; i++) {
        const int t = h * 16 + i;
        const int4   id = s_idx4[t];
        const float4 ww = s_w4[t];
        if (id.x >= 0) a0 += ww.x * __ldg(vb + (size_t)id.x * EMBED);
        if (id.y >= 0) a1 += ww.y * __ldg(vb + (size_t)id.y * EMBED);
        if (id.z >= 0) a2 += ww.z * __ldg(vb + (size_t)id.z * EMBED);
        if (id.w >= 0) a3 += ww.w * __ldg(vb + (size_t)id.w * EMBED);
    }
    samp[(size_t)bq * EMBED + tid] = (a0 + a1) + (a2 + a3);
}

// ---------------------------------------------------------------------------
// kernel_launch
// ---------------------------------------------------------------------------
extern "C" void kernel_launch(void* const* d_in, const int* in_sizes, int n_in,
                              void* d_out, int out_size)
{
    const float* query   = (const float*)d_in[0];
    const float* refp    = (const float*)d_in[1];
    const float* value   = (const float*)d_in[2];
    const int*   shapes  = (const int*)  d_in[3];
    const int*   lstart  = (const int*)  d_in[4];
    const float* w_value = (const float*)d_in[5];
    const float* b_value = (const float*)d_in[6];
    const float* w_off   = (const float*)d_in[7];
    const float* b_off   = (const float*)d_in[8];
    const float* w_attn  = (const float*)d_in[9];
    const float* b_attn  = (const float*)d_in[10];
    const float* w_out   = (const float*)d_in[11];
    const float* b_out   = (const float*)d_in[12];

    const int Mv = in_sizes[2] / EMBED;   // bs * Lv = 53176
    const int Mq = in_sizes[0] / EMBED;   // bs * Lq = 3600
    const int bs = 4;
    const int Lv = Mv / bs;
    const int Lq = Mq / bs;

    float *vproj, *offb, *logitb, *sampb;
    __nv_bfloat16 *abf, *bbf;
    cudaGetSymbolAddress((void**)&vproj,  g_vproj);
    cudaGetSymbolAddress((void**)&offb,   g_off);
    cudaGetSymbolAddress((void**)&logitb, g_logit);
    cudaGetSymbolAddress((void**)&sampb,  g_samp);
    cudaGetSymbolAddress((void**)&abf,    g_abf16);
    cudaGetSymbolAddress((void**)&bbf,    g_bbf16);

    // 1) split-convert value + w_value; also init d_out with bias
    {
        int cvt_total  = (Mv + 256) * 32;
        int init_total = Mq * 64;
        int blocks = (cvt_total + init_total + 255) / 256;
        cvt_split_init<<<blocks, 256>>>(value, w_value, abf, bbf, Mv, cvt_total,
                                        (float*)d_out, b_out, Mq);
    }

    // 2) fat kernel: vproj (tensor) + offsets GEMM + logits GEMM
    const int MB = (Mv + 127) / 128;               // 416
    static bool cfg = false;
    if (!cfg) {
        cudaFuncSetAttribute(fat_gemms,
                             cudaFuncAttributeMaxDynamicSharedMemorySize, 65536);
        cfg = true;
    }
    fat_gemms<<<2 * MB + 228 + 114, 256, 65536>>>(
        abf, bbf, b_value, vproj, Mv, MB,
        query, w_off, b_off, offb, w_attn, b_attn, logitb, Mq);

    // 3) softmax + bilinear deformable sampling
    msda_sample<<<Mq, 256>>>(vproj, refp, offb, logitb, shapes, lstart,
                             sampb, Lq, Lv);

    // 4) output projection -> d_out (split-K, atomic accumulate onto bias)
    outproj_splitk<<<dim3(4, (Mq + 63) / 64, 4), 256>>>(
        sampb, w_out, (float*)d_out, Mq);
}

// round 8
// speedup vs baseline: 2.2811x; 1.0188x over previous
#include <cuda_runtime.h>
#include <cuda_bf16.h>
#include <cstdint>
#include <cstddef>

#define EMBED    256
#define HEADS    8
#define LEVELS   4
#define POINTS   4
#define HEAD_DIM 32

// ---------------------------------------------------------------------------
// Scratch (static __device__ globals; runtime allocation is forbidden)
// ---------------------------------------------------------------------------
__device__ float g_vproj[4 * 13312 * EMBED];            // projected value
__device__ __nv_bfloat16 g_abf16[53248 * 512];          // value split hi|lo
__device__ __nv_bfloat16 g_bbf16[512 * 512];            // w_value | w_out split
__device__ float g_off  [3600 * EMBED];                 // sampling offsets
__device__ float g_logit[3600 * 128];                   // attn logits
__device__ __nv_bfloat16 g_sampbf[3712 * 512];          // sampled out split hi|lo

// ---------------------------------------------------------------------------
// helpers
// ---------------------------------------------------------------------------
__device__ __forceinline__ uint32_t smem_u32(const void* p) {
    uint32_t a;
    asm("{ .reg .u64 t; cvta.to.shared.u64 t, %1; cvt.u32.u64 %0, t; }"
        : "=r"(a) : "l"(p));
    return a;
}

__device__ __forceinline__ void ldsm4(uint32_t* r, uint32_t addr) {
    asm volatile("ldmatrix.sync.aligned.m8n8.x4.shared.b16 {%0,%1,%2,%3}, [%4];"
                 : "=r"(r[0]), "=r"(r[1]), "=r"(r[2]), "=r"(r[3]) : "r"(addr));
}

__device__ __forceinline__ void mma_bf16(float* c, const uint32_t* a,
                                         uint32_t b0, uint32_t b1) {
    asm volatile(
        "mma.sync.aligned.m16n8k16.row.col.f32.bf16.bf16.f32 "
        "{%0,%1,%2,%3}, {%4,%5,%6,%7}, {%8,%9}, {%0,%1,%2,%3};"
        : "+f"(c[0]), "+f"(c[1]), "+f"(c[2]), "+f"(c[3])
        : "r"(a[0]), "r"(a[1]), "r"(a[2]), "r"(a[3]), "r"(b0), "r"(b1));
}

__device__ __forceinline__ void cp_async16(uint32_t saddr, const void* gaddr) {
    asm volatile("cp.async.cg.shared.global [%0], [%1], 16;"
                 :: "r"(saddr), "l"(gaddr) : "memory");
}
#define CP_ASYNC_COMMIT() asm volatile("cp.async.commit_group;" ::: "memory")
#define CP_ASYNC_WAIT(N)  asm volatile("cp.async.wait_group %0;" :: "n"(N) : "memory")

union Pack8 { uint4 u; __nv_bfloat16 b[8]; };
__device__ __forceinline__ void cvt8(const float4& v0, const float4& v1,
                                     uint4& hi, uint4& lo) {
    float f[8] = {v0.x, v0.y, v0.z, v0.w, v1.x, v1.y, v1.z, v1.w};
    Pack8 H, L;
    #pragma unroll
    for (int j = 0; j < 8; j++) {
        __nv_bfloat16 h = __float2bfloat16_rn(f[j]);
        H.b[j] = h;
        L.b[j] = __float2bfloat16_rn(f[j] - __bfloat162float(h));
    }
    hi = H.u; lo = L.u;
}

#define SWZ(o) ((o) ^ (((o) >> 3) & 0x70))

// ---------------------------------------------------------------------------
// Split-convert: value rows [0,Mv) -> Ab; w_value rows [Mv,Mv+256) and
// w_out rows [Mv+256,Mv+512) -> Bb (w_out at row offset 256).
// ---------------------------------------------------------------------------
__global__ __launch_bounds__(256)
void cvt_split(const float* __restrict__ A, const float* __restrict__ Wv,
               const float* __restrict__ Wo,
               __nv_bfloat16* __restrict__ Ab, __nv_bfloat16* __restrict__ Bb,
               int Mv)
{
    int t = blockIdx.x * 256 + threadIdx.x;      // one thread per 8 floats
    int total = (Mv + 512) * 32;
    if (t >= total) return;
    int row = t >> 5;
    int s8  = t & 31;
    int kc  = s8 >> 2;
    int seg = s8 & 3;
    const float* src;
    __nv_bfloat16* dst;
    if (row < Mv) {
        src = A + (size_t)row * 256;
        dst = Ab + (size_t)row * 512;
    } else {
        int r2 = row - Mv;
        src = (r2 < 256) ? Wv + (size_t)r2 * 256 : Wo + (size_t)(r2 - 256) * 256;
        dst = Bb + (size_t)r2 * 512;
    }
    float4 v0 = *(const float4*)(src + kc * 32 + seg * 8);
    float4 v1 = *(const float4*)(src + kc * 32 + seg * 8 + 4);
    uint4 hi, lo;
    cvt8(v0, v1, hi, lo);
    *(uint4*)(dst + kc * 64 + seg * 8)      = hi;
    *(uint4*)(dst + kc * 64 + 32 + seg * 8) = lo;
}

// ---------------------------------------------------------------------------
// bf16x3 MMA GEMM body: C[M,256] tile (m0,n0) from split operands.
// Ab rows stride 512 (chunked hi|lo); Bb same. 256 threads, 64KB dyn smem.
// ---------------------------------------------------------------------------
__device__ __forceinline__ void mma_gemm_body(
    const __nv_bfloat16* __restrict__ Ab, const __nv_bfloat16* __restrict__ Bb,
    const float* __restrict__ bias, float* __restrict__ C,
    int M, int m0, int n0, char* sm)
{
    const int tid  = threadIdx.x;
    const int lane = tid & 31;
    const int w    = tid >> 5;
    const int wm   = (w & 1) * 64;
    const int wn   = (w >> 1) * 32;
    const uint32_t sb = smem_u32(sm);

    float acc[4][4][4] = {};

    auto prefetch = [&](int kc, int buf) {
        const uint32_t abase = sb + buf * 32768;
        const uint32_t bbase = abase + 16384;
        #pragma unroll
        for (int i = 0; i < 4; i++) {
            int idx = tid + i * 256;
            int row = idx >> 3;
            int seg = idx & 7;
            uint32_t so = SWZ((uint32_t)(row * 128 + seg * 16));
            cp_async16(abase + so,
                       Ab + ((size_t)(m0 + row) * 512 + kc * 64 + seg * 8));
            cp_async16(bbase + so,
                       Bb + ((size_t)(n0 + row) * 512 + kc * 64 + seg * 8));
        }
    };

    auto compute = [&](int buf) {
        const uint32_t abase = sb + buf * 32768;
        const uint32_t bbase = abase + 16384;
        const int KP[6][2] = {{0,0},{16,16},{0,32},{16,48},{32,0},{48,16}};
        const int j = lane >> 3, r = lane & 7;
        #pragma unroll
        for (int s = 0; s < 6; s++) {
            const int ka = KP[s][0], kb2 = KP[s][1];
            uint32_t af[4][4], bfr[2][4];
            #pragma unroll
            for (int mt = 0; mt < 4; mt++) {
                uint32_t row  = wm + mt * 16 + (j & 1) * 8 + r;
                uint32_t colb = (ka + (j >> 1) * 8) * 2;
                ldsm4(af[mt], abase + SWZ(row * 128 + colb));
            }
            #pragma unroll
            for (int nt = 0; nt < 2; nt++) {
                uint32_t row  = wn + nt * 16 + (j >> 1) * 8 + r;
                uint32_t colb = (kb2 + (j & 1) * 8) * 2;
                ldsm4(bfr[nt], bbase + SWZ(row * 128 + colb));
            }
            #pragma unroll
            for (int mt = 0; mt < 4; mt++)
                #pragma unroll
                for (int ns = 0; ns < 4; ns++)
                    mma_bf16(acc[mt][ns], af[mt],
                             bfr[ns >> 1][(ns & 1) * 2],
                             bfr[ns >> 1][(ns & 1) * 2 + 1]);
        }
    };

    prefetch(0, 0);
    CP_ASYNC_COMMIT();
    #pragma unroll 1
    for (int kc = 0; kc < 8; kc++) {
        int buf = kc & 1;
        if (kc + 1 < 8) {
            prefetch(kc + 1, buf ^ 1);
            CP_ASYNC_COMMIT();
            CP_ASYNC_WAIT(1);
        } else {
            CP_ASYNC_WAIT(0);
        }
        __syncthreads();
        compute(buf);
        __syncthreads();
    }

    const int g = lane >> 2, tig = lane & 3;
    #pragma unroll
    for (int mt = 0; mt < 4; mt++) {
        int mr = m0 + wm + mt * 16 + g;
        #pragma unroll
        for (int ns = 0; ns < 4; ns++) {
            int col = n0 + wn + ns * 8 + tig * 2;
            float bxv = bias[col], byv = bias[col + 1];
            if (mr < M) {
                float2 o = {acc[mt][ns][0] + bxv, acc[mt][ns][1] + byv};
                *(float2*)&C[(size_t)mr * 256 + col] = o;
            }
            if (mr + 8 < M) {
                float2 o = {acc[mt][ns][2] + bxv, acc[mt][ns][3] + byv};
                *(float2*)&C[(size_t)(mr + 8) * 256 + col] = o;
            }
        }
    }
}

// ---------------------------------------------------------------------------
// SIMT small-GEMM body (64x64 tile) on caller smem: C = A[M,256]*B[N,256]^T+bias
// ---------------------------------------------------------------------------
__device__ void gemm_small_body(const float* __restrict__ A,
                                const float* __restrict__ B,
                                const float* __restrict__ bias,
                                float* __restrict__ C,
                                int M, int N, int m0, int n0, char* smraw)
{
    float (*As)[68] = (float (*)[68])smraw;
    float (*Bs)[68] = (float (*)[68])(smraw + 32 * 68 * 4);

    const int tid = threadIdx.x;
    const int tx  = tid & 15;
    const int ty  = tid >> 4;

    float acc[4][4] = {};

    for (int k0 = 0; k0 < 256; k0 += 32) {
        #pragma unroll
        for (int i = 0; i < 2; i++) {
            int idx = tid + i * 256;
            int r   = idx >> 3;
            int c4  = idx & 7;
            int m   = m0 + r;
            float4 av = (m < M) ? *(const float4*)&A[(size_t)m * 256 + k0 + c4 * 4]
                                : make_float4(0.f, 0.f, 0.f, 0.f);
            As[c4 * 4 + 0][r] = av.x;
            As[c4 * 4 + 1][r] = av.y;
            As[c4 * 4 + 2][r] = av.z;
            As[c4 * 4 + 3][r] = av.w;
            int n   = n0 + r;
            float4 bv = (n < N) ? *(const float4*)&B[(size_t)n * 256 + k0 + c4 * 4]
                                : make_float4(0.f, 0.f, 0.f, 0.f);
            Bs[c4 * 4 + 0][r] = bv.x;
            Bs[c4 * 4 + 1][r] = bv.y;
            Bs[c4 * 4 + 2][r] = bv.z;
            Bs[c4 * 4 + 3][r] = bv.w;
        }
        __syncthreads();

        #pragma unroll
        for (int kk = 0; kk < 32; kk++) {
            float4 a = *(const float4*)&As[kk][ty * 4];
            float4 b = *(const float4*)&Bs[kk][tx * 4];
            acc[0][0] += a.x * b.x; acc[0][1] += a.x * b.y;
            acc[0][2] += a.x * b.z; acc[0][3] += a.x * b.w;
            acc[1][0] += a.y * b.x; acc[1][1] += a.y * b.y;
            acc[1][2] += a.y * b.z; acc[1][3] += a.y * b.w;
            acc[2][0] += a.z * b.x; acc[2][1] += a.z * b.y;
            acc[2][2] += a.z * b.z; acc[2][3] += a.z * b.w;
            acc[3][0] += a.w * b.x; acc[3][1] += a.w * b.y;
            acc[3][2] += a.w * b.z; acc[3][3] += a.w * b.w;
        }
        __syncthreads();
    }

    #pragma unroll
    for (int i = 0; i < 4; i++) {
        int m = m0 + ty * 4 + i;
        if (m >= M) continue;
        #pragma unroll
        for (int j = 0; j < 4; j++) {
            int n = n0 + tx * 4 + j;
            if (n < N) C[(size_t)m * N + n] = acc[i][j] + bias[n];
        }
    }
}

// ---------------------------------------------------------------------------
// Fat kernel (2 CTAs/SM):
//   blocks [0, 2*MB)    : vproj bf16x3 mma.sync
//   blocks [2*MB, +228) : offsets GEMM [Mq,256]
//   blocks [.., +114)   : logits GEMM  [Mq,128]
// ---------------------------------------------------------------------------
__global__ __launch_bounds__(256, 2)
void fat_gemms(const __nv_bfloat16* __restrict__ Ab,
               const __nv_bfloat16* __restrict__ Bb,
               const float* __restrict__ b_value,
               float* __restrict__ Cv, int Mv, int MB,
               const float* __restrict__ query,
               const float* __restrict__ w_off, const float* __restrict__ b_off,
               float* __restrict__ offb,
               const float* __restrict__ w_attn, const float* __restrict__ b_attn,
               float* __restrict__ logitb, int Mq)
{
    extern __shared__ char sm[];
    const int bx = blockIdx.x;

    if (bx >= 2 * MB) {
        int ix = bx - 2 * MB;
        if (ix < 228) {
            gemm_small_body(query, w_off, b_off, offb, Mq, 256,
                            (ix >> 2) * 64, (ix & 3) * 64, sm);
        } else {
            ix -= 228;
            gemm_small_body(query, w_attn, b_attn, logitb, Mq, 128,
                            (ix >> 1) * 64, (ix & 1) * 64, sm);
        }
        return;
    }

    mma_gemm_body(Ab, Bb, b_value, Cv, Mv, (bx >> 1) * 128, (bx & 1) * 128, sm);
}

// ---------------------------------------------------------------------------
// Output projection: d_out[Mq,256] = samp_bf16 @ w_out^T + b_out (bf16x3 MMA)
// ---------------------------------------------------------------------------
__global__ __launch_bounds__(256, 2)
void outproj_mma(const __nv_bfloat16* __restrict__ Sb,
                 const __nv_bfloat16* __restrict__ Bb,   // w_out split at +256 rows
                 const float* __restrict__ b_out,
                 float* __restrict__ C, int Mq)
{
    extern __shared__ char sm[];
    mma_gemm_body(Sb, Bb + 256 * 512, b_out, C, Mq,
                  blockIdx.y * 128, blockIdx.x * 128, sm);
}

// ---------------------------------------------------------------------------
// Deformable sampling: phase-1 dedup + gather; epilogue writes bf16 hi|lo split
// ---------------------------------------------------------------------------
__global__ __launch_bounds__(256)
void msda_sample(const float* __restrict__ vproj,
                 const float* __restrict__ refp,
                 const float* __restrict__ off,
                 const float* __restrict__ logits,
                 const int*   __restrict__ shapes,
                 const int*   __restrict__ lstart,
                 __nv_bfloat16* __restrict__ sampb,   // [3712, 512] chunked hi|lo
                 int Lq, int Lv)
{
    const int bq  = blockIdx.x;
    const int b   = bq / Lq;
    const int tid = threadIdx.x;

    __shared__ float s_log[128];
    __shared__ float s_off[EMBED];
    __shared__ float s_ref[LEVELS * 2];
    __shared__ int   s_shape[LEVELS * 2];
    __shared__ int   s_start[LEVELS];
    __shared__ int4   s_idx4[128];
    __shared__ float4 s_w4[128];

    if (tid < 128) s_log[tid] = logits[(size_t)bq * 128 + tid];
    s_off[tid] = off[(size_t)bq * EMBED + tid];
    if (tid < LEVELS * 2) {
        s_ref[tid]   = refp[(size_t)bq * (LEVELS * 2) + tid];
        s_shape[tid] = shapes[tid];
    }
    if (tid < LEVELS) s_start[tid] = lstart[tid];
    __syncthreads();

    if (tid < 128) {
        const int h = tid >> 4;
        const int i = tid & 15;
        const int l = i >> 2;

        float mx = -1e30f;
        #pragma unroll
        for (int j = 0; j < 16; j++) mx = fmaxf(mx, s_log[h * 16 + j]);
        float sum = 0.f;
        #pragma unroll
        for (int j = 0; j < 16; j++) sum += __expf(s_log[h * 16 + j] - mx);
        const float aw = __expf(s_log[tid] - mx) / sum;

        const int   Hh = s_shape[l * 2 + 0];
        const int   Ww = s_shape[l * 2 + 1];
        const float Wf = (float)Ww, Hf = (float)Hh;
        const int   st = s_start[l];
        const float rx = s_ref[l * 2 + 0];
        const float ry = s_ref[l * 2 + 1];

        const float x = (rx + s_off[tid * 2 + 0] / Wf) * Wf - 0.5f;
        const float y = (ry + s_off[tid * 2 + 1] / Hf) * Hf - 0.5f;
        const float x0f = floorf(x), y0f = floorf(y);
        const float lx = x - x0f, ly = y - y0f;
        const int   x0 = (int)x0f, y0 = (int)y0f;

        const bool vx0 = (x0 >= 0) & (x0 < Ww);
        const bool vx1 = (x0 + 1 >= 0) & (x0 + 1 < Ww);
        const bool vy0 = (y0 >= 0) & (y0 < Hh);
        const bool vy1 = (y0 + 1 >= 0) & (y0 + 1 < Hh);

        int4 id;
        id.x = (vy0 && vx0) ? st + y0 * Ww + x0           : -1;
        id.y = (vy0 && vx1) ? st + y0 * Ww + x0 + 1       : -1;
        id.z = (vy1 && vx0) ? st + (y0 + 1) * Ww + x0     : -1;
        id.w = (vy1 && vx1) ? st + (y0 + 1) * Ww + x0 + 1 : -1;

        float4 ww;
        ww.x = aw * (1.f - lx) * (1.f - ly);
        ww.y = aw * lx * (1.f - ly);
        ww.z = aw * (1.f - lx) * ly;
        ww.w = aw * lx * ly;

        s_idx4[tid] = id;
        s_w4[tid]   = ww;
    }
    __syncthreads();

    const int h = tid >> 5;
    const int d = tid & 31;
    const float* vb = vproj + (size_t)b * Lv * EMBED + h * HEAD_DIM + d;

    float a0 = 0.f, a1 = 0.f, a2 = 0.f, a3 = 0.f;
    #pragma unroll 4
    for (int i = 0; i < 16; i++) {
        const int t = h * 16 + i;
        const int4   id = s_idx4[t];
        const float4 ww = s_w4[t];
        if (id.x >= 0) a0 += ww.x * __ldg(vb + (size_t)id.x * EMBED);
        if (id.y >= 0) a1 += ww.y * __ldg(vb + (size_t)id.y * EMBED);
        if (id.z >= 0) a2 += ww.z * __ldg(vb + (size_t)id.z * EMBED);
        if (id.w >= 0) a3 += ww.w * __ldg(vb + (size_t)id.w * EMBED);
    }
    const float r = (a0 + a1) + (a2 + a3);
    // write split bf16 hi|lo in the chunked layout (row stride 512)
    __nv_bfloat16 hv = __float2bfloat16_rn(r);
    __nv_bfloat16 lv = __float2bfloat16_rn(r - __bfloat162float(hv));
    const int kc = tid >> 5;      // 32-col chunk
    const int cc = tid & 31;
    __nv_bfloat16* dst = sampb + (size_t)bq * 512 + kc * 64 + cc;
    dst[0]  = hv;
    dst[32] = lv;
}

// ---------------------------------------------------------------------------
// kernel_launch
// ---------------------------------------------------------------------------
extern "C" void kernel_launch(void* const* d_in, const int* in_sizes, int n_in,
                              void* d_out, int out_size)
{
    const float* query   = (const float*)d_in[0];
    const float* refp    = (const float*)d_in[1];
    const float* value   = (const float*)d_in[2];
    const int*   shapes  = (const int*)  d_in[3];
    const int*   lstart  = (const int*)  d_in[4];
    const float* w_value = (const float*)d_in[5];
    const float* b_value = (const float*)d_in[6];
    const float* w_off   = (const float*)d_in[7];
    const float* b_off   = (const float*)d_in[8];
    const float* w_attn  = (const float*)d_in[9];
    const float* b_attn  = (const float*)d_in[10];
    const float* w_out   = (const float*)d_in[11];
    const float* b_out   = (const float*)d_in[12];

    const int Mv = in_sizes[2] / EMBED;   // bs * Lv = 53176
    const int Mq = in_sizes[0] / EMBED;   // bs * Lq = 3600
    const int bs = 4;
    const int Lv = Mv / bs;
    const int Lq = Mq / bs;

    float *vproj, *offb, *logitb;
    __nv_bfloat16 *abf, *bbf, *sbf;
    cudaGetSymbolAddress((void**)&vproj,  g_vproj);
    cudaGetSymbolAddress((void**)&offb,   g_off);
    cudaGetSymbolAddress((void**)&logitb, g_logit);
    cudaGetSymbolAddress((void**)&abf,    g_abf16);
    cudaGetSymbolAddress((void**)&bbf,    g_bbf16);
    cudaGetSymbolAddress((void**)&sbf,    g_sampbf);

    // 1) split-convert value + w_value + w_out
    {
        int total = (Mv + 512) * 32;
        cvt_split<<<(total + 255) / 256, 256>>>(value, w_value, w_out,
                                                abf, bbf, Mv);
    }

    // 2) fat kernel: vproj (tensor) + offsets GEMM + logits GEMM
    const int MB = (Mv + 127) / 128;               // 416
    static bool cfg = false;
    if (!cfg) {
        cudaFuncSetAttribute(fat_gemms,
                             cudaFuncAttributeMaxDynamicSharedMemorySize, 65536);
        cudaFuncSetAttribute(outproj_mma,
                             cudaFuncAttributeMaxDynamicSharedMemorySize, 65536);
        cfg = true;
    }
    fat_gemms<<<2 * MB + 228 + 114, 256, 65536>>>(
        abf, bbf, b_value, vproj, Mv, MB,
        query, w_off, b_off, offb, w_attn, b_attn, logitb, Mq);

    // 3) softmax + bilinear deformable sampling -> bf16 split
    msda_sample<<<Mq, 256>>>(vproj, refp, offb, logitb, shapes, lstart,
                             sbf, Lq, Lv);

    // 4) output projection (bf16x3 MMA) -> d_out
    outproj_mma<<<dim3(2, (Mq + 127) / 128), 256, 65536>>>(
        sbf, bbf, b_out, (float*)d_out, Mq);
}

// round 9
// speedup vs baseline: 2.7948x; 1.2252x over previous
#include <cuda_runtime.h>
#include <cuda_fp16.h>
#include <cstdint>
#include <cstddef>

#define EMBED    256
#define HEADS    8
#define LEVELS   4
#define POINTS   4
#define HEAD_DIM 32

// ---------------------------------------------------------------------------
// Scratch (static __device__ globals; runtime allocation is forbidden)
// ---------------------------------------------------------------------------
__device__ float  g_vproj[4 * 13312 * EMBED];   // projected value (fp32)
__device__ __half g_af16[53248 * 512];          // value: fp16 hi|lo chunked
__device__ __half g_wf16[512 * 256];            // w_value rows 0-255, w_out 256-511 (plain fp16)
__device__ float  g_off  [3600 * EMBED];        // sampling offsets
__device__ float  g_logit[3600 * 128];          // attn logits
__device__ __half g_sampf16[3712 * 512];        // sampled out: fp16 hi|lo chunked

// ---------------------------------------------------------------------------
// helpers
// ---------------------------------------------------------------------------
__device__ __forceinline__ uint32_t smem_u32(const void* p) {
    uint32_t a;
    asm("{ .reg .u64 t; cvta.to.shared.u64 t, %1; cvt.u32.u64 %0, t; }"
        : "=r"(a) : "l"(p));
    return a;
}

__device__ __forceinline__ void ldsm4(uint32_t* r, uint32_t addr) {
    asm volatile("ldmatrix.sync.aligned.m8n8.x4.shared.b16 {%0,%1,%2,%3}, [%4];"
                 : "=r"(r[0]), "=r"(r[1]), "=r"(r[2]), "=r"(r[3]) : "r"(addr));
}

__device__ __forceinline__ void mma_f16(float* c, const uint32_t* a,
                                        uint32_t b0, uint32_t b1) {
    asm volatile(
        "mma.sync.aligned.m16n8k16.row.col.f32.f16.f16.f32 "
        "{%0,%1,%2,%3}, {%4,%5,%6,%7}, {%8,%9}, {%0,%1,%2,%3};"
        : "+f"(c[0]), "+f"(c[1]), "+f"(c[2]), "+f"(c[3])
        : "r"(a[0]), "r"(a[1]), "r"(a[2]), "r"(a[3]), "r"(b0), "r"(b1));
}

__device__ __forceinline__ void cp_async16(uint32_t saddr, const void* gaddr) {
    asm volatile("cp.async.cg.shared.global [%0], [%1], 16;"
                 :: "r"(saddr), "l"(gaddr) : "memory");
}
#define CP_ASYNC_COMMIT() asm volatile("cp.async.commit_group;" ::: "memory")
#define CP_ASYNC_WAIT(N)  asm volatile("cp.async.wait_group %0;" :: "n"(N) : "memory")

union Pack8h { uint4 u; __half b[8]; };

#define SWZ(o) ((o) ^ (((o) >> 3) & 0x70))

// ---------------------------------------------------------------------------
// Convert: value -> fp16 hi|lo chunked (row 512 halves, chunk c = [c*64, c*64+32) hi,
// +32 lo); weights (w_value then w_out) -> plain fp16 rows of 256.
// ---------------------------------------------------------------------------
__global__ __launch_bounds__(256)
void cvt_split(const float* __restrict__ A, const float* __restrict__ Wv,
               const float* __restrict__ Wo,
               __half* __restrict__ Af, __half* __restrict__ Wf, int Mv)
{
    int t = blockIdx.x * 256 + threadIdx.x;      // one thread per 8 floats
    int total = (Mv + 512) * 32;
    if (t >= total) return;
    int row = t >> 5;
    int s8  = t & 31;
    if (row < Mv) {
        int kc  = s8 >> 2;
        int seg = s8 & 3;
        const float* src = A + (size_t)row * 256 + kc * 32 + seg * 8;
        float f[8];
        #pragma unroll
        for (int j = 0; j < 8; j++) f[j] = src[j];
        Pack8h H, L;
        #pragma unroll
        for (int j = 0; j < 8; j++) {
            __half h = __float2half_rn(f[j]);
            H.b[j] = h;
            L.b[j] = __float2half_rn(f[j] - __half2float(h));
        }
        __half* dst = Af + (size_t)row * 512 + kc * 64 + seg * 8;
        *(uint4*)(dst)      = H.u;
        *(uint4*)(dst + 32) = L.u;
    } else {
        int r2 = row - Mv;                        // 0..511
        const float* src = (r2 < 256) ? Wv + (size_t)r2 * 256 + s8 * 8
                                      : Wo + (size_t)(r2 - 256) * 256 + s8 * 8;
        Pack8h H;
        #pragma unroll
        for (int j = 0; j < 8; j++) H.b[j] = __float2half_rn(src[j]);
        *(uint4*)(Wf + (size_t)r2 * 256 + s8 * 8) = H.u;
    }
}

// ---------------------------------------------------------------------------
// fp16 2-term MMA GEMM body: C[M,256] tile (m0,n0).
// A: chunked hi|lo rows of 512 halves. B: plain fp16 rows of 256.
// Pipeline stage = 64 k-floats. smem/stage: A 32KB (2 tiles) + B 16KB = 48KB;
// double-buffered = 96KB dynamic smem.
// ---------------------------------------------------------------------------
__device__ __forceinline__ void mma_gemm_body(
    const __half* __restrict__ Af, const __half* __restrict__ Wf,
    const float* __restrict__ bias, float* __restrict__ C,
    int M, int m0, int n0, char* sm)
{
    const int tid  = threadIdx.x;
    const int lane = tid & 31;
    const int w    = tid >> 5;
    const int wm   = (w & 1) * 64;
    const int wn   = (w >> 1) * 32;
    const uint32_t sb = smem_u32(sm);

    float acc[4][4][4] = {};

    auto prefetch = [&](int p, int buf) {
        const uint32_t base = sb + buf * 49152;
        #pragma unroll
        for (int i = 0; i < 12; i++) {
            int idx = tid + i * 256;             // 0..3071
            if (idx < 2048) {                    // A: two 16KB tiles
                int tc  = idx >> 10;             // chunk within pair
                int r   = (idx >> 3) & 127;
                int seg = idx & 7;
                cp_async16(base + tc * 16384 + SWZ((uint32_t)(r * 128 + seg * 16)),
                           Af + ((size_t)(m0 + r) * 512 + (p * 2 + tc) * 64 + seg * 8));
            } else {                             // B: 16KB (chunk pair packed)
                int i2  = idx - 2048;
                int r   = i2 >> 3;
                int seg = i2 & 7;
                cp_async16(base + 32768 + SWZ((uint32_t)(r * 128 + seg * 16)),
                           Wf + ((size_t)(n0 + r) * 256 + p * 64 + seg * 8));
            }
        }
    };

    auto compute = [&](int buf) {
        const uint32_t base  = sb + buf * 49152;
        const uint32_t bbase = base + 32768;
        const int j = lane >> 3, r = lane & 7;
        #pragma unroll
        for (int c = 0; c < 2; c++) {
            const uint32_t abase = base + c * 16384;
            #pragma unroll
            for (int g = 0; g < 2; g++) {
                uint32_t bfr[2][4];
                #pragma unroll
                for (int nt = 0; nt < 2; nt++) {
                    uint32_t row  = wn + nt * 16 + (j >> 1) * 8 + r;
                    uint32_t colb = (c * 32 + g * 16 + (j & 1) * 8) * 2;
                    ldsm4(bfr[nt], bbase + SWZ(row * 128 + colb));
                }
                #pragma unroll
                for (int t = 0; t < 2; t++) {
                    uint32_t af[4][4];
                    #pragma unroll
                    for (int mt = 0; mt < 4; mt++) {
                        uint32_t row  = wm + mt * 16 + (j & 1) * 8 + r;
                        uint32_t colb = (t * 32 + g * 16 + (j >> 1) * 8) * 2;
                        ldsm4(af[mt], abase + SWZ(row * 128 + colb));
                    }
                    #pragma unroll
                    for (int mt = 0; mt < 4; mt++)
                        #pragma unroll
                        for (int ns = 0; ns < 4; ns++)
                            mma_f16(acc[mt][ns], af[mt],
                                    bfr[ns >> 1][(ns & 1) * 2],
                                    bfr[ns >> 1][(ns & 1) * 2 + 1]);
                }
            }
        }
    };

    prefetch(0, 0);
    CP_ASYNC_COMMIT();
    #pragma unroll 1
    for (int p = 0; p < 4; p++) {
        int buf = p & 1;
        if (p + 1 < 4) {
            prefetch(p + 1, buf ^ 1);
            CP_ASYNC_COMMIT();
            CP_ASYNC_WAIT(1);
        } else {
            CP_ASYNC_WAIT(0);
        }
        __syncthreads();
        compute(buf);
        __syncthreads();
    }

    const int g = lane >> 2, tig = lane & 3;
    #pragma unroll
    for (int mt = 0; mt < 4; mt++) {
        int mr = m0 + wm + mt * 16 + g;
        #pragma unroll
        for (int ns = 0; ns < 4; ns++) {
            int col = n0 + wn + ns * 8 + tig * 2;
            float bxv = bias[col], byv = bias[col + 1];
            if (mr < M) {
                float2 o = {acc[mt][ns][0] + bxv, acc[mt][ns][1] + byv};
                *(float2*)&C[(size_t)mr * 256 + col] = o;
            }
            if (mr + 8 < M) {
                float2 o = {acc[mt][ns][2] + bxv, acc[mt][ns][3] + byv};
                *(float2*)&C[(size_t)(mr + 8) * 256 + col] = o;
            }
        }
    }
}

// ---------------------------------------------------------------------------
// SIMT small-GEMM body (64x64 tile) on caller smem: C = A[M,256]*B[N,256]^T+bias
// ---------------------------------------------------------------------------
__device__ void gemm_small_body(const float* __restrict__ A,
                                const float* __restrict__ B,
                                const float* __restrict__ bias,
                                float* __restrict__ C,
                                int M, int N, int m0, int n0, char* smraw)
{
    float (*As)[68] = (float (*)[68])smraw;
    float (*Bs)[68] = (float (*)[68])(smraw + 32 * 68 * 4);

    const int tid = threadIdx.x;
    const int tx  = tid & 15;
    const int ty  = tid >> 4;

    float acc[4][4] = {};

    for (int k0 = 0; k0 < 256; k0 += 32) {
        #pragma unroll
        for (int i = 0; i < 2; i++) {
            int idx = tid + i * 256;
            int r   = idx >> 3;
            int c4  = idx & 7;
            int m   = m0 + r;
            float4 av = (m < M) ? *(const float4*)&A[(size_t)m * 256 + k0 + c4 * 4]
                                : make_float4(0.f, 0.f, 0.f, 0.f);
            As[c4 * 4 + 0][r] = av.x;
            As[c4 * 4 + 1][r] = av.y;
            As[c4 * 4 + 2][r] = av.z;
            As[c4 * 4 + 3][r] = av.w;
            int n   = n0 + r;
            float4 bv = (n < N) ? *(const float4*)&B[(size_t)n * 256 + k0 + c4 * 4]
                                : make_float4(0.f, 0.f, 0.f, 0.f);
            Bs[c4 * 4 + 0][r] = bv.x;
            Bs[c4 * 4 + 1][r] = bv.y;
            Bs[c4 * 4 + 2][r] = bv.z;
            Bs[c4 * 4 + 3][r] = bv.w;
        }
        __syncthreads();

        #pragma unroll
        for (int kk = 0; kk < 32; kk++) {
            float4 a = *(const float4*)&As[kk][ty * 4];
            float4 b = *(const float4*)&Bs[kk][tx * 4];
            acc[0][0] += a.x * b.x; acc[0][1] += a.x * b.y;
            acc[0][2] += a.x * b.z; acc[0][3] += a.x * b.w;
            acc[1][0] += a.y * b.x; acc[1][1] += a.y * b.y;
            acc[1][2] += a.y * b.z; acc[1][3] += a.y * b.w;
            acc[2][0] += a.z * b.x; acc[2][1] += a.z * b.y;
            acc[2][2] += a.z * b.z; acc[2][3] += a.z * b.w;
            acc[3][0] += a.w * b.x; acc[3][1] += a.w * b.y;
            acc[3][2] += a.w * b.z; acc[3][3] += a.w * b.w;
        }
        __syncthreads();
    }

    #pragma unroll
    for (int i = 0; i < 4; i++) {
        int m = m0 + ty * 4 + i;
        if (m >= M) continue;
        #pragma unroll
        for (int j = 0; j < 4; j++) {
            int n = n0 + tx * 4 + j;
            if (n < N) C[(size_t)m * N + n] = acc[i][j] + bias[n];
        }
    }
}

// ---------------------------------------------------------------------------
// Fat kernel (2 CTAs/SM). Small SIMT GEMMs dispatch FIRST so they start early
// and finish inside the vproj shadow.
//   blocks [0,228)        : offsets GEMM [Mq,256]
//   blocks [228,342)      : logits  GEMM [Mq,128]
//   blocks [342, 342+2MB) : vproj fp16x2 mma.sync
// ---------------------------------------------------------------------------
__global__ __launch_bounds__(256, 2)
void fat_gemms(const __half* __restrict__ Af, const __half* __restrict__ Wf,
               const float* __restrict__ b_value,
               float* __restrict__ Cv, int Mv, int MB,
               const float* __restrict__ query,
               const float* __restrict__ w_off, const float* __restrict__ b_off,
               float* __restrict__ offb,
               const float* __restrict__ w_attn, const float* __restrict__ b_attn,
               float* __restrict__ logitb, int Mq)
{
    extern __shared__ char sm[];
    const int bx = blockIdx.x;

    if (bx < 228) {
        gemm_small_body(query, w_off, b_off, offb, Mq, 256,
                        (bx >> 2) * 64, (bx & 3) * 64, sm);
        return;
    }
    if (bx < 342) {
        int ix = bx - 228;
        gemm_small_body(query, w_attn, b_attn, logitb, Mq, 128,
                        (ix >> 1) * 64, (ix & 1) * 64, sm);
        return;
    }
    int vb = bx - 342;
    mma_gemm_body(Af, Wf, b_value, Cv, Mv, (vb >> 1) * 128, (vb & 1) * 128, sm);
}

// ---------------------------------------------------------------------------
// Output projection: d_out = samp_f16 @ w_out^T + b_out (fp16x2 MMA)
// ---------------------------------------------------------------------------
__global__ __launch_bounds__(256, 2)
void outproj_mma(const __half* __restrict__ Sf, const __half* __restrict__ Wf,
                 const float* __restrict__ b_out, float* __restrict__ C, int Mq)
{
    extern __shared__ char sm[];
    mma_gemm_body(Sf, Wf + 256 * 256, b_out, C, Mq,
                  blockIdx.y * 128, blockIdx.x * 128, sm);
}

// ---------------------------------------------------------------------------
// Deformable sampling (dedup phase-1); epilogue writes fp16 hi|lo split
// ---------------------------------------------------------------------------
__global__ __launch_bounds__(256)
void msda_sample(const float* __restrict__ vproj,
                 const float* __restrict__ refp,
                 const float* __restrict__ off,
                 const float* __restrict__ logits,
                 const int*   __restrict__ shapes,
                 const int*   __restrict__ lstart,
                 __half* __restrict__ sampf,     // [3712, 512] chunked hi|lo
                 int Lq, int Lv)
{
    const int bq  = blockIdx.x;
    const int b   = bq / Lq;
    const int tid = threadIdx.x;

    __shared__ float s_log[128];
    __shared__ float s_off[EMBED];
    __shared__ float s_ref[LEVELS * 2];
    __shared__ int   s_shape[LEVELS * 2];
    __shared__ int   s_start[LEVELS];
    __shared__ int4   s_idx4[128];
    __shared__ float4 s_w4[128];

    if (tid < 128) s_log[tid] = logits[(size_t)bq * 128 + tid];
    s_off[tid] = off[(size_t)bq * EMBED + tid];
    if (tid < LEVELS * 2) {
        s_ref[tid]   = refp[(size_t)bq * (LEVELS * 2) + tid];
        s_shape[tid] = shapes[tid];
    }
    if (tid < LEVELS) s_start[tid] = lstart[tid];
    __syncthreads();

    if (tid < 128) {
        const int h = tid >> 4;
        const int i = tid & 15;
        const int l = i >> 2;

        float mx = -1e30f;
        #pragma unroll
        for (int j = 0; j < 16; j++) mx = fmaxf(mx, s_log[h * 16 + j]);
        float sum = 0.f;
        #pragma unroll
        for (int j = 0; j < 16; j++) sum += __expf(s_log[h * 16 + j] - mx);
        const float aw = __expf(s_log[tid] - mx) / sum;

        const int   Hh = s_shape[l * 2 + 0];
        const int   Ww = s_shape[l * 2 + 1];
        const float Wfl = (float)Ww, Hfl = (float)Hh;
        const int   st = s_start[l];
        const float rx = s_ref[l * 2 + 0];
        const float ry = s_ref[l * 2 + 1];

        const float x = (rx + s_off[tid * 2 + 0] / Wfl) * Wfl - 0.5f;
        const float y = (ry + s_off[tid * 2 + 1] / Hfl) * Hfl - 0.5f;
        const float x0f = floorf(x), y0f = floorf(y);
        const float lx = x - x0f, ly = y - y0f;
        const int   x0 = (int)x0f, y0 = (int)y0f;

        const bool vx0 = (x0 >= 0) & (x0 < Ww);
        const bool vx1 = (x0 + 1 >= 0) & (x0 + 1 < Ww);
        const bool vy0 = (y0 >= 0) & (y0 < Hh);
        const bool vy1 = (y0 + 1 >= 0) & (y0 + 1 < Hh);

        int4 id;
        id.x = (vy0 && vx0) ? st + y0 * Ww + x0           : -1;
        id.y = (vy0 && vx1) ? st + y0 * Ww + x0 + 1       : -1;
        id.z = (vy1 && vx0) ? st + (y0 + 1) * Ww + x0     : -1;
        id.w = (vy1 && vx1) ? st + (y0 + 1) * Ww + x0 + 1 : -1;

        float4 ww;
        ww.x = aw * (1.f - lx) * (1.f - ly);
        ww.y = aw * lx * (1.f - ly);
        ww.z = aw * (1.f - lx) * ly;
        ww.w = aw * lx * ly;

        s_idx4[tid] = id;
        s_w4[tid]   = ww;
    }
    __syncthreads();

    const int h = tid >> 5;
    const int d = tid & 31;
    const float* vb = vproj + (size_t)b * Lv * EMBED + h * HEAD_DIM + d;

    float a0 = 0.f, a1 = 0.f, a2 = 0.f, a3 = 0.f;
    #pragma unroll 4
    for (int i = 0; i < 16; i++) {
        const int t = h * 16 + i;
        const int4   id = s_idx4[t];
        const float4 ww = s_w4[t];
        if (id.x >= 0) a0 += ww.x * __ldg(vb + (size_t)id.x * EMBED);
        if (id.y >= 0) a1 += ww.y * __ldg(vb + (size_t)id.y * EMBED);
        if (id.z >= 0) a2 += ww.z * __ldg(vb + (size_t)id.z * EMBED);
        if (id.w >= 0) a3 += ww.w * __ldg(vb + (size_t)id.w * EMBED);
    }
    const float r = (a0 + a1) + (a2 + a3);
    __half hv = __float2half_rn(r);
    __half lv = __float2half_rn(r - __half2float(hv));
    const int kc = tid >> 5;
    const int cc = tid & 31;
    __half* dst = sampf + (size_t)bq * 512 + kc * 64 + cc;
    dst[0]  = hv;
    dst[32] = lv;
}

// ---------------------------------------------------------------------------
// kernel_launch
// ---------------------------------------------------------------------------
extern "C" void kernel_launch(void* const* d_in, const int* in_sizes, int n_in,
                              void* d_out, int out_size)
{
    const float* query   = (const float*)d_in[0];
    const float* refp    = (const float*)d_in[1];
    const float* value   = (const float*)d_in[2];
    const int*   shapes  = (const int*)  d_in[3];
    const int*   lstart  = (const int*)  d_in[4];
    const float* w_value = (const float*)d_in[5];
    const float* b_value = (const float*)d_in[6];
    const float* w_off   = (const float*)d_in[7];
    const float* b_off   = (const float*)d_in[8];
    const float* w_attn  = (const float*)d_in[9];
    const float* b_attn  = (const float*)d_in[10];
    const float* w_out   = (const float*)d_in[11];
    const float* b_out   = (const float*)d_in[12];

    const int Mv = in_sizes[2] / EMBED;   // bs * Lv = 53176
    const int Mq = in_sizes[0] / EMBED;   // bs * Lq = 3600
    const int bs = 4;
    const int Lv = Mv / bs;
    const int Lq = Mq / bs;

    float *vproj, *offb, *logitb;
    __half *af, *wf, *sf;
    cudaGetSymbolAddress((void**)&vproj,  g_vproj);
    cudaGetSymbolAddress((void**)&offb,   g_off);
    cudaGetSymbolAddress((void**)&logitb, g_logit);
    cudaGetSymbolAddress((void**)&af,     g_af16);
    cudaGetSymbolAddress((void**)&wf,     g_wf16);
    cudaGetSymbolAddress((void**)&sf,     g_sampf16);

    // 1) fp16 conversion: value split hi|lo; weights single fp16
    {
        int total = (Mv + 512) * 32;
        cvt_split<<<(total + 255) / 256, 256>>>(value, w_value, w_out, af, wf, Mv);
    }

    // 2) fat kernel: small GEMMs first, then vproj (fp16x2 tensor)
    const int MB = (Mv + 127) / 128;               // 416
    static bool cfg = false;
    if (!cfg) {
        cudaFuncSetAttribute(fat_gemms,
                             cudaFuncAttributeMaxDynamicSharedMemorySize, 98304);
        cudaFuncSetAttribute(outproj_mma,
                             cudaFuncAttributeMaxDynamicSharedMemorySize, 98304);
        cfg = true;
    }
    fat_gemms<<<342 + 2 * MB, 256, 98304>>>(
        af, wf, b_value, vproj, Mv, MB,
        query, w_off, b_off, offb, w_attn, b_attn, logitb, Mq);

    // 3) softmax + bilinear deformable sampling -> fp16 split
    msda_sample<<<Mq, 256>>>(vproj, refp, offb, logitb, shapes, lstart,
                             sf, Lq, Lv);

    // 4) output projection (fp16x2 MMA) -> d_out
    outproj_mma<<<dim3(2, (Mq + 127) / 128), 256, 98304>>>(
        sf, wf, b_out, (float*)d_out, Mq);
}

// round 10
// speedup vs baseline: 3.2506x; 1.1631x over previous
#include <cuda_runtime.h>
#include <cuda_fp16.h>
#include <cstdint>
#include <cstddef>

#define EMBED    256
#define HEADS    8
#define LEVELS   4
#define POINTS   4
#define HEAD_DIM 32

// ---------------------------------------------------------------------------
// Scratch (static __device__ globals; runtime allocation is forbidden)
// ---------------------------------------------------------------------------
__device__ float  g_vproj[4 * 13312 * EMBED];   // projected value (fp32)
__device__ __half g_af16[53248 * 256];          // value: plain fp16 rows of 256
__device__ __half g_wf16[512 * 256];            // w_value rows 0-255, w_out 256-511
__device__ float  g_off  [3600 * EMBED];        // sampling offsets
__device__ float  g_logit[3600 * 128];          // attn logits
__device__ __half g_sampf16[3712 * 512];        // sampled out: fp16 hi|lo chunked

// ---------------------------------------------------------------------------
// helpers
// ---------------------------------------------------------------------------
__device__ __forceinline__ uint32_t smem_u32(const void* p) {
    uint32_t a;
    asm("{ .reg .u64 t; cvta.to.shared.u64 t, %1; cvt.u32.u64 %0, t; }"
        : "=r"(a) : "l"(p));
    return a;
}

__device__ __forceinline__ void ldsm4(uint32_t* r, uint32_t addr) {
    asm volatile("ldmatrix.sync.aligned.m8n8.x4.shared.b16 {%0,%1,%2,%3}, [%4];"
                 : "=r"(r[0]), "=r"(r[1]), "=r"(r[2]), "=r"(r[3]) : "r"(addr));
}

__device__ __forceinline__ void mma_f16(float* c, const uint32_t* a,
                                        uint32_t b0, uint32_t b1) {
    asm volatile(
        "mma.sync.aligned.m16n8k16.row.col.f32.f16.f16.f32 "
        "{%0,%1,%2,%3}, {%4,%5,%6,%7}, {%8,%9}, {%0,%1,%2,%3};"
        : "+f"(c[0]), "+f"(c[1]), "+f"(c[2]), "+f"(c[3])
        : "r"(a[0]), "r"(a[1]), "r"(a[2]), "r"(a[3]), "r"(b0), "r"(b1));
}

__device__ __forceinline__ void cp_async16(uint32_t saddr, const void* gaddr) {
    asm volatile("cp.async.cg.shared.global [%0], [%1], 16;"
                 :: "r"(saddr), "l"(gaddr) : "memory");
}
#define CP_ASYNC_COMMIT() asm volatile("cp.async.commit_group;" ::: "memory")
#define CP_ASYNC_WAIT(N)  asm volatile("cp.async.wait_group %0;" :: "n"(N) : "memory")

union Pack8h { uint4 u; __half b[8]; };

#define SWZ(o) ((o) ^ (((o) >> 3) & 0x70))

// ---------------------------------------------------------------------------
// Convert: value -> plain fp16 (rows of 256); weights (w_value then w_out)
// -> plain fp16 rows of 256.
// ---------------------------------------------------------------------------
__global__ __launch_bounds__(256)
void cvt_f16(const float* __restrict__ A, const float* __restrict__ Wv,
             const float* __restrict__ Wo,
             __half* __restrict__ Af, __half* __restrict__ Wf, int Mv)
{
    int t = blockIdx.x * 256 + threadIdx.x;      // one thread per 8 floats
    int total = (Mv + 512) * 32;
    if (t >= total) return;
    int row = t >> 5;
    int s8  = t & 31;
    const float* src;
    __half* dst;
    if (row < Mv) {
        src = A + (size_t)row * 256 + s8 * 8;
        dst = Af + (size_t)row * 256 + s8 * 8;
    } else {
        int r2 = row - Mv;                        // 0..511
        src = (r2 < 256) ? Wv + (size_t)r2 * 256 + s8 * 8
                         : Wo + (size_t)(r2 - 256) * 256 + s8 * 8;
        dst = Wf + (size_t)r2 * 256 + s8 * 8;
    }
    Pack8h H;
    #pragma unroll
    for (int j = 0; j < 8; j++) H.b[j] = __float2half_rn(src[j]);
    *(uint4*)dst = H.u;
}

// ---------------------------------------------------------------------------
// Plain fp16 MMA GEMM body (single term): C[M,256] tile 128x128 at (m0,n0).
// A, B: plain fp16 rows of 256. 4 stages of 64 k; smem 2 x (16+16)KB = 64KB.
// ---------------------------------------------------------------------------
__device__ __forceinline__ void mma_gemm_plain(
    const __half* __restrict__ Af, const __half* __restrict__ Wf,
    const float* __restrict__ bias, float* __restrict__ C,
    int M, int m0, int n0, char* sm)
{
    const int tid  = threadIdx.x;
    const int lane = tid & 31;
    const int w    = tid >> 5;
    const int wm   = (w & 1) * 64;
    const int wn   = (w >> 1) * 32;
    const uint32_t sb = smem_u32(sm);

    float acc[4][4][4] = {};

    auto prefetch = [&](int p, int buf) {
        const uint32_t base = sb + buf * 32768;
        #pragma unroll
        for (int i = 0; i < 8; i++) {
            int idx = tid + i * 256;             // 0..2047
            int r   = (idx >> 3) & 127;
            int seg = idx & 7;
            uint32_t so = SWZ((uint32_t)(r * 128 + seg * 16));
            if (idx < 1024) {
                cp_async16(base + so,
                           Af + ((size_t)(m0 + r) * 256 + p * 64 + seg * 8));
            } else {
                cp_async16(base + 16384 + so,
                           Wf + ((size_t)(n0 + r) * 256 + p * 64 + seg * 8));
            }
        }
    };

    auto compute = [&](int buf) {
        const uint32_t abase = sb + buf * 32768;
        const uint32_t bbase = abase + 16384;
        const int j = lane >> 3, r = lane & 7;
        #pragma unroll
        for (int g = 0; g < 4; g++) {
            uint32_t bfr[2][4];
            #pragma unroll
            for (int nt = 0; nt < 2; nt++) {
                uint32_t row  = wn + nt * 16 + (j >> 1) * 8 + r;
                uint32_t colb = (g * 16 + (j & 1) * 8) * 2;
                ldsm4(bfr[nt], bbase + SWZ(row * 128 + colb));
            }
            #pragma unroll
            for (int mt = 0; mt < 4; mt++) {
                uint32_t af[4];
                uint32_t row  = wm + mt * 16 + (j & 1) * 8 + r;
                uint32_t colb = (g * 16 + (j >> 1) * 8) * 2;
                ldsm4(af, abase + SWZ(row * 128 + colb));
                #pragma unroll
                for (int ns = 0; ns < 4; ns++)
                    mma_f16(acc[mt][ns], af,
                            bfr[ns >> 1][(ns & 1) * 2],
                            bfr[ns >> 1][(ns & 1) * 2 + 1]);
            }
        }
    };

    prefetch(0, 0);
    CP_ASYNC_COMMIT();
    #pragma unroll 1
    for (int p = 0; p < 4; p++) {
        int buf = p & 1;
        if (p + 1 < 4) {
            prefetch(p + 1, buf ^ 1);
            CP_ASYNC_COMMIT();
            CP_ASYNC_WAIT(1);
        } else {
            CP_ASYNC_WAIT(0);
        }
        __syncthreads();
        compute(buf);
        __syncthreads();
    }

    const int g = lane >> 2, tig = lane & 3;
    #pragma unroll
    for (int mt = 0; mt < 4; mt++) {
        int mr = m0 + wm + mt * 16 + g;
        #pragma unroll
        for (int ns = 0; ns < 4; ns++) {
            int col = n0 + wn + ns * 8 + tig * 2;
            float bxv = bias[col], byv = bias[col + 1];
            if (mr < M) {
                float2 o = {acc[mt][ns][0] + bxv, acc[mt][ns][1] + byv};
                *(float2*)&C[(size_t)mr * 256 + col] = o;
            }
            if (mr + 8 < M) {
                float2 o = {acc[mt][ns][2] + bxv, acc[mt][ns][3] + byv};
                *(float2*)&C[(size_t)(mr + 8) * 256 + col] = o;
            }
        }
    }
}

// ---------------------------------------------------------------------------
// SIMT small-GEMM body (64x64 tile) on caller smem: C = A[M,256]*B[N,256]^T+bias
// ---------------------------------------------------------------------------
__device__ void gemm_small_body(const float* __restrict__ A,
                                const float* __restrict__ B,
                                const float* __restrict__ bias,
                                float* __restrict__ C,
                                int M, int N, int m0, int n0, char* smraw)
{
    float (*As)[68] = (float (*)[68])smraw;
    float (*Bs)[68] = (float (*)[68])(smraw + 32 * 68 * 4);

    const int tid = threadIdx.x;
    const int tx  = tid & 15;
    const int ty  = tid >> 4;

    float acc[4][4] = {};

    for (int k0 = 0; k0 < 256; k0 += 32) {
        #pragma unroll
        for (int i = 0; i < 2; i++) {
            int idx = tid + i * 256;
            int r   = idx >> 3;
            int c4  = idx & 7;
            int m   = m0 + r;
            float4 av = (m < M) ? *(const float4*)&A[(size_t)m * 256 + k0 + c4 * 4]
                                : make_float4(0.f, 0.f, 0.f, 0.f);
            As[c4 * 4 + 0][r] = av.x;
            As[c4 * 4 + 1][r] = av.y;
            As[c4 * 4 + 2][r] = av.z;
            As[c4 * 4 + 3][r] = av.w;
            int n   = n0 + r;
            float4 bv = (n < N) ? *(const float4*)&B[(size_t)n * 256 + k0 + c4 * 4]
                                : make_float4(0.f, 0.f, 0.f, 0.f);
            Bs[c4 * 4 + 0][r] = bv.x;
            Bs[c4 * 4 + 1][r] = bv.y;
            Bs[c4 * 4 + 2][r] = bv.z;
            Bs[c4 * 4 + 3][r] = bv.w;
        }
        __syncthreads();

        #pragma unroll
        for (int kk = 0; kk < 32; kk++) {
            float4 a = *(const float4*)&As[kk][ty * 4];
            float4 b = *(const float4*)&Bs[kk][tx * 4];
            acc[0][0] += a.x * b.x; acc[0][1] += a.x * b.y;
            acc[0][2] += a.x * b.z; acc[0][3] += a.x * b.w;
            acc[1][0] += a.y * b.x; acc[1][1] += a.y * b.y;
            acc[1][2] += a.y * b.z; acc[1][3] += a.y * b.w;
            acc[2][0] += a.z * b.x; acc[2][1] += a.z * b.y;
            acc[2][2] += a.z * b.z; acc[2][3] += a.z * b.w;
            acc[3][0] += a.w * b.x; acc[3][1] += a.w * b.y;
            acc[3][2] += a.w * b.z; acc[3][3] += a.w * b.w;
        }
        __syncthreads();
    }

    #pragma unroll
    for (int i = 0; i < 4; i++) {
        int m = m0 + ty * 4 + i;
        if (m >= M) continue;
        #pragma unroll
        for (int j = 0; j < 4; j++) {
            int n = n0 + tx * 4 + j;
            if (n < N) C[(size_t)m * N + n] = acc[i][j] + bias[n];
        }
    }
}

// ---------------------------------------------------------------------------
// Fat kernel (2 CTAs/SM). Small SIMT GEMMs dispatch FIRST.
//   blocks [0,228)        : offsets GEMM [Mq,256]
//   blocks [228,342)      : logits  GEMM [Mq,128]
//   blocks [342, 342+2MB) : vproj fp16 single-term mma.sync
// ---------------------------------------------------------------------------
__global__ __launch_bounds__(256, 2)
void fat_gemms(const __half* __restrict__ Af, const __half* __restrict__ Wf,
               const float* __restrict__ b_value,
               float* __restrict__ Cv, int Mv, int MB,
               const float* __restrict__ query,
               const float* __restrict__ w_off, const float* __restrict__ b_off,
               float* __restrict__ offb,
               const float* __restrict__ w_attn, const float* __restrict__ b_attn,
               float* __restrict__ logitb, int Mq)
{
    extern __shared__ char sm[];
    const int bx = blockIdx.x;

    if (bx < 228) {
        gemm_small_body(query, w_off, b_off, offb, Mq, 256,
                        (bx >> 2) * 64, (bx & 3) * 64, sm);
        return;
    }
    if (bx < 342) {
        int ix = bx - 228;
        gemm_small_body(query, w_attn, b_attn, logitb, Mq, 128,
                        (ix >> 1) * 64, (ix & 1) * 64, sm);
        return;
    }
    int vb = bx - 342;
    mma_gemm_plain(Af, Wf, b_value, Cv, Mv, (vb >> 1) * 128, (vb & 1) * 128, sm);
}

// ---------------------------------------------------------------------------
// Output projection, tile 32x256, 2-term split A (samp hi|lo chunked),
// plain fp16 W (w_out at row offset 256). One CTA per 32 query rows.
// smem/stage: A 2x4KB subtiles + B 32KB = 40KB; double buffered = 80KB.
// ---------------------------------------------------------------------------
__global__ __launch_bounds__(256)
void outproj_mma32(const __half* __restrict__ Sf, const __half* __restrict__ Wf,
                   const float* __restrict__ b_out, float* __restrict__ C, int Mq)
{
    extern __shared__ char sm[];
    const int tid  = threadIdx.x;
    const int lane = tid & 31;
    const int w    = tid >> 5;
    const int wn   = w * 32;                 // each warp owns 32 output cols
    const int m0   = blockIdx.x * 32;
    const uint32_t sb = smem_u32(sm);
    const __half* Wo = Wf + 256 * 256;

    float acc[2][4][4] = {};                 // [mt][ns][4]

    auto prefetch = [&](int p, int buf) {
        const uint32_t base = sb + buf * 40960;
        #pragma unroll
        for (int i = 0; i < 10; i++) {
            int idx = tid + i * 256;         // 0..2559
            if (idx < 512) {                 // A: 2 subtiles of 32 rows x 128B
                int tc  = idx >> 8;
                int r   = (idx >> 3) & 31;
                int seg = idx & 7;
                cp_async16(base + tc * 4096 + SWZ((uint32_t)(r * 128 + seg * 16)),
                           Sf + ((size_t)(m0 + r) * 512 + (p * 2 + tc) * 64 + seg * 8));
            } else {                         // B: 256 rows x 128B
                int i2  = idx - 512;
                int r   = i2 >> 3;
                int seg = i2 & 7;
                cp_async16(base + 8192 + SWZ((uint32_t)(r * 128 + seg * 16)),
                           Wo + ((size_t)r * 256 + p * 64 + seg * 8));
            }
        }
    };

    auto compute = [&](int buf) {
        const uint32_t base  = sb + buf * 40960;
        const uint32_t bbase = base + 8192;
        const int j = lane >> 3, r = lane & 7;
        #pragma unroll
        for (int c = 0; c < 2; c++) {
            #pragma unroll
            for (int g = 0; g < 2; g++) {
                uint32_t bfr[2][4];
                #pragma unroll
                for (int nt = 0; nt < 2; nt++) {
                    uint32_t row  = wn + nt * 16 + (j >> 1) * 8 + r;
                    uint32_t colb = (c * 32 + g * 16 + (j & 1) * 8) * 2;
                    ldsm4(bfr[nt], bbase + SWZ(row * 128 + colb));
                }
                #pragma unroll
                for (int t = 0; t < 2; t++) {
                    #pragma unroll
                    for (int mt = 0; mt < 2; mt++) {
                        uint32_t af[4];
                        uint32_t row  = mt * 16 + (j & 1) * 8 + r;
                        uint32_t colb = (t * 32 + g * 16 + (j >> 1) * 8) * 2;
                        ldsm4(af, base + c * 4096 + SWZ(row * 128 + colb));
                        #pragma unroll
                        for (int ns = 0; ns < 4; ns++)
                            mma_f16(acc[mt][ns], af,
                                    bfr[ns >> 1][(ns & 1) * 2],
                                    bfr[ns >> 1][(ns & 1) * 2 + 1]);
                    }
                }
            }
        }
    };

    prefetch(0, 0);
    CP_ASYNC_COMMIT();
    #pragma unroll 1
    for (int p = 0; p < 4; p++) {
        int buf = p & 1;
        if (p + 1 < 4) {
            prefetch(p + 1, buf ^ 1);
            CP_ASYNC_COMMIT();
            CP_ASYNC_WAIT(1);
        } else {
            CP_ASYNC_WAIT(0);
        }
        __syncthreads();
        compute(buf);
        __syncthreads();
    }

    const int g = lane >> 2, tig = lane & 3;
    #pragma unroll
    for (int mt = 0; mt < 2; mt++) {
        int mr = m0 + mt * 16 + g;
        #pragma unroll
        for (int ns = 0; ns < 4; ns++) {
            int col = wn + ns * 8 + tig * 2;
            float bxv = b_out[col], byv = b_out[col + 1];
            if (mr < Mq) {
                float2 o = {acc[mt][ns][0] + bxv, acc[mt][ns][1] + byv};
                *(float2*)&C[(size_t)mr * 256 + col] = o;
            }
            if (mr + 8 < Mq) {
                float2 o = {acc[mt][ns][2] + bxv, acc[mt][ns][3] + byv};
                *(float2*)&C[(size_t)(mr + 8) * 256 + col] = o;
            }
        }
    }
}

// ---------------------------------------------------------------------------
// Deformable sampling (dedup phase-1); epilogue writes fp16 hi|lo split
// ---------------------------------------------------------------------------
__global__ __launch_bounds__(256)
void msda_sample(const float* __restrict__ vproj,
                 const float* __restrict__ refp,
                 const float* __restrict__ off,
                 const float* __restrict__ logits,
                 const int*   __restrict__ shapes,
                 const int*   __restrict__ lstart,
                 __half* __restrict__ sampf,     // [3712, 512] chunked hi|lo
                 int Lq, int Lv)
{
    const int bq  = blockIdx.x;
    const int b   = bq / Lq;
    const int tid = threadIdx.x;

    __shared__ float s_log[128];
    __shared__ float s_off[EMBED];
    __shared__ float s_ref[LEVELS * 2];
    __shared__ int   s_shape[LEVELS * 2];
    __shared__ int   s_start[LEVELS];
    __shared__ int4   s_idx4[128];
    __shared__ float4 s_w4[128];

    if (tid < 128) s_log[tid] = logits[(size_t)bq * 128 + tid];
    s_off[tid] = off[(size_t)bq * EMBED + tid];
    if (tid < LEVELS * 2) {
        s_ref[tid]   = refp[(size_t)bq * (LEVELS * 2) + tid];
        s_shape[tid] = shapes[tid];
    }
    if (tid < LEVELS) s_start[tid] = lstart[tid];
    __syncthreads();

    if (tid < 128) {
        const int h = tid >> 4;
        const int i = tid & 15;
        const int l = i >> 2;

        float mx = -1e30f;
        #pragma unroll
        for (int j = 0; j < 16; j++) mx = fmaxf(mx, s_log[h * 16 + j]);
        float sum = 0.f;
        #pragma unroll
        for (int j = 0; j < 16; j++) sum += __expf(s_log[h * 16 + j] - mx);
        const float aw = __expf(s_log[tid] - mx) / sum;

        const int   Hh = s_shape[l * 2 + 0];
        const int   Ww = s_shape[l * 2 + 1];
        const float Wfl = (float)Ww, Hfl = (float)Hh;
        const int   st = s_start[l];
        const float rx = s_ref[l * 2 + 0];
        const float ry = s_ref[l * 2 + 1];

        const float x = (rx + s_off[tid * 2 + 0] / Wfl) * Wfl - 0.5f;
        const float y = (ry + s_off[tid * 2 + 1] / Hfl) * Hfl - 0.5f;
        const float x0f = floorf(x), y0f = floorf(y);
        const float lx = x - x0f, ly = y - y0f;
        const int   x0 = (int)x0f, y0 = (int)y0f;

        const bool vx0 = (x0 >= 0) & (x0 < Ww);
        const bool vx1 = (x0 + 1 >= 0) & (x0 + 1 < Ww);
        const bool vy0 = (y0 >= 0) & (y0 < Hh);
        const bool vy1 = (y0 + 1 >= 0) & (y0 + 1 < Hh);

        int4 id;
        id.x = (vy0 && vx0) ? st + y0 * Ww + x0           : -1;
        id.y = (vy0 && vx1) ? st + y0 * Ww + x0 + 1       : -1;
        id.z = (vy1 && vx0) ? st + (y0 + 1) * Ww + x0     : -1;
        id.w = (vy1 && vx1) ? st + (y0 + 1) * Ww + x0 + 1 : -1;

        float4 ww;
        ww.x = aw * (1.f - lx) * (1.f - ly);
        ww.y = aw * lx * (1.f - ly);
        ww.z = aw * (1.f - lx) * ly;
        ww.w = aw * lx * ly;

        s_idx4[tid] = id;
        s_w4[tid]   = ww;
    }
    __syncthreads();

    const int h = tid >> 5;
    const int d = tid & 31;
    const float* vb = vproj + (size_t)b * Lv * EMBED + h * HEAD_DIM + d;

    float a0 = 0.f, a1 = 0.f, a2 = 0.f, a3 = 0.f;
    #pragma unroll 4
    for (int i = 0; i < 16; i++) {
        const int t = h * 16 + i;
        const int4   id = s_idx4[t];
        const float4 ww = s_w4[t];
        if (id.x >= 0) a0 += ww.x * __ldg(vb + (size_t)id.x * EMBED);
        if (id.y >= 0) a1 += ww.y * __ldg(vb + (size_t)id.y * EMBED);
        if (id.z >= 0) a2 += ww.z * __ldg(vb + (size_t)id.z * EMBED);
        if (id.w >= 0) a3 += ww.w * __ldg(vb + (size_t)id.w * EMBED);
    }
    const float r = (a0 + a1) + (a2 + a3);
    __half hv = __float2half_rn(r);
    __half lv = __float2half_rn(r - __half2float(hv));
    const int kc = tid >> 5;
    const int cc = tid & 31;
    __half* dst = sampf + (size_t)bq * 512 + kc * 64 + cc;
    dst[0]  = hv;
    dst[32] = lv;
}

// ---------------------------------------------------------------------------
// kernel_launch
// ---------------------------------------------------------------------------
extern "C" void kernel_launch(void* const* d_in, const int* in_sizes, int n_in,
                              void* d_out, int out_size)
{
    const float* query   = (const float*)d_in[0];
    const float* refp    = (const float*)d_in[1];
    const float* value   = (const float*)d_in[2];
    const int*   shapes  = (const int*)  d_in[3];
    const int*   lstart  = (const int*)  d_in[4];
    const float* w_value = (const float*)d_in[5];
    const float* b_value = (const float*)d_in[6];
    const float* w_off   = (const float*)d_in[7];
    const float* b_off   = (const float*)d_in[8];
    const float* w_attn  = (const float*)d_in[9];
    const float* b_attn  = (const float*)d_in[10];
    const float* w_out   = (const float*)d_in[11];
    const float* b_out   = (const float*)d_in[12];

    const int Mv = in_sizes[2] / EMBED;   // bs * Lv = 53176
    const int Mq = in_sizes[0] / EMBED;   // bs * Lq = 3600
    const int bs = 4;
    const int Lv = Mv / bs;
    const int Lq = Mq / bs;

    float *vproj, *offb, *logitb;
    __half *af, *wf, *sf;
    cudaGetSymbolAddress((void**)&vproj,  g_vproj);
    cudaGetSymbolAddress((void**)&offb,   g_off);
    cudaGetSymbolAddress((void**)&logitb, g_logit);
    cudaGetSymbolAddress((void**)&af,     g_af16);
    cudaGetSymbolAddress((void**)&wf,     g_wf16);
    cudaGetSymbolAddress((void**)&sf,     g_sampf16);

    // 1) fp16 conversion (plain): value + weights
    {
        int total = (Mv + 512) * 32;
        cvt_f16<<<(total + 255) / 256, 256>>>(value, w_value, w_out, af, wf, Mv);
    }

    // 2) fat kernel: small GEMMs first, then vproj (fp16 single-term tensor)
    const int MB = (Mv + 127) / 128;               // 416
    static bool cfg = false;
    if (!cfg) {
        cudaFuncSetAttribute(fat_gemms,
                             cudaFuncAttributeMaxDynamicSharedMemorySize, 65536);
        cudaFuncSetAttribute(outproj_mma32,
                             cudaFuncAttributeMaxDynamicSharedMemorySize, 81920);
        cfg = true;
    }
    fat_gemms<<<342 + 2 * MB, 256, 65536>>>(
        af, wf, b_value, vproj, Mv, MB,
        query, w_off, b_off, offb, w_attn, b_attn, logitb, Mq);

    // 3) softmax + bilinear deformable sampling -> fp16 split
    msda_sample<<<Mq, 256>>>(vproj, refp, offb, logitb, shapes, lstart,
                             sf, Lq, Lv);

    // 4) output projection (fp16, 2-term samp split, 32-row tiles) -> d_out
    outproj_mma32<<<(Mq + 31) / 32, 256, 81920>>>(sf, wf, b_out, (float*)d_out, Mq);
}

// round 11
// speedup vs baseline: 3.2686x; 1.0055x over previous
#include <cuda_runtime.h>
#include <cuda_fp16.h>
#include <cstdint>
#include <cstddef>

#define EMBED    256
#define HEADS    8
#define LEVELS   4
#define POINTS   4
#define HEAD_DIM 32

// ---------------------------------------------------------------------------
// Scratch (static __device__ globals; runtime allocation is forbidden)
// ---------------------------------------------------------------------------
__device__ float  g_vproj[4 * 13312 * EMBED];   // projected value (fp32)
__device__ __half g_af16[53248 * 256];          // value: plain fp16 rows of 256
__device__ __half g_wf16[512 * 256];            // w_value rows 0-255, w_out 256-511
__device__ float  g_off  [3600 * EMBED];        // sampling offsets
__device__ float  g_logit[3600 * 128];          // attn logits
__device__ __half g_sampf16[3712 * 512];        // sampled out: fp16 hi|lo chunked

// ---------------------------------------------------------------------------
// helpers
// ---------------------------------------------------------------------------
__device__ __forceinline__ uint32_t smem_u32(const void* p) {
    uint32_t a;
    asm("{ .reg .u64 t; cvta.to.shared.u64 t, %1; cvt.u32.u64 %0, t; }"
        : "=r"(a) : "l"(p));
    return a;
}

__device__ __forceinline__ void ldsm4(uint32_t* r, uint32_t addr) {
    asm volatile("ldmatrix.sync.aligned.m8n8.x4.shared.b16 {%0,%1,%2,%3}, [%4];"
                 : "=r"(r[0]), "=r"(r[1]), "=r"(r[2]), "=r"(r[3]) : "r"(addr));
}

__device__ __forceinline__ void mma_f16(float* c, const uint32_t* a,
                                        uint32_t b0, uint32_t b1) {
    asm volatile(
        "mma.sync.aligned.m16n8k16.row.col.f32.f16.f16.f32 "
        "{%0,%1,%2,%3}, {%4,%5,%6,%7}, {%8,%9}, {%0,%1,%2,%3};"
        : "+f"(c[0]), "+f"(c[1]), "+f"(c[2]), "+f"(c[3])
        : "r"(a[0]), "r"(a[1]), "r"(a[2]), "r"(a[3]), "r"(b0), "r"(b1));
}

__device__ __forceinline__ void cp_async16(uint32_t saddr, const void* gaddr) {
    asm volatile("cp.async.cg.shared.global [%0], [%1], 16;"
                 :: "r"(saddr), "l"(gaddr) : "memory");
}
#define CP_ASYNC_COMMIT() asm volatile("cp.async.commit_group;" ::: "memory")
#define CP_ASYNC_WAIT(N)  asm volatile("cp.async.wait_group %0;" :: "n"(N) : "memory")

union Pack8h { uint4 u; __half b[8]; };

#define SWZ(o) ((o) ^ (((o) >> 3) & 0x70))

// ---------------------------------------------------------------------------
// Convert: value -> plain fp16 (rows of 256); weights (w_value then w_out)
// -> plain fp16 rows of 256.
// ---------------------------------------------------------------------------
__global__ __launch_bounds__(256)
void cvt_f16(const float* __restrict__ A, const float* __restrict__ Wv,
             const float* __restrict__ Wo,
             __half* __restrict__ Af, __half* __restrict__ Wf, int Mv)
{
    int t = blockIdx.x * 256 + threadIdx.x;      // one thread per 8 floats
    int total = (Mv + 512) * 32;
    if (t >= total) return;
    int row = t >> 5;
    int s8  = t & 31;
    const float* src;
    __half* dst;
    if (row < Mv) {
        src = A + (size_t)row * 256 + s8 * 8;
        dst = Af + (size_t)row * 256 + s8 * 8;
    } else {
        int r2 = row - Mv;                        // 0..511
        src = (r2 < 256) ? Wv + (size_t)r2 * 256 + s8 * 8
                         : Wo + (size_t)(r2 - 256) * 256 + s8 * 8;
        dst = Wf + (size_t)r2 * 256 + s8 * 8;
    }
    Pack8h H;
    #pragma unroll
    for (int j = 0; j < 8; j++) H.b[j] = __float2half_rn(src[j]);
    *(uint4*)dst = H.u;
}

// ---------------------------------------------------------------------------
// Plain fp16 MMA GEMM body (single term): C[M,256] tile 128x128 at (m0,n0).
// A, B: plain fp16 rows of 256. 4 stages of 64 k; smem 2 x (16+16)KB = 64KB.
// ---------------------------------------------------------------------------
__device__ __forceinline__ void mma_gemm_plain(
    const __half* __restrict__ Af, const __half* __restrict__ Wf,
    const float* __restrict__ bias, float* __restrict__ C,
    int M, int m0, int n0, char* sm)
{
    const int tid  = threadIdx.x;
    const int lane = tid & 31;
    const int w    = tid >> 5;
    const int wm   = (w & 1) * 64;
    const int wn   = (w >> 1) * 32;
    const uint32_t sb = smem_u32(sm);

    float acc[4][4][4] = {};

    auto prefetch = [&](int p, int buf) {
        const uint32_t base = sb + buf * 32768;
        #pragma unroll
        for (int i = 0; i < 8; i++) {
            int idx = tid + i * 256;             // 0..2047
            int r   = (idx >> 3) & 127;
            int seg = idx & 7;
            uint32_t so = SWZ((uint32_t)(r * 128 + seg * 16));
            if (idx < 1024) {
                cp_async16(base + so,
                           Af + ((size_t)(m0 + r) * 256 + p * 64 + seg * 8));
            } else {
                cp_async16(base + 16384 + so,
                           Wf + ((size_t)(n0 + r) * 256 + p * 64 + seg * 8));
            }
        }
    };

    auto compute = [&](int buf) {
        const uint32_t abase = sb + buf * 32768;
        const uint32_t bbase = abase + 16384;
        const int j = lane >> 3, r = lane & 7;
        #pragma unroll
        for (int g = 0; g < 4; g++) {
            uint32_t bfr[2][4];
            #pragma unroll
            for (int nt = 0; nt < 2; nt++) {
                uint32_t row  = wn + nt * 16 + (j >> 1) * 8 + r;
                uint32_t colb = (g * 16 + (j & 1) * 8) * 2;
                ldsm4(bfr[nt], bbase + SWZ(row * 128 + colb));
            }
            #pragma unroll
            for (int mt = 0; mt < 4; mt++) {
                uint32_t af[4];
                uint32_t row  = wm + mt * 16 + (j & 1) * 8 + r;
                uint32_t colb = (g * 16 + (j >> 1) * 8) * 2;
                ldsm4(af, abase + SWZ(row * 128 + colb));
                #pragma unroll
                for (int ns = 0; ns < 4; ns++)
                    mma_f16(acc[mt][ns], af,
                            bfr[ns >> 1][(ns & 1) * 2],
                            bfr[ns >> 1][(ns & 1) * 2 + 1]);
            }
        }
    };

    prefetch(0, 0);
    CP_ASYNC_COMMIT();
    #pragma unroll 1
    for (int p = 0; p < 4; p++) {
        int buf = p & 1;
        if (p + 1 < 4) {
            prefetch(p + 1, buf ^ 1);
            CP_ASYNC_COMMIT();
            CP_ASYNC_WAIT(1);
        } else {
            CP_ASYNC_WAIT(0);
        }
        __syncthreads();
        compute(buf);
        __syncthreads();
    }

    const int g = lane >> 2, tig = lane & 3;
    #pragma unroll
    for (int mt = 0; mt < 4; mt++) {
        int mr = m0 + wm + mt * 16 + g;
        #pragma unroll
        for (int ns = 0; ns < 4; ns++) {
            int col = n0 + wn + ns * 8 + tig * 2;
            float bxv = bias[col], byv = bias[col + 1];
            if (mr < M) {
                float2 o = {acc[mt][ns][0] + bxv, acc[mt][ns][1] + byv};
                *(float2*)&C[(size_t)mr * 256 + col] = o;
            }
            if (mr + 8 < M) {
                float2 o = {acc[mt][ns][2] + bxv, acc[mt][ns][3] + byv};
                *(float2*)&C[(size_t)(mr + 8) * 256 + col] = o;
            }
        }
    }
}

// ---------------------------------------------------------------------------
// SIMT small-GEMM body (64x64 tile) on caller smem: C = A[M,256]*B[N,256]^T+bias
// ---------------------------------------------------------------------------
__device__ void gemm_small_body(const float* __restrict__ A,
                                const float* __restrict__ B,
                                const float* __restrict__ bias,
                                float* __restrict__ C,
                                int M, int N, int m0, int n0, char* smraw)
{
    float (*As)[68] = (float (*)[68])smraw;
    float (*Bs)[68] = (float (*)[68])(smraw + 32 * 68 * 4);

    const int tid = threadIdx.x;
    const int tx  = tid & 15;
    const int ty  = tid >> 4;

    float acc[4][4] = {};

    for (int k0 = 0; k0 < 256; k0 += 32) {
        #pragma unroll
        for (int i = 0; i < 2; i++) {
            int idx = tid + i * 256;
            int r   = idx >> 3;
            int c4  = idx & 7;
            int m   = m0 + r;
            float4 av = (m < M) ? *(const float4*)&A[(size_t)m * 256 + k0 + c4 * 4]
                                : make_float4(0.f, 0.f, 0.f, 0.f);
            As[c4 * 4 + 0][r] = av.x;
            As[c4 * 4 + 1][r] = av.y;
            As[c4 * 4 + 2][r] = av.z;
            As[c4 * 4 + 3][r] = av.w;
            int n   = n0 + r;
            float4 bv = (n < N) ? *(const float4*)&B[(size_t)n * 256 + k0 + c4 * 4]
                                : make_float4(0.f, 0.f, 0.f, 0.f);
            Bs[c4 * 4 + 0][r] = bv.x;
            Bs[c4 * 4 + 1][r] = bv.y;
            Bs[c4 * 4 + 2][r] = bv.z;
            Bs[c4 * 4 + 3][r] = bv.w;
        }
        __syncthreads();

        #pragma unroll
        for (int kk = 0; kk < 32; kk++) {
            float4 a = *(const float4*)&As[kk][ty * 4];
            float4 b = *(const float4*)&Bs[kk][tx * 4];
            acc[0][0] += a.x * b.x; acc[0][1] += a.x * b.y;
            acc[0][2] += a.x * b.z; acc[0][3] += a.x * b.w;
            acc[1][0] += a.y * b.x; acc[1][1] += a.y * b.y;
            acc[1][2] += a.y * b.z; acc[1][3] += a.y * b.w;
            acc[2][0] += a.z * b.x; acc[2][1] += a.z * b.y;
            acc[2][2] += a.z * b.z; acc[2][3] += a.z * b.w;
            acc[3][0] += a.w * b.x; acc[3][1] += a.w * b.y;
            acc[3][2] += a.w * b.z; acc[3][3] += a.w * b.w;
        }
        __syncthreads();
    }

    #pragma unroll
    for (int i = 0; i < 4; i++) {
        int m = m0 + ty * 4 + i;
        if (m >= M) continue;
        #pragma unroll
        for (int j = 0; j < 4; j++) {
            int n = n0 + tx * 4 + j;
            if (n < N) C[(size_t)m * N + n] = acc[i][j] + bias[n];
        }
    }
}

// ---------------------------------------------------------------------------
// Fat kernel (2 CTAs/SM). Small SIMT GEMMs dispatch FIRST.
//   blocks [0,228)        : offsets GEMM [Mq,256]
//   blocks [228,342)      : logits  GEMM [Mq,128]
//   blocks [342, 342+2MB) : vproj fp16 single-term mma.sync
// ---------------------------------------------------------------------------
__global__ __launch_bounds__(256, 2)
void fat_gemms(const __half* __restrict__ Af, const __half* __restrict__ Wf,
               const float* __restrict__ b_value,
               float* __restrict__ Cv, int Mv, int MB,
               const float* __restrict__ query,
               const float* __restrict__ w_off, const float* __restrict__ b_off,
               float* __restrict__ offb,
               const float* __restrict__ w_attn, const float* __restrict__ b_attn,
               float* __restrict__ logitb, int Mq)
{
    extern __shared__ char sm[];
    const int bx = blockIdx.x;

    if (bx < 228) {
        gemm_small_body(query, w_off, b_off, offb, Mq, 256,
                        (bx >> 2) * 64, (bx & 3) * 64, sm);
        return;
    }
    if (bx < 342) {
        int ix = bx - 228;
        gemm_small_body(query, w_attn, b_attn, logitb, Mq, 128,
                        (ix >> 1) * 64, (ix & 1) * 64, sm);
        return;
    }
    int vb = bx - 342;
    mma_gemm_plain(Af, Wf, b_value, Cv, Mv, (vb >> 1) * 128, (vb & 1) * 128, sm);
}

// ---------------------------------------------------------------------------
// Output projection, tile 32x256, 2-term split A (samp hi|lo chunked),
// plain fp16 W (w_out at row offset 256). One CTA per 32 query rows.
// smem/stage: A 2x4KB subtiles + B 32KB = 40KB; double buffered = 80KB.
// ---------------------------------------------------------------------------
__global__ __launch_bounds__(256)
void outproj_mma32(const __half* __restrict__ Sf, const __half* __restrict__ Wf,
                   const float* __restrict__ b_out, float* __restrict__ C, int Mq)
{
    extern __shared__ char sm[];
    const int tid  = threadIdx.x;
    const int lane = tid & 31;
    const int w    = tid >> 5;
    const int wn   = w * 32;                 // each warp owns 32 output cols
    const int m0   = blockIdx.x * 32;
    const uint32_t sb = smem_u32(sm);
    const __half* Wo = Wf + 256 * 256;

    float acc[2][4][4] = {};                 // [mt][ns][4]

    auto prefetch = [&](int p, int buf) {
        const uint32_t base = sb + buf * 40960;
        #pragma unroll
        for (int i = 0; i < 10; i++) {
            int idx = tid + i * 256;         // 0..2559
            if (idx < 512) {                 // A: 2 subtiles of 32 rows x 128B
                int tc  = idx >> 8;
                int r   = (idx >> 3) & 31;
                int seg = idx & 7;
                cp_async16(base + tc * 4096 + SWZ((uint32_t)(r * 128 + seg * 16)),
                           Sf + ((size_t)(m0 + r) * 512 + (p * 2 + tc) * 64 + seg * 8));
            } else {                         // B: 256 rows x 128B
                int i2  = idx - 512;
                int r   = i2 >> 3;
                int seg = i2 & 7;
                cp_async16(base + 8192 + SWZ((uint32_t)(r * 128 + seg * 16)),
                           Wo + ((size_t)r * 256 + p * 64 + seg * 8));
            }
        }
    };

    auto compute = [&](int buf) {
        const uint32_t base  = sb + buf * 40960;
        const uint32_t bbase = base + 8192;
        const int j = lane >> 3, r = lane & 7;
        #pragma unroll
        for (int c = 0; c < 2; c++) {
            #pragma unroll
            for (int g = 0; g < 2; g++) {
                uint32_t bfr[2][4];
                #pragma unroll
                for (int nt = 0; nt < 2; nt++) {
                    uint32_t row  = wn + nt * 16 + (j >> 1) * 8 + r;
                    uint32_t colb = (c * 32 + g * 16 + (j & 1) * 8) * 2;
                    ldsm4(bfr[nt], bbase + SWZ(row * 128 + colb));
                }
                #pragma unroll
                for (int t = 0; t < 2; t++) {
                    #pragma unroll
                    for (int mt = 0; mt < 2; mt++) {
                        uint32_t af[4];
                        uint32_t row  = mt * 16 + (j & 1) * 8 + r;
                        uint32_t colb = (t * 32 + g * 16 + (j >> 1) * 8) * 2;
                        ldsm4(af, base + c * 4096 + SWZ(row * 128 + colb));
                        #pragma unroll
                        for (int ns = 0; ns < 4; ns++)
                            mma_f16(acc[mt][ns], af,
                                    bfr[ns >> 1][(ns & 1) * 2],
                                    bfr[ns >> 1][(ns & 1) * 2 + 1]);
                    }
                }
            }
        }
    };

    prefetch(0, 0);
    CP_ASYNC_COMMIT();
    #pragma unroll 1
    for (int p = 0; p < 4; p++) {
        int buf = p & 1;
        if (p + 1 < 4) {
            prefetch(p + 1, buf ^ 1);
            CP_ASYNC_COMMIT();
            CP_ASYNC_WAIT(1);
        } else {
            CP_ASYNC_WAIT(0);
        }
        __syncthreads();
        compute(buf);
        __syncthreads();
    }

    const int g = lane >> 2, tig = lane & 3;
    #pragma unroll
    for (int mt = 0; mt < 2; mt++) {
        int mr = m0 + mt * 16 + g;
        #pragma unroll
        for (int ns = 0; ns < 4; ns++) {
            int col = wn + ns * 8 + tig * 2;
            float bxv = b_out[col], byv = b_out[col + 1];
            if (mr < Mq) {
                float2 o = {acc[mt][ns][0] + bxv, acc[mt][ns][1] + byv};
                *(float2*)&C[(size_t)mr * 256 + col] = o;
            }
            if (mr + 8 < Mq) {
                float2 o = {acc[mt][ns][2] + bxv, acc[mt][ns][3] + byv};
                *(float2*)&C[(size_t)(mr + 8) * 256 + col] = o;
            }
        }
    }
}

// ---------------------------------------------------------------------------
// Deformable sampling (dedup phase-1); epilogue writes fp16 hi|lo split
// ---------------------------------------------------------------------------
__global__ __launch_bounds__(256)
void msda_sample(const float* __restrict__ vproj,
                 const float* __restrict__ refp,
                 const float* __restrict__ off,
                 const float* __restrict__ logits,
                 const int*   __restrict__ shapes,
                 const int*   __restrict__ lstart,
                 __half* __restrict__ sampf,     // [3712, 512] chunked hi|lo
                 int Lq, int Lv)
{
    const int bq  = blockIdx.x;
    const int b   = bq / Lq;
    const int tid = threadIdx.x;

    __shared__ float s_log[128];
    __shared__ float s_off[EMBED];
    __shared__ float s_ref[LEVELS * 2];
    __shared__ int   s_shape[LEVELS * 2];
    __shared__ int   s_start[LEVELS];
    __shared__ int4   s_idx4[128];
    __shared__ float4 s_w4[128];

    if (tid < 128) s_log[tid] = logits[(size_t)bq * 128 + tid];
    s_off[tid] = off[(size_t)bq * EMBED + tid];
    if (tid < LEVELS * 2) {
        s_ref[tid]   = refp[(size_t)bq * (LEVELS * 2) + tid];
        s_shape[tid] = shapes[tid];
    }
    if (tid < LEVELS) s_start[tid] = lstart[tid];
    __syncthreads();

    if (tid < 128) {
        const int h = tid >> 4;
        const int i = tid & 15;
        const int l = i >> 2;

        float mx = -1e30f;
        #pragma unroll
        for (int j = 0; j < 16; j++) mx = fmaxf(mx, s_log[h * 16 + j]);
        float sum = 0.f;
        #pragma unroll
        for (int j = 0; j < 16; j++) sum += __expf(s_log[h * 16 + j] - mx);
        const float aw = __expf(s_log[tid] - mx) / sum;

        const int   Hh = s_shape[l * 2 + 0];
        const int   Ww = s_shape[l * 2 + 1];
        const float Wfl = (float)Ww, Hfl = (float)Hh;
        const int   st = s_start[l];
        const float rx = s_ref[l * 2 + 0];
        const float ry = s_ref[l * 2 + 1];

        const float x = (rx + s_off[tid * 2 + 0] / Wfl) * Wfl - 0.5f;
        const float y = (ry + s_off[tid * 2 + 1] / Hfl) * Hfl - 0.5f;
        const float x0f = floorf(x), y0f = floorf(y);
        const float lx = x - x0f, ly = y - y0f;
        const int   x0 = (int)x0f, y0 = (int)y0f;

        const bool vx0 = (x0 >= 0) & (x0 < Ww);
        const bool vx1 = (x0 + 1 >= 0) & (x0 + 1 < Ww);
        const bool vy0 = (y0 >= 0) & (y0 < Hh);
        const bool vy1 = (y0 + 1 >= 0) & (y0 + 1 < Hh);

        int4 id;
        id.x = (vy0 && vx0) ? st + y0 * Ww + x0           : -1;
        id.y = (vy0 && vx1) ? st + y0 * Ww + x0 + 1       : -1;
        id.z = (vy1 && vx0) ? st + (y0 + 1) * Ww + x0     : -1;
        id.w = (vy1 && vx1) ? st + (y0 + 1) * Ww + x0 + 1 : -1;

        float4 ww;
        ww.x = aw * (1.f - lx) * (1.f - ly);
        ww.y = aw * lx * (1.f - ly);
        ww.z = aw * (1.f - lx) * ly;
        ww.w = aw * lx * ly;

        s_idx4[tid] = id;
        s_w4[tid]   = ww;
    }
    __syncthreads();

    const int h = tid >> 5;
    const int d = tid & 31;
    const float* vb = vproj + (size_t)b * Lv * EMBED + h * HEAD_DIM + d;

    float a0 = 0.f, a1 = 0.f, a2 = 0.f, a3 = 0.f;
    #pragma unroll 4
    for (int i = 0; i < 16; i++) {
        const int t = h * 16 + i;
        const int4   id = s_idx4[t];
        const float4 ww = s_w4[t];
        if (id.x >= 0) a0 += ww.x * __ldg(vb + (size_t)id.x * EMBED);
        if (id.y >= 0) a1 += ww.y * __ldg(vb + (size_t)id.y * EMBED);
        if (id.z >= 0) a2 += ww.z * __ldg(vb + (size_t)id.z * EMBED);
        if (id.w >= 0) a3 += ww.w * __ldg(vb + (size_t)id.w * EMBED);
    }
    const float r = (a0 + a1) + (a2 + a3);
    __half hv = __float2half_rn(r);
    __half lv = __float2half_rn(r - __half2float(hv));
    const int kc = tid >> 5;
    const int cc = tid & 31;
    __half* dst = sampf + (size_t)bq * 512 + kc * 64 + cc;
    dst[0]  = hv;
    dst[32] = lv;
}

// ---------------------------------------------------------------------------
// kernel_launch
// ---------------------------------------------------------------------------
extern "C" void kernel_launch(void* const* d_in, const int* in_sizes, int n_in,
                              void* d_out, int out_size)
{
    const float* query   = (const float*)d_in[0];
    const float* refp    = (const float*)d_in[1];
    const float* value   = (const float*)d_in[2];
    const int*   shapes  = (const int*)  d_in[3];
    const int*   lstart  = (const int*)  d_in[4];
    const float* w_value = (const float*)d_in[5];
    const float* b_value = (const float*)d_in[6];
    const float* w_off   = (const float*)d_in[7];
    const float* b_off   = (const float*)d_in[8];
    const float* w_attn  = (const float*)d_in[9];
    const float* b_attn  = (const float*)d_in[10];
    const float* w_out   = (const float*)d_in[11];
    const float* b_out   = (const float*)d_in[12];

    const int Mv = in_sizes[2] / EMBED;   // bs * Lv = 53176
    const int Mq = in_sizes[0] / EMBED;   // bs * Lq = 3600
    const int bs = 4;
    const int Lv = Mv / bs;
    const int Lq = Mq / bs;

    float *vproj, *offb, *logitb;
    __half *af, *wf, *sf;
    cudaGetSymbolAddress((void**)&vproj,  g_vproj);
    cudaGetSymbolAddress((void**)&offb,   g_off);
    cudaGetSymbolAddress((void**)&logitb, g_logit);
    cudaGetSymbolAddress((void**)&af,     g_af16);
    cudaGetSymbolAddress((void**)&wf,     g_wf16);
    cudaGetSymbolAddress((void**)&sf,     g_sampf16);

    // 1) fp16 conversion (plain): value + weights
    {
        int total = (Mv + 512) * 32;
        cvt_f16<<<(total + 255) / 256, 256>>>(value, w_value, w_out, af, wf, Mv);
    }

    // 2) fat kernel: small GEMMs first, then vproj (fp16 single-term tensor)
    const int MB = (Mv + 127) / 128;               // 416
    static bool cfg = false;
    if (!cfg) {
        cudaFuncSetAttribute(fat_gemms,
                             cudaFuncAttributeMaxDynamicSharedMemorySize, 65536);
        cudaFuncSetAttribute(outproj_mma32,
                             cudaFuncAttributeMaxDynamicSharedMemorySize, 81920);
        cfg = true;
    }
    fat_gemms<<<342 + 2 * MB, 256, 65536>>>(
        af, wf, b_value, vproj, Mv, MB,
        query, w_off, b_off, offb, w_attn, b_attn, logitb, Mq);

    // 3) softmax + bilinear deformable sampling -> fp16 split
    msda_sample<<<Mq, 256>>>(vproj, refp, offb, logitb, shapes, lstart,
                             sf, Lq, Lv);

    // 4) output projection (fp16, 2-term samp split, 32-row tiles) -> d_out
    outproj_mma32<<<(Mq + 31) / 32, 256, 81920>>>(sf, wf, b_out, (float*)d_out, Mq);
}